// round 5
// baseline (speedup 1.0000x reference)
#include <cuda_runtime.h>
#include <cuda_bf16.h>
#include <cstdint>

#define B_    16
#define L_    512
#define HID_  1024
#define NH_   16
#define HD_   64
#define M_TOT (B_*L_)      // 8192
#define DCAT  192
#define XN    ((size_t)M_TOT*HID_)
#define WN    ((size_t)HID_*HID_)

// ---------------- scratch (static device arrays) ----------------
__device__ __nv_bfloat16 g_xh[5ULL*XN];
__device__ __nv_bfloat16 g_xl[5ULL*XN];
__device__ __nv_bfloat16 g_wh[8ULL*WN];
__device__ __nv_bfloat16 g_wl[8ULL*WN];
__device__ __nv_bfloat16 g_qh[(size_t)B_*NH_*L_*DCAT];
__device__ __nv_bfloat16 g_ql[(size_t)B_*NH_*L_*DCAT];
__device__ __nv_bfloat16 g_kh[(size_t)B_*NH_*L_*DCAT];
__device__ __nv_bfloat16 g_kl[(size_t)B_*NH_*L_*DCAT];
__device__ __nv_bfloat16 g_vth[(size_t)B_*NH_*HD_*L_];
__device__ __nv_bfloat16 g_vtl[(size_t)B_*NH_*HD_*L_];

// ---------------- PTX helpers (baseline ISA only) ----------------
__device__ __forceinline__ uint32_t smem_u32(const void* p) {
    uint32_t a;
    asm("{ .reg .u64 t; cvta.to.shared.u64 t, %1; cvt.u32.u64 %0, t; }" : "=r"(a) : "l"(p));
    return a;
}
__device__ __forceinline__ void cp16(uint32_t dst, const void* src) {
    asm volatile("cp.async.cg.shared.global [%0], [%1], 16;" :: "r"(dst), "l"(src));
}
__device__ __forceinline__ void ldm_x4(uint32_t* r, uint32_t addr) {
    asm volatile("ldmatrix.sync.aligned.m8n8.x4.shared.b16 {%0,%1,%2,%3}, [%4];"
                 : "=r"(r[0]), "=r"(r[1]), "=r"(r[2]), "=r"(r[3]) : "r"(addr));
}
__device__ __forceinline__ void mma16816(float* d, const uint32_t* a, const uint32_t* b) {
    asm volatile(
        "mma.sync.aligned.m16n8k16.row.col.f32.bf16.bf16.f32 "
        "{%0,%1,%2,%3}, {%4,%5,%6,%7}, {%8,%9}, {%0,%1,%2,%3};"
        : "+f"(d[0]), "+f"(d[1]), "+f"(d[2]), "+f"(d[3])
        : "r"(a[0]), "r"(a[1]), "r"(a[2]), "r"(a[3]), "r"(b[0]), "r"(b[1]));
}
__device__ __forceinline__ uint32_t pack_bf2(float a, float b) {
    __nv_bfloat162 t;
    t.x = __float2bfloat16(a); t.y = __float2bfloat16(b);
    return *(uint32_t*)&t;
}

// ---------------- batched fp32 -> split bf16 ----------------
struct SplitSrc { const float* p[4]; };
__global__ __launch_bounds__(256)
void split_b(SplitSrc s, __nv_bfloat16* __restrict__ hi, __nv_bfloat16* __restrict__ lo, int n4)
{
    int i = blockIdx.x * 256 + threadIdx.x;
    if (i >= n4) return;
    int z = blockIdx.y;
    const float* src = s.p[z];
    __nv_bfloat16* hz = hi + (size_t)z * XN;
    __nv_bfloat16* lz = lo + (size_t)z * XN;
    float4 v = ((const float4*)src)[i];
    __nv_bfloat16 h0 = __float2bfloat16(v.x), h1 = __float2bfloat16(v.y);
    __nv_bfloat16 h2 = __float2bfloat16(v.z), h3 = __float2bfloat16(v.w);
    __nv_bfloat162 hh0{h0, h1}, hh1{h2, h3};
    __nv_bfloat162 ll0, ll1;
    ll0.x = __float2bfloat16(v.x - __bfloat162float(h0));
    ll0.y = __float2bfloat16(v.y - __bfloat162float(h1));
    ll1.x = __float2bfloat16(v.z - __bfloat162float(h2));
    ll1.y = __float2bfloat16(v.w - __bfloat162float(h3));
    ((__nv_bfloat162*)hz)[i*2] = hh0;  ((__nv_bfloat162*)hz)[i*2+1] = hh1;
    ((__nv_bfloat162*)lz)[i*2] = ll0;  ((__nv_bfloat162*)lz)[i*2+1] = ll1;
}

// ---------------- batched W[k][n] -> W^T[n][k] split ----------------
struct WSrc { const float* p[8]; };
__global__ __launch_bounds__(256)
void splitT_b(WSrc s, __nv_bfloat16* __restrict__ hiT, __nv_bfloat16* __restrict__ loT)
{
    __shared__ float t[32][33];
    int z = blockIdx.z;
    const float* W = s.p[z];
    __nv_bfloat16* hz = hiT + (size_t)z * WN;
    __nv_bfloat16* lz = loT + (size_t)z * WN;
    int bx = blockIdx.x * 32, by = blockIdx.y * 32;
    int tx = threadIdx.x, ty = threadIdx.y;
#pragma unroll
    for (int j = 0; j < 4; j++)
        t[ty + 8*j][tx] = W[(size_t)(by + ty + 8*j) * HID_ + bx + tx];
    __syncthreads();
#pragma unroll
    for (int j = 0; j < 4; j++) {
        float v = t[tx][ty + 8*j];
        int n = bx + ty + 8*j, k = by + tx;
        __nv_bfloat16 h = __float2bfloat16(v);
        hz[(size_t)n * HID_ + k] = h;
        lz[(size_t)n * HID_ + k] = __float2bfloat16(v - __bfloat162float(h));
    }
}

// ---------------- GEMM core: CTA 128x256, warp 64x64, 3-stage cp.async ----------------
#define KC        64
#define NCHUNK    48
#define ROWB      144u
#define ATILE_B   (128u*ROWB)            // 18432
#define STAGE_B   (384u*ROWB)            // 55296 (A 128 rows + B 256 rows)
#define GEMM_SMEM (3*STAGE_B)            // 165888

__device__ __forceinline__ void gemm_load_tile(
    uint32_t sbase, int stage, int c, int m0, int n0, int tid,
    const __nv_bfloat16* Ah, const __nv_bfloat16* Al,
    const __nv_bfloat16* Bh, const __nv_bfloat16* Bl)
{
    const __nv_bfloat16* asrc = (c < 32) ? Ah : Al;
    const __nv_bfloat16* bsrc = (c < 16) ? Bh : ((c < 32) ? Bl : Bh);
    const int k0 = (c & 15) * KC;
    const uint32_t dstA = sbase + (uint32_t)stage * STAGE_B;
    const uint32_t dstB = dstA + ATILE_B;
#pragma unroll
    for (int i = 0; i < 12; i++) {
        int idx = i * 256 + tid;                 // 0..3071 16B segments
        if (idx < 1024) {
            int r = idx >> 3, c16 = idx & 7;
            cp16(dstA + r * ROWB + c16 * 16, asrc + (size_t)(m0 + r) * HID_ + k0 + c16 * 8);
        } else {
            int j = idx - 1024;
            int r = j >> 3, c16 = j & 7;         // r 0..255
            cp16(dstB + r * ROWB + c16 * 16, bsrc + (size_t)(n0 + r) * HID_ + k0 + c16 * 8);
        }
    }
    asm volatile("cp.async.commit_group;");
}

__device__ __forceinline__ void gemm_core(
    uint32_t sbase, int m0, int n0, int tid, int wm, int wn, int lane,
    const __nv_bfloat16* Ah, const __nv_bfloat16* Al,
    const __nv_bfloat16* Bh, const __nv_bfloat16* Bl,
    float acc[4][8][4])
{
    const uint32_t a_l = (uint32_t)(wm * 64 + (lane & 7) + ((lane >> 3) & 1) * 8) * ROWB
                       + (lane >> 4) * 16;
    const uint32_t b_l = (uint32_t)(wn * 64 + (lane & 7) + ((lane >> 4) & 1) * 8) * ROWB
                       + ((lane >> 3) & 1) * 16;

    gemm_load_tile(sbase, 0, 0, m0, n0, tid, Ah, Al, Bh, Bl);
    gemm_load_tile(sbase, 1, 1, m0, n0, tid, Ah, Al, Bh, Bl);

    for (int c = 0; c < NCHUNK; c++) {
        if (c < NCHUNK - 1) asm volatile("cp.async.wait_group 1;" ::: "memory");
        else                asm volatile("cp.async.wait_group 0;" ::: "memory");
        __syncthreads();
        if (c + 2 < NCHUNK)
            gemm_load_tile(sbase, (c + 2) % 3, c + 2, m0, n0, tid, Ah, Al, Bh, Bl);

        const uint32_t sb = sbase + (uint32_t)(c % 3) * STAGE_B;
        const uint32_t aBase = sb + a_l;
        const uint32_t bBase = sb + ATILE_B + b_l;
#pragma unroll
        for (int kk = 0; kk < KC / 16; kk++) {
            const uint32_t koff = kk * 32;
            uint32_t aq[4][4];
#pragma unroll
            for (int mf = 0; mf < 4; mf++)
                ldm_x4(aq[mf], aBase + mf * 16 * ROWB + koff);
            uint32_t bq[16];
#pragma unroll
            for (int np = 0; np < 4; np++)
                ldm_x4(&bq[np * 4], bBase + np * 16 * ROWB + koff);
#pragma unroll
            for (int mf = 0; mf < 4; mf++)
#pragma unroll
                for (int nf = 0; nf < 8; nf++)
                    mma16816(acc[mf][nf], aq[mf], &bq[(nf >> 1) * 4 + (nf & 1) * 2]);
        }
    }
}

// ---------------- batched projection GEMMs ----------------
struct GemmB {
    const __nv_bfloat16 *Ah[7], *Al[7], *Bh[7], *Bl[7];
    const float* bias[7];
    __nv_bfloat16 *Oh[7], *Ol[7];
    int mode[7];   // 0 = QK scatter, 1 = V transpose
    int part[7];
};

__global__ __launch_bounds__(256, 1)
void gemm_batch(GemmB args)
{
    extern __shared__ char smem[];
    const uint32_t sbase = smem_u32(smem);
    const int z = blockIdx.z;
    const int tid = threadIdx.x;
    const int wid = tid >> 5, lane = tid & 31;
    const int m0 = blockIdx.y * 128, n0 = blockIdx.x * 256;
    const int wm = wid & 1, wn = wid >> 1;

    float acc[4][8][4];
#pragma unroll
    for (int mf = 0; mf < 4; mf++)
#pragma unroll
        for (int nf = 0; nf < 8; nf++)
#pragma unroll
            for (int q = 0; q < 4; q++) acc[mf][nf][q] = 0.f;

    gemm_core(sbase, m0, n0, tid, wm, wn, lane,
              args.Ah[z], args.Al[z], args.Bh[z], args.Bl[z], acc);

    const float* bias = args.bias[z];
    __nv_bfloat16* Oh = args.Oh[z];
    __nv_bfloat16* Ol = args.Ol[z];
    const int mode = args.mode[z], part = args.part[z];

    const int g = lane >> 2, tq = lane & 3;
    float2 bv[8];
#pragma unroll
    for (int nf = 0; nf < 8; nf++)
        bv[nf] = *(const float2*)(bias + n0 + wn * 64 + nf * 8 + 2 * tq);

#pragma unroll
    for (int mf = 0; mf < 4; mf++) {
#pragma unroll
        for (int half = 0; half < 2; half++) {
            const int m = m0 + wm * 64 + mf * 16 + g + half * 8;
            const int bb = m >> 9, ll = m & 511;
#pragma unroll
            for (int nf = 0; nf < 8; nf++) {
                const int n = n0 + wn * 64 + nf * 8 + 2 * tq;
                const int h = n >> 6, dd = n & 63;
                float vx = acc[mf][nf][half * 2 + 0] + bv[nf].x;
                float vy = acc[mf][nf][half * 2 + 1] + bv[nf].y;
                __nv_bfloat16 hx = __float2bfloat16(vx), hy = __float2bfloat16(vy);
                __nv_bfloat16 lx = __float2bfloat16(vx - __bfloat162float(hx));
                __nv_bfloat16 ly = __float2bfloat16(vy - __bfloat162float(hy));
                if (mode == 0) {
                    size_t dst = ((((size_t)bb * NH_ + h) * L_ + ll) * DCAT)
                               + (size_t)part * 64 + dd;
                    __nv_bfloat162 hi2{hx, hy}, lo2{lx, ly};
                    *(__nv_bfloat162*)(Oh + dst) = hi2;
                    *(__nv_bfloat162*)(Ol + dst) = lo2;
                } else {
                    size_t dst = (((size_t)bb * NH_ + h) * HD_ + dd) * L_ + ll;
                    Oh[dst] = hx;  Ol[dst] = lx;
                    Oh[dst + L_] = hy;  Ol[dst + L_] = ly;
                }
            }
        }
    }
}

// ---------------- output projection GEMM (fp32 out) ----------------
__global__ __launch_bounds__(256, 1)
void gemm_out(const __nv_bfloat16* __restrict__ Ah, const __nv_bfloat16* __restrict__ Al,
              const __nv_bfloat16* __restrict__ Bh, const __nv_bfloat16* __restrict__ Bl,
              const float* __restrict__ bias, float* __restrict__ out)
{
    extern __shared__ char smem[];
    const uint32_t sbase = smem_u32(smem);
    const int tid = threadIdx.x;
    const int wid = tid >> 5, lane = tid & 31;
    const int m0 = blockIdx.y * 128, n0 = blockIdx.x * 256;
    const int wm = wid & 1, wn = wid >> 1;

    float acc[4][8][4];
#pragma unroll
    for (int mf = 0; mf < 4; mf++)
#pragma unroll
        for (int nf = 0; nf < 8; nf++)
#pragma unroll
            for (int q = 0; q < 4; q++) acc[mf][nf][q] = 0.f;

    gemm_core(sbase, m0, n0, tid, wm, wn, lane, Ah, Al, Bh, Bl, acc);

    const int g = lane >> 2, tq = lane & 3;
    float2 bv[8];
#pragma unroll
    for (int nf = 0; nf < 8; nf++)
        bv[nf] = *(const float2*)(bias + n0 + wn * 64 + nf * 8 + 2 * tq);
#pragma unroll
    for (int mf = 0; mf < 4; mf++)
#pragma unroll
        for (int half = 0; half < 2; half++) {
            const int m = m0 + wm * 64 + mf * 16 + g + half * 8;
#pragma unroll
            for (int nf = 0; nf < 8; nf++) {
                const int n = n0 + wn * 64 + nf * 8 + 2 * tq;
                float2 v;
                v.x = acc[mf][nf][half * 2 + 0] + bv[nf].x;
                v.y = acc[mf][nf][half * 2 + 1] + bv[nf].y;
                *(float2*)(out + (size_t)m * HID_ + n) = v;
            }
        }
}

// ---------------- flash attention via mma.sync (unchanged from R4) ----------------
#define AQ_STRIDE 400u
#define AV_STRIDE 144u
#define SM_QH 0u
#define SM_QL 51200u
#define SM_KH 102400u
#define SM_KL 128000u
#define SM_VH 153600u
#define SM_VL 162816u
#define ATT_SMEM 172032

__global__ __launch_bounds__(256, 1)
void attn_mma(const float* __restrict__ rel,
              const __nv_bfloat16* __restrict__ Qh, const __nv_bfloat16* __restrict__ Ql,
              const __nv_bfloat16* __restrict__ Kh, const __nv_bfloat16* __restrict__ Kl,
              const __nv_bfloat16* __restrict__ Vth, const __nv_bfloat16* __restrict__ Vtl,
              __nv_bfloat16* __restrict__ Oh, __nv_bfloat16* __restrict__ Ol)
{
    extern __shared__ char smc[];
    const uint32_t sb = smem_u32(smc);
    const int qt = blockIdx.x, bh = blockIdx.y;
    const int q0 = qt * 128;
    const int tid = threadIdx.x, wid = tid >> 5, lane = tid & 31;
    const int g = lane >> 2, tq = lane & 3;
    const int wrow = wid * 16;

    const __nv_bfloat16* qh_g = Qh  + (size_t)bh * L_ * DCAT;
    const __nv_bfloat16* ql_g = Ql  + (size_t)bh * L_ * DCAT;
    const __nv_bfloat16* kh_g = Kh  + (size_t)bh * L_ * DCAT;
    const __nv_bfloat16* kl_g = Kl  + (size_t)bh * L_ * DCAT;
    const __nv_bfloat16* vh_g = Vth + (size_t)bh * HD_ * L_;
    const __nv_bfloat16* vl_g = Vtl + (size_t)bh * HD_ * L_;
    const float* relg = rel + (size_t)bh * L_ * L_;

#pragma unroll
    for (int i = 0; i < 24; i++) {
        int idx = i * 256 + tid;
        int mat = idx >= 3072;
        int j = idx - mat * 3072;
        int r = j / 24, s2 = j % 24;
        cp16(sb + (mat ? SM_QL : SM_QH) + r * AQ_STRIDE + s2 * 16,
             (mat ? ql_g : qh_g) + (size_t)(q0 + r) * DCAT + s2 * 8);
    }
    asm volatile("cp.async.commit_group;");

    float m_i[2] = {-3.0e38f, -3.0e38f};
    float l_i[2] = {0.f, 0.f};
    float oacc[8][4];
#pragma unroll
    for (int nf = 0; nf < 8; nf++)
#pragma unroll
        for (int q = 0; q < 4; q++) oacc[nf][q] = 0.f;

    const uint32_t aoffQ = (uint32_t)(wrow + (lane & 7) + ((lane >> 3) & 1) * 8) * AQ_STRIDE
                         + (lane >> 4) * 16;
    const uint32_t boffK = (uint32_t)((lane & 7) + ((lane >> 4) & 1) * 8) * AQ_STRIDE
                         + ((lane >> 3) & 1) * 16;
    const uint32_t boffV = (uint32_t)((lane & 7) + ((lane >> 4) & 1) * 8) * AV_STRIDE
                         + ((lane >> 3) & 1) * 16;

    const int ntiles = qt * 2 + 2;
    for (int kt = 0; kt < ntiles; kt++) {
        const int k0 = kt * 64;
        __syncthreads();
#pragma unroll
        for (int i = 0; i < 16; i++) {
            int idx = i * 256 + tid;
            if (idx < 3072) {
                int mat = idx >= 1536;
                int j = idx - mat * 1536;
                int r = j / 24, s2 = j % 24;
                cp16(sb + (mat ? SM_KL : SM_KH) + r * AQ_STRIDE + s2 * 16,
                     (mat ? kl_g : kh_g) + (size_t)(k0 + r) * DCAT + s2 * 8);
            } else {
                int j = idx - 3072;
                int mat = j >= 512;
                j -= mat * 512;
                int d = j / 8, s2 = j % 8;
                cp16(sb + (mat ? SM_VL : SM_VH) + d * AV_STRIDE + s2 * 16,
                     (mat ? vl_g : vh_g) + (size_t)d * L_ + k0 + s2 * 8);
            }
        }
        asm volatile("cp.async.commit_group;");
        asm volatile("cp.async.wait_group 0;" ::: "memory");
        __syncthreads();

        if (k0 > q0 + wrow + 15) continue;

        float sacc[8][4];
#pragma unroll
        for (int nf = 0; nf < 8; nf++)
#pragma unroll
            for (int q = 0; q < 4; q++) sacc[nf][q] = 0.f;

#pragma unroll
        for (int ks = 0; ks < 12; ks++) {
            const uint32_t koff = ks * 32;
            uint32_t aqh[4], aql[4], bqh[16], bql[16];
            ldm_x4(aqh, sb + SM_QH + aoffQ + koff);
            ldm_x4(aql, sb + SM_QL + aoffQ + koff);
#pragma unroll
            for (int np = 0; np < 4; np++) {
                ldm_x4(&bqh[np * 4], sb + SM_KH + boffK + np * 16 * AQ_STRIDE + koff);
                ldm_x4(&bql[np * 4], sb + SM_KL + boffK + np * 16 * AQ_STRIDE + koff);
            }
#pragma unroll
            for (int nf = 0; nf < 8; nf++) {
                const uint32_t* bh_ = &bqh[(nf >> 1) * 4 + (nf & 1) * 2];
                const uint32_t* bl_ = &bql[(nf >> 1) * 4 + (nf & 1) * 2];
                mma16816(sacc[nf], aqh, bh_);
                mma16816(sacc[nf], aqh, bl_);
                mma16816(sacc[nf], aql, bh_);
            }
        }

        const int row0 = q0 + wrow + g;
        const int row1 = row0 + 8;
        const bool diag = (k0 + 63 > q0 + wrow);
        float pmax0 = -3.0e38f, pmax1 = -3.0e38f;
#pragma unroll
        for (int nf = 0; nf < 8; nf++) {
            const int col = k0 + nf * 8 + 2 * tq;
            float2 r0 = *(const float2*)(relg + (size_t)row0 * L_ + col);
            float2 r1 = *(const float2*)(relg + (size_t)row1 * L_ + col);
            float s0 = fmaf(sacc[nf][0], 0.125f, r0.x);
            float s1 = fmaf(sacc[nf][1], 0.125f, r0.y);
            float s2 = fmaf(sacc[nf][2], 0.125f, r1.x);
            float s3 = fmaf(sacc[nf][3], 0.125f, r1.y);
            if (diag) {
                if (col     > row0) s0 = -3.0e38f;
                if (col + 1 > row0) s1 = -3.0e38f;
                if (col     > row1) s2 = -3.0e38f;
                if (col + 1 > row1) s3 = -3.0e38f;
            }
            sacc[nf][0] = s0; sacc[nf][1] = s1; sacc[nf][2] = s2; sacc[nf][3] = s3;
            pmax0 = fmaxf(pmax0, fmaxf(s0, s1));
            pmax1 = fmaxf(pmax1, fmaxf(s2, s3));
        }
#pragma unroll
        for (int d = 1; d < 4; d <<= 1) {
            pmax0 = fmaxf(pmax0, __shfl_xor_sync(0xffffffffu, pmax0, d));
            pmax1 = fmaxf(pmax1, __shfl_xor_sync(0xffffffffu, pmax1, d));
        }
        const float nm0 = fmaxf(m_i[0], pmax0);
        const float nm1 = fmaxf(m_i[1], pmax1);
        const float al0 = __expf(m_i[0] - nm0);
        const float al1 = __expf(m_i[1] - nm1);
        float rs0 = 0.f, rs1 = 0.f;
#pragma unroll
        for (int nf = 0; nf < 8; nf++) {
            sacc[nf][0] = __expf(sacc[nf][0] - nm0);
            sacc[nf][1] = __expf(sacc[nf][1] - nm0);
            sacc[nf][2] = __expf(sacc[nf][2] - nm1);
            sacc[nf][3] = __expf(sacc[nf][3] - nm1);
            rs0 += sacc[nf][0] + sacc[nf][1];
            rs1 += sacc[nf][2] + sacc[nf][3];
        }
#pragma unroll
        for (int d = 1; d < 4; d <<= 1) {
            rs0 += __shfl_xor_sync(0xffffffffu, rs0, d);
            rs1 += __shfl_xor_sync(0xffffffffu, rs1, d);
        }
        l_i[0] = l_i[0] * al0 + rs0;  m_i[0] = nm0;
        l_i[1] = l_i[1] * al1 + rs1;  m_i[1] = nm1;
#pragma unroll
        for (int nf = 0; nf < 8; nf++) {
            oacc[nf][0] *= al0; oacc[nf][1] *= al0;
            oacc[nf][2] *= al1; oacc[nf][3] *= al1;
        }

#pragma unroll
        for (int ks = 0; ks < 4; ks++) {
            uint32_t afh[4], afl[4];
            {
                float p00 = sacc[2*ks][0],   p01 = sacc[2*ks][1];
                float p02 = sacc[2*ks][2],   p03 = sacc[2*ks][3];
                float p10 = sacc[2*ks+1][0], p11 = sacc[2*ks+1][1];
                float p12 = sacc[2*ks+1][2], p13 = sacc[2*ks+1][3];
                afh[0] = pack_bf2(p00, p01);
                afh[1] = pack_bf2(p02, p03);
                afh[2] = pack_bf2(p10, p11);
                afh[3] = pack_bf2(p12, p13);
                __nv_bfloat162 h0 = *(__nv_bfloat162*)&afh[0];
                __nv_bfloat162 h1 = *(__nv_bfloat162*)&afh[1];
                __nv_bfloat162 h2 = *(__nv_bfloat162*)&afh[2];
                __nv_bfloat162 h3 = *(__nv_bfloat162*)&afh[3];
                afl[0] = pack_bf2(p00 - __bfloat162float(h0.x), p01 - __bfloat162float(h0.y));
                afl[1] = pack_bf2(p02 - __bfloat162float(h1.x), p03 - __bfloat162float(h1.y));
                afl[2] = pack_bf2(p10 - __bfloat162float(h2.x), p11 - __bfloat162float(h2.y));
                afl[3] = pack_bf2(p12 - __bfloat162float(h3.x), p13 - __bfloat162float(h3.y));
            }
            uint32_t bvh[16], bvl[16];
            const uint32_t koff = ks * 32;
#pragma unroll
            for (int np = 0; np < 4; np++) {
                ldm_x4(&bvh[np * 4], sb + SM_VH + boffV + np * 16 * AV_STRIDE + koff);
                ldm_x4(&bvl[np * 4], sb + SM_VL + boffV + np * 16 * AV_STRIDE + koff);
            }
#pragma unroll
            for (int nf = 0; nf < 8; nf++) {
                const uint32_t* bh_ = &bvh[(nf >> 1) * 4 + (nf & 1) * 2];
                const uint32_t* bl_ = &bvl[(nf >> 1) * 4 + (nf & 1) * 2];
                mma16816(oacc[nf], afh, bh_);
                mma16816(oacc[nf], afh, bl_);
                mma16816(oacc[nf], afl, bh_);
            }
        }
    }

    const int b = bh >> 4, h = bh & 15;
    const float inv0 = 1.0f / l_i[0];
    const float inv1 = 1.0f / l_i[1];
    const size_t m0g = (size_t)(b * L_ + q0 + wrow + g) * HID_;
    const size_t m1g = m0g + 8 * HID_;
#pragma unroll
    for (int nf = 0; nf < 8; nf++) {
        const int col = h * 64 + nf * 8 + 2 * tq;
        float v0 = oacc[nf][0] * inv0, v1 = oacc[nf][1] * inv0;
        float v2 = oacc[nf][2] * inv1, v3 = oacc[nf][3] * inv1;
        __nv_bfloat162 hi0, lo0, hi1, lo1;
        hi0.x = __float2bfloat16(v0); hi0.y = __float2bfloat16(v1);
        lo0.x = __float2bfloat16(v0 - __bfloat162float(hi0.x));
        lo0.y = __float2bfloat16(v1 - __bfloat162float(hi0.y));
        hi1.x = __float2bfloat16(v2); hi1.y = __float2bfloat16(v3);
        lo1.x = __float2bfloat16(v2 - __bfloat162float(hi1.x));
        lo1.y = __float2bfloat16(v3 - __bfloat162float(hi1.y));
        *(__nv_bfloat162*)(Oh + m0g + col) = hi0;
        *(__nv_bfloat162*)(Ol + m0g + col) = lo0;
        *(__nv_bfloat162*)(Oh + m1g + col) = hi1;
        *(__nv_bfloat162*)(Ol + m1g + col) = lo1;
    }
}

// ---------------- launcher ----------------
extern "C" void kernel_launch(void* const* d_in, const int* in_sizes, int n_in,
                              void* d_out, int out_size)
{
    const float* rel = (const float*)d_in[5];
    float* out = (float*)d_out;

    __nv_bfloat16 *xh, *xl, *wh, *wl, *qh, *ql, *kh, *kl, *vth, *vtl;
    cudaGetSymbolAddress((void**)&xh, g_xh);
    cudaGetSymbolAddress((void**)&xl, g_xl);
    cudaGetSymbolAddress((void**)&wh, g_wh);
    cudaGetSymbolAddress((void**)&wl, g_wl);
    cudaGetSymbolAddress((void**)&qh, g_qh);
    cudaGetSymbolAddress((void**)&ql, g_ql);
    cudaGetSymbolAddress((void**)&kh, g_kh);
    cudaGetSymbolAddress((void**)&kl, g_kl);
    cudaGetSymbolAddress((void**)&vth, g_vth);
    cudaGetSymbolAddress((void**)&vtl, g_vtl);

    cudaFuncSetAttribute(gemm_batch, cudaFuncAttributeMaxDynamicSharedMemorySize, GEMM_SMEM);
    cudaFuncSetAttribute(gemm_out, cudaFuncAttributeMaxDynamicSharedMemorySize, GEMM_SMEM);
    cudaFuncSetAttribute(attn_mma, cudaFuncAttributeMaxDynamicSharedMemorySize, ATT_SMEM);

    const int n4 = (int)(XN / 4);

    SplitSrc ss;
    ss.p[0] = (const float*)d_in[0];
    ss.p[1] = (const float*)d_in[1];
    ss.p[2] = (const float*)d_in[2];
    ss.p[3] = (const float*)d_in[3];
    split_b<<<dim3((n4 + 255) / 256, 4), 256>>>(ss, xh, xl, n4);

    WSrc ws;
    ws.p[0] = (const float*)d_in[6];   ws.p[1] = (const float*)d_in[8];
    ws.p[2] = (const float*)d_in[10];  ws.p[3] = (const float*)d_in[12];
    ws.p[4] = (const float*)d_in[14];  ws.p[5] = (const float*)d_in[16];
    ws.p[6] = (const float*)d_in[18];  ws.p[7] = (const float*)d_in[20];
    splitT_b<<<dim3(32, 32, 8), dim3(32, 8)>>>(ws, wh, wl);

    GemmB gb;
    const int ain[7]  = {0, 1, 2, 0, 1, 2, 3};
    const int wsl[7]  = {0, 3, 5, 1, 4, 6, 2};
    const int bidx[7] = {7, 13, 17, 9, 15, 19, 11};
    for (int z = 0; z < 7; z++) {
        gb.Ah[z] = xh + (size_t)ain[z] * XN;
        gb.Al[z] = xl + (size_t)ain[z] * XN;
        gb.Bh[z] = wh + (size_t)wsl[z] * WN;
        gb.Bl[z] = wl + (size_t)wsl[z] * WN;
        gb.bias[z] = (const float*)d_in[bidx[z]];
    }
    gb.Oh[0] = qh;  gb.Ol[0] = ql;  gb.mode[0] = 0; gb.part[0] = 0;
    gb.Oh[1] = qh;  gb.Ol[1] = ql;  gb.mode[1] = 0; gb.part[1] = 1;
    gb.Oh[2] = qh;  gb.Ol[2] = ql;  gb.mode[2] = 0; gb.part[2] = 2;
    gb.Oh[3] = kh;  gb.Ol[3] = kl;  gb.mode[3] = 0; gb.part[3] = 0;
    gb.Oh[4] = kh;  gb.Ol[4] = kl;  gb.mode[4] = 0; gb.part[4] = 1;
    gb.Oh[5] = kh;  gb.Ol[5] = kl;  gb.mode[5] = 0; gb.part[5] = 2;
    gb.Oh[6] = vth; gb.Ol[6] = vtl; gb.mode[6] = 1; gb.part[6] = 0;
    gemm_batch<<<dim3(4, 64, 7), 256, GEMM_SMEM>>>(gb);

    attn_mma<<<dim3(4, 256), 256, ATT_SMEM>>>(rel, qh, ql, kh, kl, vth, vtl,
                                              xh + 4 * XN, xl + 4 * XN);

    gemm_out<<<dim3(4, 64), 256, GEMM_SMEM>>>(xh + 4 * XN, xl + 4 * XN,
                                              wh + 7 * WN, wl + 7 * WN,
                                              (const float*)d_in[21], out);
}

// round 6
// speedup vs baseline: 1.0537x; 1.0537x over previous
#include <cuda_runtime.h>
#include <cuda_bf16.h>
#include <cstdint>

#define B_    16
#define L_    512
#define HID_  1024
#define NH_   16
#define HD_   64
#define M_TOT (B_*L_)      // 8192
#define DCAT  192
#define XN    ((size_t)M_TOT*HID_)
#define WN    ((size_t)HID_*HID_)

// ---------------- scratch (static device arrays) ----------------
__device__ __nv_bfloat16 g_xh[5ULL*XN];
__device__ __nv_bfloat16 g_xl[5ULL*XN];
__device__ __nv_bfloat16 g_wh[8ULL*WN];
__device__ __nv_bfloat16 g_wl[8ULL*WN];
__device__ __nv_bfloat16 g_qh[(size_t)B_*NH_*L_*DCAT];
__device__ __nv_bfloat16 g_ql[(size_t)B_*NH_*L_*DCAT];
__device__ __nv_bfloat16 g_kh[(size_t)B_*NH_*L_*DCAT];
__device__ __nv_bfloat16 g_kl[(size_t)B_*NH_*L_*DCAT];
__device__ __nv_bfloat16 g_vth[(size_t)B_*NH_*HD_*L_];
__device__ __nv_bfloat16 g_vtl[(size_t)B_*NH_*HD_*L_];

// ---------------- PTX helpers (baseline ISA only) ----------------
__device__ __forceinline__ uint32_t smem_u32(const void* p) {
    uint32_t a;
    asm("{ .reg .u64 t; cvta.to.shared.u64 t, %1; cvt.u32.u64 %0, t; }" : "=r"(a) : "l"(p));
    return a;
}
__device__ __forceinline__ void cp16(uint32_t dst, const void* src) {
    asm volatile("cp.async.cg.shared.global [%0], [%1], 16;" :: "r"(dst), "l"(src));
}
__device__ __forceinline__ void ldm_x4(uint32_t* r, uint32_t addr) {
    asm volatile("ldmatrix.sync.aligned.m8n8.x4.shared.b16 {%0,%1,%2,%3}, [%4];"
                 : "=r"(r[0]), "=r"(r[1]), "=r"(r[2]), "=r"(r[3]) : "r"(addr));
}
__device__ __forceinline__ void mma16816(float* d, const uint32_t* a, const uint32_t* b) {
    asm volatile(
        "mma.sync.aligned.m16n8k16.row.col.f32.bf16.bf16.f32 "
        "{%0,%1,%2,%3}, {%4,%5,%6,%7}, {%8,%9}, {%0,%1,%2,%3};"
        : "+f"(d[0]), "+f"(d[1]), "+f"(d[2]), "+f"(d[3])
        : "r"(a[0]), "r"(a[1]), "r"(a[2]), "r"(a[3]), "r"(b[0]), "r"(b[1]));
}
__device__ __forceinline__ uint32_t pack_bf2(float a, float b) {
    __nv_bfloat162 t;
    t.x = __float2bfloat16(a); t.y = __float2bfloat16(b);
    return *(uint32_t*)&t;
}

// ---------------- batched fp32 -> split bf16 ----------------
struct SplitSrc { const float* p[4]; };
__global__ __launch_bounds__(256)
void split_b(SplitSrc s, __nv_bfloat16* __restrict__ hi, __nv_bfloat16* __restrict__ lo, int n4)
{
    int i = blockIdx.x * 256 + threadIdx.x;
    if (i >= n4) return;
    int z = blockIdx.y;
    const float* src = s.p[z];
    __nv_bfloat16* hz = hi + (size_t)z * XN;
    __nv_bfloat16* lz = lo + (size_t)z * XN;
    float4 v = ((const float4*)src)[i];
    __nv_bfloat16 h0 = __float2bfloat16(v.x), h1 = __float2bfloat16(v.y);
    __nv_bfloat16 h2 = __float2bfloat16(v.z), h3 = __float2bfloat16(v.w);
    __nv_bfloat162 hh0{h0, h1}, hh1{h2, h3};
    __nv_bfloat162 ll0, ll1;
    ll0.x = __float2bfloat16(v.x - __bfloat162float(h0));
    ll0.y = __float2bfloat16(v.y - __bfloat162float(h1));
    ll1.x = __float2bfloat16(v.z - __bfloat162float(h2));
    ll1.y = __float2bfloat16(v.w - __bfloat162float(h3));
    ((__nv_bfloat162*)hz)[i*2] = hh0;  ((__nv_bfloat162*)hz)[i*2+1] = hh1;
    ((__nv_bfloat162*)lz)[i*2] = ll0;  ((__nv_bfloat162*)lz)[i*2+1] = ll1;
}

// ---------------- batched W[k][n] -> W^T[n][k] split ----------------
struct WSrc { const float* p[8]; };
__global__ __launch_bounds__(256)
void splitT_b(WSrc s, __nv_bfloat16* __restrict__ hiT, __nv_bfloat16* __restrict__ loT)
{
    __shared__ float t[32][33];
    int z = blockIdx.z;
    const float* W = s.p[z];
    __nv_bfloat16* hz = hiT + (size_t)z * WN;
    __nv_bfloat16* lz = loT + (size_t)z * WN;
    int bx = blockIdx.x * 32, by = blockIdx.y * 32;
    int tx = threadIdx.x, ty = threadIdx.y;
#pragma unroll
    for (int j = 0; j < 4; j++)
        t[ty + 8*j][tx] = W[(size_t)(by + ty + 8*j) * HID_ + bx + tx];
    __syncthreads();
#pragma unroll
    for (int j = 0; j < 4; j++) {
        float v = t[tx][ty + 8*j];
        int n = bx + ty + 8*j, k = by + tx;
        __nv_bfloat16 h = __float2bfloat16(v);
        hz[(size_t)n * HID_ + k] = h;
        lz[(size_t)n * HID_ + k] = __float2bfloat16(v - __bfloat162float(h));
    }
}

// ---------------- GEMM core (R4 config): CTA 128x128, warp 32x64, 3-stage ----------------
#define KC        64
#define NCHUNK    48
#define ROWB      144u
#define ATILE_B   (128u*ROWB)
#define STAGE_B   (2u*ATILE_B)          // 36864
#define GEMM_SMEM (3*STAGE_B)           // 110592

__device__ __forceinline__ void gemm_load_tile(
    uint32_t sbase, int stage, int c, int m0, int n0, int tid,
    const __nv_bfloat16* Ah, const __nv_bfloat16* Al,
    const __nv_bfloat16* Bh, const __nv_bfloat16* Bl)
{
    const __nv_bfloat16* asrc = (c < 32) ? Ah : Al;
    const __nv_bfloat16* bsrc = (c < 16) ? Bh : ((c < 32) ? Bl : Bh);
    const int k0 = (c & 15) * KC;
    const uint32_t dstA = sbase + (uint32_t)stage * STAGE_B;
    const uint32_t dstB = dstA + ATILE_B;
#pragma unroll
    for (int i = 0; i < 8; i++) {
        int idx = i * 256 + tid;
        int r = (idx >> 3) & 127, c16 = idx & 7;
        if (idx < 1024)
            cp16(dstA + r * ROWB + c16 * 16, asrc + (size_t)(m0 + r) * HID_ + k0 + c16 * 8);
        else
            cp16(dstB + r * ROWB + c16 * 16, bsrc + (size_t)(n0 + r) * HID_ + k0 + c16 * 8);
    }
    asm volatile("cp.async.commit_group;");
}

__device__ __forceinline__ void gemm_core(
    uint32_t sbase, int m0, int n0, int tid, int wm, int wn, int lane,
    const __nv_bfloat16* Ah, const __nv_bfloat16* Al,
    const __nv_bfloat16* Bh, const __nv_bfloat16* Bl,
    float acc[2][8][4])
{
    const int arow = wm * 32 + (lane & 7) + ((lane >> 3) & 1) * 8;
    const uint32_t a_l = (uint32_t)arow * ROWB + ((lane >> 4) * 16);
    const int brow = wn * 64 + (lane & 7) + ((lane >> 4) & 1) * 8;
    const uint32_t b_l = (uint32_t)brow * ROWB + (((lane >> 3) & 1) * 16);

    gemm_load_tile(sbase, 0, 0, m0, n0, tid, Ah, Al, Bh, Bl);
    gemm_load_tile(sbase, 1, 1, m0, n0, tid, Ah, Al, Bh, Bl);

    for (int c = 0; c < NCHUNK; c++) {
        if (c < NCHUNK - 1) asm volatile("cp.async.wait_group 1;" ::: "memory");
        else                asm volatile("cp.async.wait_group 0;" ::: "memory");
        __syncthreads();
        if (c + 2 < NCHUNK)
            gemm_load_tile(sbase, (c + 2) % 3, c + 2, m0, n0, tid, Ah, Al, Bh, Bl);

        const uint32_t sb = sbase + (uint32_t)(c % 3) * STAGE_B;
        const uint32_t aBase = sb + a_l;
        const uint32_t bBase = sb + ATILE_B + b_l;
#pragma unroll
        for (int kk = 0; kk < KC / 16; kk++) {
            const uint32_t koff = kk * 32;
            uint32_t bq[16];
#pragma unroll
            for (int np = 0; np < 4; np++)
                ldm_x4(&bq[np * 4], bBase + np * 16 * ROWB + koff);
            uint32_t aq[2][4];
#pragma unroll
            for (int mf = 0; mf < 2; mf++)
                ldm_x4(aq[mf], aBase + mf * 16 * ROWB + koff);
#pragma unroll
            for (int mf = 0; mf < 2; mf++)
#pragma unroll
                for (int nf = 0; nf < 8; nf++)
                    mma16816(acc[mf][nf], aq[mf], &bq[(nf >> 1) * 4 + (nf & 1) * 2]);
        }
    }
}

// ---------------- batched projection GEMMs ----------------
struct GemmB {
    const __nv_bfloat16 *Ah[7], *Al[7], *Bh[7], *Bl[7];
    const float* bias[7];
    __nv_bfloat16 *Oh[7], *Ol[7];
    int mode[7];
    int part[7];
};

__global__ __launch_bounds__(256, 2)
void gemm_batch(GemmB args)
{
    extern __shared__ char smem[];
    const uint32_t sbase = smem_u32(smem);
    const int z = blockIdx.z;
    const int tid = threadIdx.x;
    const int wid = tid >> 5, lane = tid & 31;
    const int m0 = blockIdx.y * 128, n0 = blockIdx.x * 128;
    const int wm = wid & 3, wn = wid >> 2;

    float acc[2][8][4];
#pragma unroll
    for (int mf = 0; mf < 2; mf++)
#pragma unroll
        for (int nf = 0; nf < 8; nf++)
#pragma unroll
            for (int q = 0; q < 4; q++) acc[mf][nf][q] = 0.f;

    gemm_core(sbase, m0, n0, tid, wm, wn, lane,
              args.Ah[z], args.Al[z], args.Bh[z], args.Bl[z], acc);

    const float* bias = args.bias[z];
    __nv_bfloat16* Oh = args.Oh[z];
    __nv_bfloat16* Ol = args.Ol[z];
    const int mode = args.mode[z], part = args.part[z];

    const int g = lane >> 2, tq = lane & 3;
    float2 bv[8];
#pragma unroll
    for (int nf = 0; nf < 8; nf++)
        bv[nf] = *(const float2*)(bias + n0 + wn * 64 + nf * 8 + 2 * tq);

#pragma unroll
    for (int mf = 0; mf < 2; mf++) {
#pragma unroll
        for (int half = 0; half < 2; half++) {
            const int m = m0 + wm * 32 + mf * 16 + g + half * 8;
            const int bb = m >> 9, ll = m & 511;
#pragma unroll
            for (int nf = 0; nf < 8; nf++) {
                const int n = n0 + wn * 64 + nf * 8 + 2 * tq;
                const int h = n >> 6, dd = n & 63;
                float vx = acc[mf][nf][half * 2 + 0] + bv[nf].x;
                float vy = acc[mf][nf][half * 2 + 1] + bv[nf].y;
                __nv_bfloat16 hx = __float2bfloat16(vx), hy = __float2bfloat16(vy);
                __nv_bfloat16 lx = __float2bfloat16(vx - __bfloat162float(hx));
                __nv_bfloat16 ly = __float2bfloat16(vy - __bfloat162float(hy));
                if (mode == 0) {
                    size_t dst = ((((size_t)bb * NH_ + h) * L_ + ll) * DCAT)
                               + (size_t)part * 64 + dd;
                    __nv_bfloat162 hi2{hx, hy}, lo2{lx, ly};
                    *(__nv_bfloat162*)(Oh + dst) = hi2;
                    *(__nv_bfloat162*)(Ol + dst) = lo2;
                } else {
                    size_t dst = (((size_t)bb * NH_ + h) * HD_ + dd) * L_ + ll;
                    Oh[dst] = hx;  Ol[dst] = lx;
                    Oh[dst + L_] = hy;  Ol[dst + L_] = ly;
                }
            }
        }
    }
}

// ---------------- output projection GEMM (fp32 out) ----------------
__global__ __launch_bounds__(256, 2)
void gemm_out(const __nv_bfloat16* __restrict__ Ah, const __nv_bfloat16* __restrict__ Al,
              const __nv_bfloat16* __restrict__ Bh, const __nv_bfloat16* __restrict__ Bl,
              const float* __restrict__ bias, float* __restrict__ out)
{
    extern __shared__ char smem[];
    const uint32_t sbase = smem_u32(smem);
    const int tid = threadIdx.x;
    const int wid = tid >> 5, lane = tid & 31;
    const int m0 = blockIdx.y * 128, n0 = blockIdx.x * 128;
    const int wm = wid & 3, wn = wid >> 2;

    float acc[2][8][4];
#pragma unroll
    for (int mf = 0; mf < 2; mf++)
#pragma unroll
        for (int nf = 0; nf < 8; nf++)
#pragma unroll
            for (int q = 0; q < 4; q++) acc[mf][nf][q] = 0.f;

    gemm_core(sbase, m0, n0, tid, wm, wn, lane, Ah, Al, Bh, Bl, acc);

    const int g = lane >> 2, tq = lane & 3;
    float2 bv[8];
#pragma unroll
    for (int nf = 0; nf < 8; nf++)
        bv[nf] = *(const float2*)(bias + n0 + wn * 64 + nf * 8 + 2 * tq);
#pragma unroll
    for (int mf = 0; mf < 2; mf++)
#pragma unroll
        for (int half = 0; half < 2; half++) {
            const int m = m0 + wm * 32 + mf * 16 + g + half * 8;
#pragma unroll
            for (int nf = 0; nf < 8; nf++) {
                const int n = n0 + wn * 64 + nf * 8 + 2 * tq;
                float2 v;
                v.x = acc[mf][nf][half * 2 + 0] + bv[nf].x;
                v.y = acc[mf][nf][half * 2 + 1] + bv[nf].y;
                *(float2*)(out + (size_t)m * HID_ + n) = v;
            }
        }
}

// ---------------- flash attention: double-buffered 32-row K tiles ----------------
#define AQ_STRIDE 400u
#define AV_STRIDE 80u
#define SM_QH 0u
#define SM_QL 51200u
#define STAGE0   102400u
#define KSTG_B   35840u     // KH 12800 + KL 12800 + VH 5120 + VL 5120
#define ATT_SMEM (102400 + 2*35840)   // 174080

__global__ __launch_bounds__(256, 1)
void attn_mma(const float* __restrict__ rel,
              const __nv_bfloat16* __restrict__ Qh, const __nv_bfloat16* __restrict__ Ql,
              const __nv_bfloat16* __restrict__ Kh, const __nv_bfloat16* __restrict__ Kl,
              const __nv_bfloat16* __restrict__ Vth, const __nv_bfloat16* __restrict__ Vtl,
              __nv_bfloat16* __restrict__ Oh, __nv_bfloat16* __restrict__ Ol)
{
    extern __shared__ char smc[];
    const uint32_t sb = smem_u32(smc);
    const int qt = blockIdx.x, bh = blockIdx.y;
    const int q0 = qt * 128;
    const int tid = threadIdx.x, wid = tid >> 5, lane = tid & 31;
    const int g = lane >> 2, tq = lane & 3;
    const int wrow = wid * 16;

    const __nv_bfloat16* qh_g = Qh  + (size_t)bh * L_ * DCAT;
    const __nv_bfloat16* ql_g = Ql  + (size_t)bh * L_ * DCAT;
    const __nv_bfloat16* kh_g = Kh  + (size_t)bh * L_ * DCAT;
    const __nv_bfloat16* kl_g = Kl  + (size_t)bh * L_ * DCAT;
    const __nv_bfloat16* vh_g = Vth + (size_t)bh * HD_ * L_;
    const __nv_bfloat16* vl_g = Vtl + (size_t)bh * HD_ * L_;
    const float* relg = rel + (size_t)bh * L_ * L_;

    // Q tile load (own commit group)
#pragma unroll
    for (int i = 0; i < 24; i++) {
        int idx = i * 256 + tid;
        int mat = idx >= 3072;
        int j = idx - mat * 3072;
        int r = j / 24, s2 = j % 24;
        cp16(sb + (mat ? SM_QL : SM_QH) + r * AQ_STRIDE + s2 * 16,
             (mat ? ql_g : qh_g) + (size_t)(q0 + r) * DCAT + s2 * 8);
    }
    asm volatile("cp.async.commit_group;");

    // K/V tile loader: 32 K-rows (hi+lo) + 64 Vt-rows x 32 cols (hi+lo)
    auto load_tile = [&](int kt, int s) {
        const int k0 = kt * 32;
        const uint32_t stg = sb + STAGE0 + (uint32_t)s * KSTG_B;
#pragma unroll
        for (int i = 0; i < 8; i++) {
            int idx = i * 256 + tid;                 // 0..2047
            if (idx < 1536) {
                int mat = idx >= 768;
                int j = idx - mat * 768;
                int r = j / 24, s2 = j % 24;
                cp16(stg + (uint32_t)mat * 12800u + r * AQ_STRIDE + s2 * 16,
                     (mat ? kl_g : kh_g) + (size_t)(k0 + r) * DCAT + s2 * 8);
            } else {
                int j = idx - 1536;
                int mat = j >= 256;
                j -= mat * 256;
                int d = j >> 2, s2 = j & 3;
                cp16(stg + 25600u + (uint32_t)mat * 5120u + d * AV_STRIDE + s2 * 16,
                     (mat ? vl_g : vh_g) + (size_t)d * L_ + k0 + s2 * 8);
            }
        }
        asm volatile("cp.async.commit_group;");
    };

    const int ntiles = qt * 4 + 4;
    load_tile(0, 0);
    load_tile(1, 1);

    float m_i[2] = {-3.0e38f, -3.0e38f};
    float l_i[2] = {0.f, 0.f};
    float oacc[8][4];
#pragma unroll
    for (int nf = 0; nf < 8; nf++)
#pragma unroll
        for (int q = 0; q < 4; q++) oacc[nf][q] = 0.f;

    const uint32_t aoffQ = (uint32_t)(wrow + (lane & 7) + ((lane >> 3) & 1) * 8) * AQ_STRIDE
                         + (lane >> 4) * 16;
    const uint32_t boffK = (uint32_t)((lane & 7) + ((lane >> 4) & 1) * 8) * AQ_STRIDE
                         + ((lane >> 3) & 1) * 16;
    const uint32_t boffV = (uint32_t)((lane & 7) + ((lane >> 4) & 1) * 8) * AV_STRIDE
                         + ((lane >> 3) & 1) * 16;

    for (int kt = 0; kt < ntiles; kt++) {
        const int k0 = kt * 32;
        if (kt + 1 < ntiles) asm volatile("cp.async.wait_group 1;" ::: "memory");
        else                 asm volatile("cp.async.wait_group 0;" ::: "memory");
        __syncthreads();

        const bool active = (k0 <= q0 + wrow + 15);
        if (active) {
            const uint32_t stg = sb + STAGE0 + (uint32_t)(kt & 1) * KSTG_B;
            const uint32_t kH = stg, kL = stg + 12800u;
            const uint32_t vH = stg + 25600u, vL = stg + 30720u;

            // ---- S = Qh*Kh + Qh*Kl + Ql*Kh over k=192, 32 key cols ----
            float sacc[4][4];
#pragma unroll
            for (int nf = 0; nf < 4; nf++)
#pragma unroll
                for (int q = 0; q < 4; q++) sacc[nf][q] = 0.f;

#pragma unroll
            for (int ks = 0; ks < 12; ks++) {
                const uint32_t koff = ks * 32;
                uint32_t aqh[4], aql[4], bqh[8], bql[8];
                ldm_x4(aqh, sb + SM_QH + aoffQ + koff);
                ldm_x4(aql, sb + SM_QL + aoffQ + koff);
#pragma unroll
                for (int np = 0; np < 2; np++) {
                    ldm_x4(&bqh[np * 4], kH + boffK + np * 16 * AQ_STRIDE + koff);
                    ldm_x4(&bql[np * 4], kL + boffK + np * 16 * AQ_STRIDE + koff);
                }
#pragma unroll
                for (int nf = 0; nf < 4; nf++) {
                    const uint32_t* bh_ = &bqh[(nf >> 1) * 4 + (nf & 1) * 2];
                    const uint32_t* bl_ = &bql[(nf >> 1) * 4 + (nf & 1) * 2];
                    mma16816(sacc[nf], aqh, bh_);
                    mma16816(sacc[nf], aqh, bl_);
                    mma16816(sacc[nf], aql, bh_);
                }
            }

            // ---- bias + mask + online softmax ----
            const int row0 = q0 + wrow + g;
            const int row1 = row0 + 8;
            const bool diag = (k0 + 31 > q0 + wrow);
            float pmax0 = -3.0e38f, pmax1 = -3.0e38f;
#pragma unroll
            for (int nf = 0; nf < 4; nf++) {
                const int col = k0 + nf * 8 + 2 * tq;
                float2 r0 = *(const float2*)(relg + (size_t)row0 * L_ + col);
                float2 r1 = *(const float2*)(relg + (size_t)row1 * L_ + col);
                float s0 = fmaf(sacc[nf][0], 0.125f, r0.x);
                float s1 = fmaf(sacc[nf][1], 0.125f, r0.y);
                float s2 = fmaf(sacc[nf][2], 0.125f, r1.x);
                float s3 = fmaf(sacc[nf][3], 0.125f, r1.y);
                if (diag) {
                    if (col     > row0) s0 = -3.0e38f;
                    if (col + 1 > row0) s1 = -3.0e38f;
                    if (col     > row1) s2 = -3.0e38f;
                    if (col + 1 > row1) s3 = -3.0e38f;
                }
                sacc[nf][0] = s0; sacc[nf][1] = s1; sacc[nf][2] = s2; sacc[nf][3] = s3;
                pmax0 = fmaxf(pmax0, fmaxf(s0, s1));
                pmax1 = fmaxf(pmax1, fmaxf(s2, s3));
            }
#pragma unroll
            for (int d = 1; d < 4; d <<= 1) {
                pmax0 = fmaxf(pmax0, __shfl_xor_sync(0xffffffffu, pmax0, d));
                pmax1 = fmaxf(pmax1, __shfl_xor_sync(0xffffffffu, pmax1, d));
            }
            const float nm0 = fmaxf(m_i[0], pmax0);
            const float nm1 = fmaxf(m_i[1], pmax1);
            const float al0 = __expf(m_i[0] - nm0);
            const float al1 = __expf(m_i[1] - nm1);
            float rs0 = 0.f, rs1 = 0.f;
#pragma unroll
            for (int nf = 0; nf < 4; nf++) {
                sacc[nf][0] = __expf(sacc[nf][0] - nm0);
                sacc[nf][1] = __expf(sacc[nf][1] - nm0);
                sacc[nf][2] = __expf(sacc[nf][2] - nm1);
                sacc[nf][3] = __expf(sacc[nf][3] - nm1);
                rs0 += sacc[nf][0] + sacc[nf][1];
                rs1 += sacc[nf][2] + sacc[nf][3];
            }
#pragma unroll
            for (int d = 1; d < 4; d <<= 1) {
                rs0 += __shfl_xor_sync(0xffffffffu, rs0, d);
                rs1 += __shfl_xor_sync(0xffffffffu, rs1, d);
            }
            l_i[0] = l_i[0] * al0 + rs0;  m_i[0] = nm0;
            l_i[1] = l_i[1] * al1 + rs1;  m_i[1] = nm1;
#pragma unroll
            for (int nf = 0; nf < 8; nf++) {
                oacc[nf][0] *= al0; oacc[nf][1] *= al0;
                oacc[nf][2] *= al1; oacc[nf][3] *= al1;
            }

            // ---- O += (Ph+Pl) @ (Vh+Vl) over k=32 ----
#pragma unroll
            for (int ks = 0; ks < 2; ks++) {
                uint32_t afh[4], afl[4];
                {
                    float p00 = sacc[2*ks][0],   p01 = sacc[2*ks][1];
                    float p02 = sacc[2*ks][2],   p03 = sacc[2*ks][3];
                    float p10 = sacc[2*ks+1][0], p11 = sacc[2*ks+1][1];
                    float p12 = sacc[2*ks+1][2], p13 = sacc[2*ks+1][3];
                    afh[0] = pack_bf2(p00, p01);
                    afh[1] = pack_bf2(p02, p03);
                    afh[2] = pack_bf2(p10, p11);
                    afh[3] = pack_bf2(p12, p13);
                    __nv_bfloat162 h0 = *(__nv_bfloat162*)&afh[0];
                    __nv_bfloat162 h1 = *(__nv_bfloat162*)&afh[1];
                    __nv_bfloat162 h2 = *(__nv_bfloat162*)&afh[2];
                    __nv_bfloat162 h3 = *(__nv_bfloat162*)&afh[3];
                    afl[0] = pack_bf2(p00 - __bfloat162float(h0.x), p01 - __bfloat162float(h0.y));
                    afl[1] = pack_bf2(p02 - __bfloat162float(h1.x), p03 - __bfloat162float(h1.y));
                    afl[2] = pack_bf2(p10 - __bfloat162float(h2.x), p11 - __bfloat162float(h2.y));
                    afl[3] = pack_bf2(p12 - __bfloat162float(h3.x), p13 - __bfloat162float(h3.y));
                }
                uint32_t bvh[16], bvl[16];
                const uint32_t koff = ks * 32;
#pragma unroll
                for (int np = 0; np < 4; np++) {
                    ldm_x4(&bvh[np * 4], vH + boffV + np * 16 * AV_STRIDE + koff);
                    ldm_x4(&bvl[np * 4], vL + boffV + np * 16 * AV_STRIDE + koff);
                }
#pragma unroll
                for (int nf = 0; nf < 8; nf++) {
                    const uint32_t* bh_ = &bvh[(nf >> 1) * 4 + (nf & 1) * 2];
                    const uint32_t* bl_ = &bvl[(nf >> 1) * 4 + (nf & 1) * 2];
                    mma16816(oacc[nf], afh, bh_);
                    mma16816(oacc[nf], afh, bl_);
                    mma16816(oacc[nf], afl, bh_);
                }
            }
        }
        __syncthreads();
        if (kt + 2 < ntiles) load_tile(kt + 2, kt & 1);
    }

    // ---- epilogue ----
    const int b = bh >> 4, h = bh & 15;
    const float inv0 = 1.0f / l_i[0];
    const float inv1 = 1.0f / l_i[1];
    const size_t m0g = (size_t)(b * L_ + q0 + wrow + g) * HID_;
    const size_t m1g = m0g + 8 * HID_;
#pragma unroll
    for (int nf = 0; nf < 8; nf++) {
        const int col = h * 64 + nf * 8 + 2 * tq;
        float v0 = oacc[nf][0] * inv0, v1 = oacc[nf][1] * inv0;
        float v2 = oacc[nf][2] * inv1, v3 = oacc[nf][3] * inv1;
        __nv_bfloat162 hi0, lo0, hi1, lo1;
        hi0.x = __float2bfloat16(v0); hi0.y = __float2bfloat16(v1);
        lo0.x = __float2bfloat16(v0 - __bfloat162float(hi0.x));
        lo0.y = __float2bfloat16(v1 - __bfloat162float(hi0.y));
        hi1.x = __float2bfloat16(v2); hi1.y = __float2bfloat16(v3);
        lo1.x = __float2bfloat16(v2 - __bfloat162float(hi1.x));
        lo1.y = __float2bfloat16(v3 - __bfloat162float(hi1.y));
        *(__nv_bfloat162*)(Oh + m0g + col) = hi0;
        *(__nv_bfloat162*)(Ol + m0g + col) = lo0;
        *(__nv_bfloat162*)(Oh + m1g + col) = hi1;
        *(__nv_bfloat162*)(Ol + m1g + col) = lo1;
    }
}

// ---------------- launcher ----------------
extern "C" void kernel_launch(void* const* d_in, const int* in_sizes, int n_in,
                              void* d_out, int out_size)
{
    const float* rel = (const float*)d_in[5];
    float* out = (float*)d_out;

    __nv_bfloat16 *xh, *xl, *wh, *wl, *qh, *ql, *kh, *kl, *vth, *vtl;
    cudaGetSymbolAddress((void**)&xh, g_xh);
    cudaGetSymbolAddress((void**)&xl, g_xl);
    cudaGetSymbolAddress((void**)&wh, g_wh);
    cudaGetSymbolAddress((void**)&wl, g_wl);
    cudaGetSymbolAddress((void**)&qh, g_qh);
    cudaGetSymbolAddress((void**)&ql, g_ql);
    cudaGetSymbolAddress((void**)&kh, g_kh);
    cudaGetSymbolAddress((void**)&kl, g_kl);
    cudaGetSymbolAddress((void**)&vth, g_vth);
    cudaGetSymbolAddress((void**)&vtl, g_vtl);

    cudaFuncSetAttribute(gemm_batch, cudaFuncAttributeMaxDynamicSharedMemorySize, GEMM_SMEM);
    cudaFuncSetAttribute(gemm_out, cudaFuncAttributeMaxDynamicSharedMemorySize, GEMM_SMEM);
    cudaFuncSetAttribute(attn_mma, cudaFuncAttributeMaxDynamicSharedMemorySize, ATT_SMEM);

    const int n4 = (int)(XN / 4);

    SplitSrc ss;
    ss.p[0] = (const float*)d_in[0];
    ss.p[1] = (const float*)d_in[1];
    ss.p[2] = (const float*)d_in[2];
    ss.p[3] = (const float*)d_in[3];
    split_b<<<dim3((n4 + 255) / 256, 4), 256>>>(ss, xh, xl, n4);

    WSrc ws;
    ws.p[0] = (const float*)d_in[6];   ws.p[1] = (const float*)d_in[8];
    ws.p[2] = (const float*)d_in[10];  ws.p[3] = (const float*)d_in[12];
    ws.p[4] = (const float*)d_in[14];  ws.p[5] = (const float*)d_in[16];
    ws.p[6] = (const float*)d_in[18];  ws.p[7] = (const float*)d_in[20];
    splitT_b<<<dim3(32, 32, 8), dim3(32, 8)>>>(ws, wh, wl);

    GemmB gb;
    const int ain[7]  = {0, 1, 2, 0, 1, 2, 3};
    const int wsl[7]  = {0, 3, 5, 1, 4, 6, 2};
    const int bidx[7] = {7, 13, 17, 9, 15, 19, 11};
    for (int z = 0; z < 7; z++) {
        gb.Ah[z] = xh + (size_t)ain[z] * XN;
        gb.Al[z] = xl + (size_t)ain[z] * XN;
        gb.Bh[z] = wh + (size_t)wsl[z] * WN;
        gb.Bl[z] = wl + (size_t)wsl[z] * WN;
        gb.bias[z] = (const float*)d_in[bidx[z]];
    }
    gb.Oh[0] = qh;  gb.Ol[0] = ql;  gb.mode[0] = 0; gb.part[0] = 0;
    gb.Oh[1] = qh;  gb.Ol[1] = ql;  gb.mode[1] = 0; gb.part[1] = 1;
    gb.Oh[2] = qh;  gb.Ol[2] = ql;  gb.mode[2] = 0; gb.part[2] = 2;
    gb.Oh[3] = kh;  gb.Ol[3] = kl;  gb.mode[3] = 0; gb.part[3] = 0;
    gb.Oh[4] = kh;  gb.Ol[4] = kl;  gb.mode[4] = 0; gb.part[4] = 1;
    gb.Oh[5] = kh;  gb.Ol[5] = kl;  gb.mode[5] = 0; gb.part[5] = 2;
    gb.Oh[6] = vth; gb.Ol[6] = vtl; gb.mode[6] = 1; gb.part[6] = 0;
    gemm_batch<<<dim3(8, 64, 7), 256, GEMM_SMEM>>>(gb);

    attn_mma<<<dim3(4, 256), 256, ATT_SMEM>>>(rel, qh, ql, kh, kl, vth, vtl,
                                              xh + 4 * XN, xl + 4 * XN);

    gemm_out<<<dim3(8, 64), 256, GEMM_SMEM>>>(xh + 4 * XN, xl + 4 * XN,
                                              wh + 7 * WN, wl + 7 * WN,
                                              (const float*)d_in[21], out);
}

// round 7
// speedup vs baseline: 1.0633x; 1.0091x over previous
#include <cuda_runtime.h>
#include <cuda_bf16.h>
#include <cuda_fp16.h>
#include <cstdint>

#define B_    16
#define L_    512
#define HID_  1024
#define NH_   16
#define HD_   64
#define M_TOT (B_*L_)      // 8192
#define DCAT  192
#define XN    ((size_t)M_TOT*HID_)
#define WN    ((size_t)HID_*HID_)

// ---------------- scratch (static device arrays) ----------------
__device__ __nv_bfloat16 g_xh[5ULL*XN];
__device__ __nv_bfloat16 g_xl[5ULL*XN];
__device__ __nv_bfloat16 g_wh[8ULL*WN];
__device__ __nv_bfloat16 g_wl[8ULL*WN];
__device__ __nv_bfloat16 g_qh[(size_t)B_*NH_*L_*DCAT];
__device__ __nv_bfloat16 g_ql[(size_t)B_*NH_*L_*DCAT];
__device__ __nv_bfloat16 g_kh[(size_t)B_*NH_*L_*DCAT];
__device__ __nv_bfloat16 g_kl[(size_t)B_*NH_*L_*DCAT];
__device__ __nv_bfloat16 g_vth[(size_t)B_*NH_*HD_*L_];
__device__ __nv_bfloat16 g_vtl[(size_t)B_*NH_*HD_*L_];

// ---------------- PTX helpers (baseline ISA only) ----------------
__device__ __forceinline__ uint32_t smem_u32(const void* p) {
    uint32_t a;
    asm("{ .reg .u64 t; cvta.to.shared.u64 t, %1; cvt.u32.u64 %0, t; }" : "=r"(a) : "l"(p));
    return a;
}
__device__ __forceinline__ void cp16(uint32_t dst, const void* src) {
    asm volatile("cp.async.cg.shared.global [%0], [%1], 16;" :: "r"(dst), "l"(src));
}
__device__ __forceinline__ void ldm_x4(uint32_t* r, uint32_t addr) {
    asm volatile("ldmatrix.sync.aligned.m8n8.x4.shared.b16 {%0,%1,%2,%3}, [%4];"
                 : "=r"(r[0]), "=r"(r[1]), "=r"(r[2]), "=r"(r[3]) : "r"(addr));
}
__device__ __forceinline__ void mma16816(float* d, const uint32_t* a, const uint32_t* b) {
    asm volatile(
        "mma.sync.aligned.m16n8k16.row.col.f32.bf16.bf16.f32 "
        "{%0,%1,%2,%3}, {%4,%5,%6,%7}, {%8,%9}, {%0,%1,%2,%3};"
        : "+f"(d[0]), "+f"(d[1]), "+f"(d[2]), "+f"(d[3])
        : "r"(a[0]), "r"(a[1]), "r"(a[2]), "r"(a[3]), "r"(b[0]), "r"(b[1]));
}
__device__ __forceinline__ uint32_t pack_bf2(float a, float b) {
    __nv_bfloat162 t;
    t.x = __float2bfloat16(a); t.y = __float2bfloat16(b);
    return *(uint32_t*)&t;
}

// ---------------- batched fp32 -> split bf16 ----------------
struct SplitSrc { const float* p[4]; };
__global__ __launch_bounds__(256)
void split_b(SplitSrc s, __nv_bfloat16* __restrict__ hi, __nv_bfloat16* __restrict__ lo, int n4)
{
    int i = blockIdx.x * 256 + threadIdx.x;
    if (i >= n4) return;
    int z = blockIdx.y;
    const float* src = s.p[z];
    __nv_bfloat16* hz = hi + (size_t)z * XN;
    __nv_bfloat16* lz = lo + (size_t)z * XN;
    float4 v = ((const float4*)src)[i];
    __nv_bfloat16 h0 = __float2bfloat16(v.x), h1 = __float2bfloat16(v.y);
    __nv_bfloat16 h2 = __float2bfloat16(v.z), h3 = __float2bfloat16(v.w);
    __nv_bfloat162 hh0{h0, h1}, hh1{h2, h3};
    __nv_bfloat162 ll0, ll1;
    ll0.x = __float2bfloat16(v.x - __bfloat162float(h0));
    ll0.y = __float2bfloat16(v.y - __bfloat162float(h1));
    ll1.x = __float2bfloat16(v.z - __bfloat162float(h2));
    ll1.y = __float2bfloat16(v.w - __bfloat162float(h3));
    ((__nv_bfloat162*)hz)[i*2] = hh0;  ((__nv_bfloat162*)hz)[i*2+1] = hh1;
    ((__nv_bfloat162*)lz)[i*2] = ll0;  ((__nv_bfloat162*)lz)[i*2+1] = ll1;
}

// ---------------- batched W[k][n] -> W^T[n][k] split ----------------
struct WSrc { const float* p[8]; };
__global__ __launch_bounds__(256)
void splitT_b(WSrc s, __nv_bfloat16* __restrict__ hiT, __nv_bfloat16* __restrict__ loT)
{
    __shared__ float t[32][33];
    int z = blockIdx.z;
    const float* W = s.p[z];
    __nv_bfloat16* hz = hiT + (size_t)z * WN;
    __nv_bfloat16* lz = loT + (size_t)z * WN;
    int bx = blockIdx.x * 32, by = blockIdx.y * 32;
    int tx = threadIdx.x, ty = threadIdx.y;
#pragma unroll
    for (int j = 0; j < 4; j++)
        t[ty + 8*j][tx] = W[(size_t)(by + ty + 8*j) * HID_ + bx + tx];
    __syncthreads();
#pragma unroll
    for (int j = 0; j < 4; j++) {
        float v = t[tx][ty + 8*j];
        int n = bx + ty + 8*j, k = by + tx;
        __nv_bfloat16 h = __float2bfloat16(v);
        hz[(size_t)n * HID_ + k] = h;
        lz[(size_t)n * HID_ + k] = __float2bfloat16(v - __bfloat162float(h));
    }
}

// ---------------- GEMM core (R4 config): CTA 128x128, warp 32x64, 3-stage ----------------
#define KC        64
#define NCHUNK    48
#define ROWB      144u
#define ATILE_B   (128u*ROWB)
#define STAGE_B   (2u*ATILE_B)          // 36864
#define GEMM_SMEM (3*STAGE_B)           // 110592

__device__ __forceinline__ void gemm_load_tile(
    uint32_t sbase, int stage, int c, int m0, int n0, int tid,
    const __nv_bfloat16* Ah, const __nv_bfloat16* Al,
    const __nv_bfloat16* Bh, const __nv_bfloat16* Bl)
{
    const __nv_bfloat16* asrc = (c < 32) ? Ah : Al;
    const __nv_bfloat16* bsrc = (c < 16) ? Bh : ((c < 32) ? Bl : Bh);
    const int k0 = (c & 15) * KC;
    const uint32_t dstA = sbase + (uint32_t)stage * STAGE_B;
    const uint32_t dstB = dstA + ATILE_B;
#pragma unroll
    for (int i = 0; i < 8; i++) {
        int idx = i * 256 + tid;
        int r = (idx >> 3) & 127, c16 = idx & 7;
        if (idx < 1024)
            cp16(dstA + r * ROWB + c16 * 16, asrc + (size_t)(m0 + r) * HID_ + k0 + c16 * 8);
        else
            cp16(dstB + r * ROWB + c16 * 16, bsrc + (size_t)(n0 + r) * HID_ + k0 + c16 * 8);
    }
    asm volatile("cp.async.commit_group;");
}

__device__ __forceinline__ void gemm_core(
    uint32_t sbase, int m0, int n0, int tid, int wm, int wn, int lane,
    const __nv_bfloat16* Ah, const __nv_bfloat16* Al,
    const __nv_bfloat16* Bh, const __nv_bfloat16* Bl,
    float acc[2][8][4])
{
    const int arow = wm * 32 + (lane & 7) + ((lane >> 3) & 1) * 8;
    const uint32_t a_l = (uint32_t)arow * ROWB + ((lane >> 4) * 16);
    const int brow = wn * 64 + (lane & 7) + ((lane >> 4) & 1) * 8;
    const uint32_t b_l = (uint32_t)brow * ROWB + (((lane >> 3) & 1) * 16);

    gemm_load_tile(sbase, 0, 0, m0, n0, tid, Ah, Al, Bh, Bl);
    gemm_load_tile(sbase, 1, 1, m0, n0, tid, Ah, Al, Bh, Bl);

    for (int c = 0; c < NCHUNK; c++) {
        if (c < NCHUNK - 1) asm volatile("cp.async.wait_group 1;" ::: "memory");
        else                asm volatile("cp.async.wait_group 0;" ::: "memory");
        __syncthreads();
        if (c + 2 < NCHUNK)
            gemm_load_tile(sbase, (c + 2) % 3, c + 2, m0, n0, tid, Ah, Al, Bh, Bl);

        const uint32_t sb = sbase + (uint32_t)(c % 3) * STAGE_B;
        const uint32_t aBase = sb + a_l;
        const uint32_t bBase = sb + ATILE_B + b_l;
#pragma unroll
        for (int kk = 0; kk < KC / 16; kk++) {
            const uint32_t koff = kk * 32;
            uint32_t bq[16];
#pragma unroll
            for (int np = 0; np < 4; np++)
                ldm_x4(&bq[np * 4], bBase + np * 16 * ROWB + koff);
            uint32_t aq[2][4];
#pragma unroll
            for (int mf = 0; mf < 2; mf++)
                ldm_x4(aq[mf], aBase + mf * 16 * ROWB + koff);
#pragma unroll
            for (int mf = 0; mf < 2; mf++)
#pragma unroll
                for (int nf = 0; nf < 8; nf++)
                    mma16816(acc[mf][nf], aq[mf], &bq[(nf >> 1) * 4 + (nf & 1) * 2]);
        }
    }
}

// ---------------- batched projection GEMMs ----------------
struct GemmB {
    const __nv_bfloat16 *Ah[7], *Al[7], *Bh[7], *Bl[7];
    const float* bias[7];
    __nv_bfloat16 *Oh[7], *Ol[7];
    int mode[7];
    int part[7];
};

__global__ __launch_bounds__(256, 2)
void gemm_batch(GemmB args)
{
    extern __shared__ char smem[];
    const uint32_t sbase = smem_u32(smem);
    const int z = blockIdx.z;
    const int tid = threadIdx.x;
    const int wid = tid >> 5, lane = tid & 31;
    const int m0 = blockIdx.y * 128, n0 = blockIdx.x * 128;
    const int wm = wid & 3, wn = wid >> 2;

    float acc[2][8][4];
#pragma unroll
    for (int mf = 0; mf < 2; mf++)
#pragma unroll
        for (int nf = 0; nf < 8; nf++)
#pragma unroll
            for (int q = 0; q < 4; q++) acc[mf][nf][q] = 0.f;

    gemm_core(sbase, m0, n0, tid, wm, wn, lane,
              args.Ah[z], args.Al[z], args.Bh[z], args.Bl[z], acc);

    const float* bias = args.bias[z];
    __nv_bfloat16* Oh = args.Oh[z];
    __nv_bfloat16* Ol = args.Ol[z];
    const int mode = args.mode[z], part = args.part[z];

    const int g = lane >> 2, tq = lane & 3;
    float2 bv[8];
#pragma unroll
    for (int nf = 0; nf < 8; nf++)
        bv[nf] = *(const float2*)(bias + n0 + wn * 64 + nf * 8 + 2 * tq);

#pragma unroll
    for (int mf = 0; mf < 2; mf++) {
#pragma unroll
        for (int half = 0; half < 2; half++) {
            const int m = m0 + wm * 32 + mf * 16 + g + half * 8;
            const int bb = m >> 9, ll = m & 511;
#pragma unroll
            for (int nf = 0; nf < 8; nf++) {
                const int n = n0 + wn * 64 + nf * 8 + 2 * tq;
                const int h = n >> 6, dd = n & 63;
                float vx = acc[mf][nf][half * 2 + 0] + bv[nf].x;
                float vy = acc[mf][nf][half * 2 + 1] + bv[nf].y;
                __nv_bfloat16 hx = __float2bfloat16(vx), hy = __float2bfloat16(vy);
                __nv_bfloat16 lx = __float2bfloat16(vx - __bfloat162float(hx));
                __nv_bfloat16 ly = __float2bfloat16(vy - __bfloat162float(hy));
                if (mode == 0) {
                    size_t dst = ((((size_t)bb * NH_ + h) * L_ + ll) * DCAT)
                               + (size_t)part * 64 + dd;
                    __nv_bfloat162 hi2{hx, hy}, lo2{lx, ly};
                    *(__nv_bfloat162*)(Oh + dst) = hi2;
                    *(__nv_bfloat162*)(Ol + dst) = lo2;
                } else {
                    size_t dst = (((size_t)bb * NH_ + h) * HD_ + dd) * L_ + ll;
                    Oh[dst] = hx;  Ol[dst] = lx;
                    Oh[dst + L_] = hy;  Ol[dst + L_] = ly;
                }
            }
        }
    }
}

// ---------------- output projection GEMM (fp32 out) ----------------
__global__ __launch_bounds__(256, 2)
void gemm_out(const __nv_bfloat16* __restrict__ Ah, const __nv_bfloat16* __restrict__ Al,
              const __nv_bfloat16* __restrict__ Bh, const __nv_bfloat16* __restrict__ Bl,
              const float* __restrict__ bias, float* __restrict__ out)
{
    extern __shared__ char smem[];
    const uint32_t sbase = smem_u32(smem);
    const int tid = threadIdx.x;
    const int wid = tid >> 5, lane = tid & 31;
    const int m0 = blockIdx.y * 128, n0 = blockIdx.x * 128;
    const int wm = wid & 3, wn = wid >> 2;

    float acc[2][8][4];
#pragma unroll
    for (int mf = 0; mf < 2; mf++)
#pragma unroll
        for (int nf = 0; nf < 8; nf++)
#pragma unroll
            for (int q = 0; q < 4; q++) acc[mf][nf][q] = 0.f;

    gemm_core(sbase, m0, n0, tid, wm, wn, lane, Ah, Al, Bh, Bl, acc);

    const int g = lane >> 2, tq = lane & 3;
    float2 bv[8];
#pragma unroll
    for (int nf = 0; nf < 8; nf++)
        bv[nf] = *(const float2*)(bias + n0 + wn * 64 + nf * 8 + 2 * tq);
#pragma unroll
    for (int mf = 0; mf < 2; mf++)
#pragma unroll
        for (int half = 0; half < 2; half++) {
            const int m = m0 + wm * 32 + mf * 16 + g + half * 8;
#pragma unroll
            for (int nf = 0; nf < 8; nf++) {
                const int n = n0 + wn * 64 + nf * 8 + 2 * tq;
                float2 v;
                v.x = acc[mf][nf][half * 2 + 0] + bv[nf].x;
                v.y = acc[mf][nf][half * 2 + 1] + bv[nf].y;
                *(float2*)(out + (size_t)m * HID_ + n) = v;
            }
        }
}

// ---------------- flash attention via mma.sync (R4 structure + rel prefetch) ----------------
#define AQ_STRIDE 400u
#define AV_STRIDE 144u
#define SM_QH 0u
#define SM_QL 51200u
#define SM_KH 102400u
#define SM_KL 128000u
#define SM_VH 153600u
#define SM_VL 162816u
#define ATT_SMEM 172032

__global__ __launch_bounds__(256, 1)
void attn_mma(const float* __restrict__ rel,
              const __nv_bfloat16* __restrict__ Qh, const __nv_bfloat16* __restrict__ Ql,
              const __nv_bfloat16* __restrict__ Kh, const __nv_bfloat16* __restrict__ Kl,
              const __nv_bfloat16* __restrict__ Vth, const __nv_bfloat16* __restrict__ Vtl,
              __nv_bfloat16* __restrict__ Oh, __nv_bfloat16* __restrict__ Ol)
{
    extern __shared__ char smc[];
    const uint32_t sb = smem_u32(smc);
    const int qt = blockIdx.x, bh = blockIdx.y;
    const int q0 = qt * 128;
    const int tid = threadIdx.x, wid = tid >> 5, lane = tid & 31;
    const int g = lane >> 2, tq = lane & 3;
    const int wrow = wid * 16;

    const __nv_bfloat16* qh_g = Qh  + (size_t)bh * L_ * DCAT;
    const __nv_bfloat16* ql_g = Ql  + (size_t)bh * L_ * DCAT;
    const __nv_bfloat16* kh_g = Kh  + (size_t)bh * L_ * DCAT;
    const __nv_bfloat16* kl_g = Kl  + (size_t)bh * L_ * DCAT;
    const __nv_bfloat16* vh_g = Vth + (size_t)bh * HD_ * L_;
    const __nv_bfloat16* vl_g = Vtl + (size_t)bh * HD_ * L_;
    const float* relg = rel + (size_t)bh * L_ * L_;

#pragma unroll
    for (int i = 0; i < 24; i++) {
        int idx = i * 256 + tid;
        int mat = idx >= 3072;
        int j = idx - mat * 3072;
        int r = j / 24, s2 = j % 24;
        cp16(sb + (mat ? SM_QL : SM_QH) + r * AQ_STRIDE + s2 * 16,
             (mat ? ql_g : qh_g) + (size_t)(q0 + r) * DCAT + s2 * 8);
    }
    asm volatile("cp.async.commit_group;");

    float m_i[2] = {-3.0e38f, -3.0e38f};
    float l_i[2] = {0.f, 0.f};
    float oacc[8][4];
#pragma unroll
    for (int nf = 0; nf < 8; nf++)
#pragma unroll
        for (int q = 0; q < 4; q++) oacc[nf][q] = 0.f;

    const uint32_t aoffQ = (uint32_t)(wrow + (lane & 7) + ((lane >> 3) & 1) * 8) * AQ_STRIDE
                         + (lane >> 4) * 16;
    const uint32_t boffK = (uint32_t)((lane & 7) + ((lane >> 4) & 1) * 8) * AQ_STRIDE
                         + ((lane >> 3) & 1) * 16;
    const uint32_t boffV = (uint32_t)((lane & 7) + ((lane >> 4) & 1) * 8) * AV_STRIDE
                         + ((lane >> 3) & 1) * 16;

    const int row0c = q0 + wrow + g;
    const int row1c = row0c + 8;

    const int ntiles = qt * 2 + 2;
    for (int kt = 0; kt < ntiles; kt++) {
        const int k0 = kt * 64;
        __syncthreads();
#pragma unroll
        for (int i = 0; i < 16; i++) {
            int idx = i * 256 + tid;
            if (idx < 3072) {
                int mat = idx >= 1536;
                int j = idx - mat * 1536;
                int r = j / 24, s2 = j % 24;
                cp16(sb + (mat ? SM_KL : SM_KH) + r * AQ_STRIDE + s2 * 16,
                     (mat ? kl_g : kh_g) + (size_t)(k0 + r) * DCAT + s2 * 8);
            } else {
                int j = idx - 3072;
                int mat = j >= 512;
                j -= mat * 512;
                int d = j / 8, s2 = j % 8;
                cp16(sb + (mat ? SM_VL : SM_VH) + d * AV_STRIDE + s2 * 16,
                     (mat ? vl_g : vh_g) + (size_t)d * L_ + k0 + s2 * 8);
            }
        }
        asm volatile("cp.async.commit_group;");
        asm volatile("cp.async.wait_group 0;" ::: "memory");
        __syncthreads();

        if (k0 > q0 + wrow + 15) continue;

        // ---- prefetch relative_time bias for this tile (hidden under QK mma) ----
        float2 rr0[8], rr1[8];
#pragma unroll
        for (int nf = 0; nf < 8; nf++) {
            const int col = k0 + nf * 8 + 2 * tq;
            rr0[nf] = *(const float2*)(relg + (size_t)row0c * L_ + col);
            rr1[nf] = *(const float2*)(relg + (size_t)row1c * L_ + col);
        }

        // ---- S = Qh*Kh + Qh*Kl + Ql*Kh over k=192 ----
        float sacc[8][4];
#pragma unroll
        for (int nf = 0; nf < 8; nf++)
#pragma unroll
            for (int q = 0; q < 4; q++) sacc[nf][q] = 0.f;

#pragma unroll
        for (int ks = 0; ks < 12; ks++) {
            const uint32_t koff = ks * 32;
            uint32_t aqh[4], aql[4], bqh[16], bql[16];
            ldm_x4(aqh, sb + SM_QH + aoffQ + koff);
            ldm_x4(aql, sb + SM_QL + aoffQ + koff);
#pragma unroll
            for (int np = 0; np < 4; np++) {
                ldm_x4(&bqh[np * 4], sb + SM_KH + boffK + np * 16 * AQ_STRIDE + koff);
                ldm_x4(&bql[np * 4], sb + SM_KL + boffK + np * 16 * AQ_STRIDE + koff);
            }
#pragma unroll
            for (int nf = 0; nf < 8; nf++) {
                const uint32_t* bh_ = &bqh[(nf >> 1) * 4 + (nf & 1) * 2];
                const uint32_t* bl_ = &bql[(nf >> 1) * 4 + (nf & 1) * 2];
                mma16816(sacc[nf], aqh, bh_);
                mma16816(sacc[nf], aqh, bl_);
                mma16816(sacc[nf], aql, bh_);
            }
        }

        // ---- bias + mask + online softmax ----
        const int row0 = row0c;
        const int row1 = row1c;
        const bool diag = (k0 + 63 > q0 + wrow);
        float pmax0 = -3.0e38f, pmax1 = -3.0e38f;
#pragma unroll
        for (int nf = 0; nf < 8; nf++) {
            const int col = k0 + nf * 8 + 2 * tq;
            float s0 = fmaf(sacc[nf][0], 0.125f, rr0[nf].x);
            float s1 = fmaf(sacc[nf][1], 0.125f, rr0[nf].y);
            float s2 = fmaf(sacc[nf][2], 0.125f, rr1[nf].x);
            float s3 = fmaf(sacc[nf][3], 0.125f, rr1[nf].y);
            if (diag) {
                if (col     > row0) s0 = -3.0e38f;
                if (col + 1 > row0) s1 = -3.0e38f;
                if (col     > row1) s2 = -3.0e38f;
                if (col + 1 > row1) s3 = -3.0e38f;
            }
            sacc[nf][0] = s0; sacc[nf][1] = s1; sacc[nf][2] = s2; sacc[nf][3] = s3;
            pmax0 = fmaxf(pmax0, fmaxf(s0, s1));
            pmax1 = fmaxf(pmax1, fmaxf(s2, s3));
        }
        // packed half2 max reduction across the 4-lane row group
        {
            __half2 hm = __floats2half2_rn(pmax0, pmax1);
#pragma unroll
            for (int d = 1; d < 4; d <<= 1) {
                uint32_t u = *(uint32_t*)&hm;
                uint32_t v = __shfl_xor_sync(0xffffffffu, u, d);
                hm = __hmax2(hm, *(__half2*)&v);
            }
            float2 fm = __half22float2(hm);
            pmax0 = fm.x;  pmax1 = fm.y;
        }
        const float nm0 = fmaxf(m_i[0], pmax0);
        const float nm1 = fmaxf(m_i[1], pmax1);
        const float al0 = __expf(m_i[0] - nm0);
        const float al1 = __expf(m_i[1] - nm1);
        float rs0 = 0.f, rs1 = 0.f;
#pragma unroll
        for (int nf = 0; nf < 8; nf++) {
            sacc[nf][0] = __expf(sacc[nf][0] - nm0);
            sacc[nf][1] = __expf(sacc[nf][1] - nm0);
            sacc[nf][2] = __expf(sacc[nf][2] - nm1);
            sacc[nf][3] = __expf(sacc[nf][3] - nm1);
            rs0 += sacc[nf][0] + sacc[nf][1];
            rs1 += sacc[nf][2] + sacc[nf][3];
        }
#pragma unroll
        for (int d = 1; d < 4; d <<= 1) {
            rs0 += __shfl_xor_sync(0xffffffffu, rs0, d);
            rs1 += __shfl_xor_sync(0xffffffffu, rs1, d);
        }
        l_i[0] = l_i[0] * al0 + rs0;  m_i[0] = nm0;
        l_i[1] = l_i[1] * al1 + rs1;  m_i[1] = nm1;
#pragma unroll
        for (int nf = 0; nf < 8; nf++) {
            oacc[nf][0] *= al0; oacc[nf][1] *= al0;
            oacc[nf][2] *= al1; oacc[nf][3] *= al1;
        }

        // ---- O += (Ph+Pl) @ (Vh+Vl) over k=64 ----
#pragma unroll
        for (int ks = 0; ks < 4; ks++) {
            uint32_t afh[4], afl[4];
            {
                float p00 = sacc[2*ks][0],   p01 = sacc[2*ks][1];
                float p02 = sacc[2*ks][2],   p03 = sacc[2*ks][3];
                float p10 = sacc[2*ks+1][0], p11 = sacc[2*ks+1][1];
                float p12 = sacc[2*ks+1][2], p13 = sacc[2*ks+1][3];
                afh[0] = pack_bf2(p00, p01);
                afh[1] = pack_bf2(p02, p03);
                afh[2] = pack_bf2(p10, p11);
                afh[3] = pack_bf2(p12, p13);
                __nv_bfloat162 h0 = *(__nv_bfloat162*)&afh[0];
                __nv_bfloat162 h1 = *(__nv_bfloat162*)&afh[1];
                __nv_bfloat162 h2 = *(__nv_bfloat162*)&afh[2];
                __nv_bfloat162 h3 = *(__nv_bfloat162*)&afh[3];
                afl[0] = pack_bf2(p00 - __bfloat162float(h0.x), p01 - __bfloat162float(h0.y));
                afl[1] = pack_bf2(p02 - __bfloat162float(h1.x), p03 - __bfloat162float(h1.y));
                afl[2] = pack_bf2(p10 - __bfloat162float(h2.x), p11 - __bfloat162float(h2.y));
                afl[3] = pack_bf2(p12 - __bfloat162float(h3.x), p13 - __bfloat162float(h3.y));
            }
            uint32_t bvh[16], bvl[16];
            const uint32_t koff = ks * 32;
#pragma unroll
            for (int np = 0; np < 4; np++) {
                ldm_x4(&bvh[np * 4], sb + SM_VH + boffV + np * 16 * AV_STRIDE + koff);
                ldm_x4(&bvl[np * 4], sb + SM_VL + boffV + np * 16 * AV_STRIDE + koff);
            }
#pragma unroll
            for (int nf = 0; nf < 8; nf++) {
                const uint32_t* bh_ = &bvh[(nf >> 1) * 4 + (nf & 1) * 2];
                const uint32_t* bl_ = &bvl[(nf >> 1) * 4 + (nf & 1) * 2];
                mma16816(oacc[nf], afh, bh_);
                mma16816(oacc[nf], afh, bl_);
                mma16816(oacc[nf], afl, bh_);
            }
        }
    }

    const int b = bh >> 4, h = bh & 15;
    const float inv0 = 1.0f / l_i[0];
    const float inv1 = 1.0f / l_i[1];
    const size_t m0g = (size_t)(b * L_ + q0 + wrow + g) * HID_;
    const size_t m1g = m0g + 8 * HID_;
#pragma unroll
    for (int nf = 0; nf < 8; nf++) {
        const int col = h * 64 + nf * 8 + 2 * tq;
        float v0 = oacc[nf][0] * inv0, v1 = oacc[nf][1] * inv0;
        float v2 = oacc[nf][2] * inv1, v3 = oacc[nf][3] * inv1;
        __nv_bfloat162 hi0, lo0, hi1, lo1;
        hi0.x = __float2bfloat16(v0); hi0.y = __float2bfloat16(v1);
        lo0.x = __float2bfloat16(v0 - __bfloat162float(hi0.x));
        lo0.y = __float2bfloat16(v1 - __bfloat162float(hi0.y));
        hi1.x = __float2bfloat16(v2); hi1.y = __float2bfloat16(v3);
        lo1.x = __float2bfloat16(v2 - __bfloat162float(hi1.x));
        lo1.y = __float2bfloat16(v3 - __bfloat162float(hi1.y));
        *(__nv_bfloat162*)(Oh + m0g + col) = hi0;
        *(__nv_bfloat162*)(Ol + m0g + col) = lo0;
        *(__nv_bfloat162*)(Oh + m1g + col) = hi1;
        *(__nv_bfloat162*)(Ol + m1g + col) = lo1;
    }
}

// ---------------- launcher ----------------
extern "C" void kernel_launch(void* const* d_in, const int* in_sizes, int n_in,
                              void* d_out, int out_size)
{
    const float* rel = (const float*)d_in[5];
    float* out = (float*)d_out;

    __nv_bfloat16 *xh, *xl, *wh, *wl, *qh, *ql, *kh, *kl, *vth, *vtl;
    cudaGetSymbolAddress((void**)&xh, g_xh);
    cudaGetSymbolAddress((void**)&xl, g_xl);
    cudaGetSymbolAddress((void**)&wh, g_wh);
    cudaGetSymbolAddress((void**)&wl, g_wl);
    cudaGetSymbolAddress((void**)&qh, g_qh);
    cudaGetSymbolAddress((void**)&ql, g_ql);
    cudaGetSymbolAddress((void**)&kh, g_kh);
    cudaGetSymbolAddress((void**)&kl, g_kl);
    cudaGetSymbolAddress((void**)&vth, g_vth);
    cudaGetSymbolAddress((void**)&vtl, g_vtl);

    cudaFuncSetAttribute(gemm_batch, cudaFuncAttributeMaxDynamicSharedMemorySize, GEMM_SMEM);
    cudaFuncSetAttribute(gemm_out, cudaFuncAttributeMaxDynamicSharedMemorySize, GEMM_SMEM);
    cudaFuncSetAttribute(attn_mma, cudaFuncAttributeMaxDynamicSharedMemorySize, ATT_SMEM);

    const int n4 = (int)(XN / 4);

    SplitSrc ss;
    ss.p[0] = (const float*)d_in[0];
    ss.p[1] = (const float*)d_in[1];
    ss.p[2] = (const float*)d_in[2];
    ss.p[3] = (const float*)d_in[3];
    split_b<<<dim3((n4 + 255) / 256, 4), 256>>>(ss, xh, xl, n4);

    WSrc ws;
    ws.p[0] = (const float*)d_in[6];   ws.p[1] = (const float*)d_in[8];
    ws.p[2] = (const float*)d_in[10];  ws.p[3] = (const float*)d_in[12];
    ws.p[4] = (const float*)d_in[14];  ws.p[5] = (const float*)d_in[16];
    ws.p[6] = (const float*)d_in[18];  ws.p[7] = (const float*)d_in[20];
    splitT_b<<<dim3(32, 32, 8), dim3(32, 8)>>>(ws, wh, wl);

    GemmB gb;
    const int ain[7]  = {0, 1, 2, 0, 1, 2, 3};
    const int wsl[7]  = {0, 3, 5, 1, 4, 6, 2};
    const int bidx[7] = {7, 13, 17, 9, 15, 19, 11};
    for (int z = 0; z < 7; z++) {
        gb.Ah[z] = xh + (size_t)ain[z] * XN;
        gb.Al[z] = xl + (size_t)ain[z] * XN;
        gb.Bh[z] = wh + (size_t)wsl[z] * WN;
        gb.Bl[z] = wl + (size_t)wsl[z] * WN;
        gb.bias[z] = (const float*)d_in[bidx[z]];
    }
    gb.Oh[0] = qh;  gb.Ol[0] = ql;  gb.mode[0] = 0; gb.part[0] = 0;
    gb.Oh[1] = qh;  gb.Ol[1] = ql;  gb.mode[1] = 0; gb.part[1] = 1;
    gb.Oh[2] = qh;  gb.Ol[2] = ql;  gb.mode[2] = 0; gb.part[2] = 2;
    gb.Oh[3] = kh;  gb.Ol[3] = kl;  gb.mode[3] = 0; gb.part[3] = 0;
    gb.Oh[4] = kh;  gb.Ol[4] = kl;  gb.mode[4] = 0; gb.part[4] = 1;
    gb.Oh[5] = kh;  gb.Ol[5] = kl;  gb.mode[5] = 0; gb.part[5] = 2;
    gb.Oh[6] = vth; gb.Ol[6] = vtl; gb.mode[6] = 1; gb.part[6] = 0;
    gemm_batch<<<dim3(8, 64, 7), 256, GEMM_SMEM>>>(gb);

    attn_mma<<<dim3(4, 256), 256, ATT_SMEM>>>(rel, qh, ql, kh, kl, vth, vtl,
                                              xh + 4 * XN, xl + 4 * XN);

    gemm_out<<<dim3(8, 64), 256, GEMM_SMEM>>>(xh + 4 * XN, xl + 4 * XN,
                                              wh + 7 * WN, wl + 7 * WN,
                                              (const float*)d_in[21], out);
}

// round 8
// speedup vs baseline: 1.4352x; 1.3497x over previous
#include <cuda_runtime.h>
#include <cuda_bf16.h>
#include <cuda_fp16.h>
#include <cstdint>

#define B_    16
#define L_    512
#define HID_  1024
#define NH_   16
#define HD_   64
#define M_TOT (B_*L_)      // 8192
#define DCAT  192
#define XN    ((size_t)M_TOT*HID_)
#define WN    ((size_t)HID_*HID_)

// ---------------- scratch (static device arrays) ----------------
__device__ __half g_xf[5ULL*XN];            // fp16 activations: 4 inputs + attn-out
__device__ __half g_wfh[8ULL*WN];           // W^T fp16 hi
__device__ __half g_wfl[8ULL*WN];           // W^T fp16 lo (residual, subnormal range ok)
__device__ __nv_bfloat16 g_qh[(size_t)B_*NH_*L_*DCAT];
__device__ __nv_bfloat16 g_ql[(size_t)B_*NH_*L_*DCAT];
__device__ __nv_bfloat16 g_kh[(size_t)B_*NH_*L_*DCAT];
__device__ __nv_bfloat16 g_kl[(size_t)B_*NH_*L_*DCAT];
__device__ __nv_bfloat16 g_vth[(size_t)B_*NH_*HD_*L_];
__device__ __nv_bfloat16 g_vtl[(size_t)B_*NH_*HD_*L_];

// ---------------- PTX helpers (baseline ISA only) ----------------
__device__ __forceinline__ uint32_t smem_u32(const void* p) {
    uint32_t a;
    asm("{ .reg .u64 t; cvta.to.shared.u64 t, %1; cvt.u32.u64 %0, t; }" : "=r"(a) : "l"(p));
    return a;
}
__device__ __forceinline__ void cp16(uint32_t dst, const void* src) {
    asm volatile("cp.async.cg.shared.global [%0], [%1], 16;" :: "r"(dst), "l"(src));
}
__device__ __forceinline__ void ldm_x4(uint32_t* r, uint32_t addr) {
    asm volatile("ldmatrix.sync.aligned.m8n8.x4.shared.b16 {%0,%1,%2,%3}, [%4];"
                 : "=r"(r[0]), "=r"(r[1]), "=r"(r[2]), "=r"(r[3]) : "r"(addr));
}
// bf16 mma (attention)
__device__ __forceinline__ void mma16816(float* d, const uint32_t* a, const uint32_t* b) {
    asm volatile(
        "mma.sync.aligned.m16n8k16.row.col.f32.bf16.bf16.f32 "
        "{%0,%1,%2,%3}, {%4,%5,%6,%7}, {%8,%9}, {%0,%1,%2,%3};"
        : "+f"(d[0]), "+f"(d[1]), "+f"(d[2]), "+f"(d[3])
        : "r"(a[0]), "r"(a[1]), "r"(a[2]), "r"(a[3]), "r"(b[0]), "r"(b[1]));
}
// fp16 mma (projection / output GEMMs)
__device__ __forceinline__ void mma16816h(float* d, const uint32_t* a, const uint32_t* b) {
    asm volatile(
        "mma.sync.aligned.m16n8k16.row.col.f32.f16.f16.f32 "
        "{%0,%1,%2,%3}, {%4,%5,%6,%7}, {%8,%9}, {%0,%1,%2,%3};"
        : "+f"(d[0]), "+f"(d[1]), "+f"(d[2]), "+f"(d[3])
        : "r"(a[0]), "r"(a[1]), "r"(a[2]), "r"(a[3]), "r"(b[0]), "r"(b[1]));
}
__device__ __forceinline__ uint32_t pack_bf2(float a, float b) {
    __nv_bfloat162 t;
    t.x = __float2bfloat16(a); t.y = __float2bfloat16(b);
    return *(uint32_t*)&t;
}

// ---------------- batched fp32 -> fp16 (single) ----------------
struct SplitSrc { const float* p[4]; };
__global__ __launch_bounds__(256)
void split_f16(SplitSrc s, __half* __restrict__ dst, int n4)
{
    int i = blockIdx.x * 256 + threadIdx.x;
    if (i >= n4) return;
    int z = blockIdx.y;
    const float* src = s.p[z];
    __half* dz = dst + (size_t)z * XN;
    float4 v = ((const float4*)src)[i];
    __half2 a = __floats2half2_rn(v.x, v.y);
    __half2 b = __floats2half2_rn(v.z, v.w);
    ((__half2*)dz)[i*2]   = a;
    ((__half2*)dz)[i*2+1] = b;
}

// ---------------- batched W[k][n] -> W^T[n][k] fp16 split ----------------
struct WSrc { const float* p[8]; };
__global__ __launch_bounds__(256)
void splitT_h(WSrc s, __half* __restrict__ hiT, __half* __restrict__ loT)
{
    __shared__ float t[32][33];
    int z = blockIdx.z;
    const float* W = s.p[z];
    __half* hz = hiT + (size_t)z * WN;
    __half* lz = loT + (size_t)z * WN;
    int bx = blockIdx.x * 32, by = blockIdx.y * 32;
    int tx = threadIdx.x, ty = threadIdx.y;
#pragma unroll
    for (int j = 0; j < 4; j++)
        t[ty + 8*j][tx] = W[(size_t)(by + ty + 8*j) * HID_ + bx + tx];
    __syncthreads();
#pragma unroll
    for (int j = 0; j < 4; j++) {
        float v = t[tx][ty + 8*j];
        int n = bx + ty + 8*j, k = by + tx;
        __half h = __float2half(v);
        hz[(size_t)n * HID_ + k] = h;
        lz[(size_t)n * HID_ + k] = __float2half(v - __half2float(h));
    }
}

// ---------------- GEMM core: fp16 2-product, CTA 128x128, warp 32x64, 3-stage ----------------
#define KC        64
#define NCHUNK2   32
#define ROWB      144u
#define ATILE_B   (128u*ROWB)
#define STAGE_B   (2u*ATILE_B)          // 36864
#define GEMM_SMEM (3*STAGE_B)           // 110592

__device__ __forceinline__ void gemm_load_tile(
    uint32_t sbase, int stage, int c, int m0, int n0, int tid,
    const __half* A, const __half* Bh, const __half* Bl)
{
    const __half* bsrc = (c < 16) ? Bh : Bl;
    const int k0 = (c & 15) * KC;
    const uint32_t dstA = sbase + (uint32_t)stage * STAGE_B;
    const uint32_t dstB = dstA + ATILE_B;
#pragma unroll
    for (int i = 0; i < 8; i++) {
        int idx = i * 256 + tid;
        int r = (idx >> 3) & 127, c16 = idx & 7;
        if (idx < 1024)
            cp16(dstA + r * ROWB + c16 * 16, A + (size_t)(m0 + r) * HID_ + k0 + c16 * 8);
        else
            cp16(dstB + r * ROWB + c16 * 16, bsrc + (size_t)(n0 + r) * HID_ + k0 + c16 * 8);
    }
    asm volatile("cp.async.commit_group;");
}

__device__ __forceinline__ void gemm_core(
    uint32_t sbase, int m0, int n0, int tid, int wm, int wn, int lane,
    const __half* A, const __half* Bh, const __half* Bl,
    float acc[2][8][4])
{
    const int arow = wm * 32 + (lane & 7) + ((lane >> 3) & 1) * 8;
    const uint32_t a_l = (uint32_t)arow * ROWB + ((lane >> 4) * 16);
    const int brow = wn * 64 + (lane & 7) + ((lane >> 4) & 1) * 8;
    const uint32_t b_l = (uint32_t)brow * ROWB + (((lane >> 3) & 1) * 16);

    gemm_load_tile(sbase, 0, 0, m0, n0, tid, A, Bh, Bl);
    gemm_load_tile(sbase, 1, 1, m0, n0, tid, A, Bh, Bl);

    for (int c = 0; c < NCHUNK2; c++) {
        if (c < NCHUNK2 - 1) asm volatile("cp.async.wait_group 1;" ::: "memory");
        else                 asm volatile("cp.async.wait_group 0;" ::: "memory");
        __syncthreads();
        if (c + 2 < NCHUNK2)
            gemm_load_tile(sbase, (c + 2) % 3, c + 2, m0, n0, tid, A, Bh, Bl);

        const uint32_t sb = sbase + (uint32_t)(c % 3) * STAGE_B;
        const uint32_t aBase = sb + a_l;
        const uint32_t bBase = sb + ATILE_B + b_l;
#pragma unroll
        for (int kk = 0; kk < KC / 16; kk++) {
            const uint32_t koff = kk * 32;
            uint32_t bq[16];
#pragma unroll
            for (int np = 0; np < 4; np++)
                ldm_x4(&bq[np * 4], bBase + np * 16 * ROWB + koff);
            uint32_t aq[2][4];
#pragma unroll
            for (int mf = 0; mf < 2; mf++)
                ldm_x4(aq[mf], aBase + mf * 16 * ROWB + koff);
#pragma unroll
            for (int mf = 0; mf < 2; mf++)
#pragma unroll
                for (int nf = 0; nf < 8; nf++)
                    mma16816h(acc[mf][nf], aq[mf], &bq[(nf >> 1) * 4 + (nf & 1) * 2]);
        }
    }
}

// ---------------- batched projection GEMMs (split-bf16 out for attention) ----------------
struct GemmB {
    const __half *A[7], *Bh[7], *Bl[7];
    const float* bias[7];
    __nv_bfloat16 *Oh[7], *Ol[7];
    int mode[7];
    int part[7];
};

__global__ __launch_bounds__(256, 2)
void gemm_batch(GemmB args)
{
    extern __shared__ char smem[];
    const uint32_t sbase = smem_u32(smem);
    const int z = blockIdx.z;
    const int tid = threadIdx.x;
    const int wid = tid >> 5, lane = tid & 31;
    const int m0 = blockIdx.y * 128, n0 = blockIdx.x * 128;
    const int wm = wid & 3, wn = wid >> 2;

    float acc[2][8][4];
#pragma unroll
    for (int mf = 0; mf < 2; mf++)
#pragma unroll
        for (int nf = 0; nf < 8; nf++)
#pragma unroll
            for (int q = 0; q < 4; q++) acc[mf][nf][q] = 0.f;

    gemm_core(sbase, m0, n0, tid, wm, wn, lane,
              args.A[z], args.Bh[z], args.Bl[z], acc);

    const float* bias = args.bias[z];
    __nv_bfloat16* Oh = args.Oh[z];
    __nv_bfloat16* Ol = args.Ol[z];
    const int mode = args.mode[z], part = args.part[z];

    const int g = lane >> 2, tq = lane & 3;
    float2 bv[8];
#pragma unroll
    for (int nf = 0; nf < 8; nf++)
        bv[nf] = *(const float2*)(bias + n0 + wn * 64 + nf * 8 + 2 * tq);

#pragma unroll
    for (int mf = 0; mf < 2; mf++) {
#pragma unroll
        for (int half = 0; half < 2; half++) {
            const int m = m0 + wm * 32 + mf * 16 + g + half * 8;
            const int bb = m >> 9, ll = m & 511;
#pragma unroll
            for (int nf = 0; nf < 8; nf++) {
                const int n = n0 + wn * 64 + nf * 8 + 2 * tq;
                const int h = n >> 6, dd = n & 63;
                float vx = acc[mf][nf][half * 2 + 0] + bv[nf].x;
                float vy = acc[mf][nf][half * 2 + 1] + bv[nf].y;
                __nv_bfloat16 hx = __float2bfloat16(vx), hy = __float2bfloat16(vy);
                __nv_bfloat16 lx = __float2bfloat16(vx - __bfloat162float(hx));
                __nv_bfloat16 ly = __float2bfloat16(vy - __bfloat162float(hy));
                if (mode == 0) {
                    size_t dst = ((((size_t)bb * NH_ + h) * L_ + ll) * DCAT)
                               + (size_t)part * 64 + dd;
                    __nv_bfloat162 hi2{hx, hy}, lo2{lx, ly};
                    *(__nv_bfloat162*)(Oh + dst) = hi2;
                    *(__nv_bfloat162*)(Ol + dst) = lo2;
                } else {
                    size_t dst = (((size_t)bb * NH_ + h) * HD_ + dd) * L_ + ll;
                    Oh[dst] = hx;  Ol[dst] = lx;
                    Oh[dst + L_] = hy;  Ol[dst + L_] = ly;
                }
            }
        }
    }
}

// ---------------- output projection GEMM (fp32 out) ----------------
__global__ __launch_bounds__(256, 2)
void gemm_out(const __half* __restrict__ A,
              const __half* __restrict__ Bh, const __half* __restrict__ Bl,
              const float* __restrict__ bias, float* __restrict__ out)
{
    extern __shared__ char smem[];
    const uint32_t sbase = smem_u32(smem);
    const int tid = threadIdx.x;
    const int wid = tid >> 5, lane = tid & 31;
    const int m0 = blockIdx.y * 128, n0 = blockIdx.x * 128;
    const int wm = wid & 3, wn = wid >> 2;

    float acc[2][8][4];
#pragma unroll
    for (int mf = 0; mf < 2; mf++)
#pragma unroll
        for (int nf = 0; nf < 8; nf++)
#pragma unroll
            for (int q = 0; q < 4; q++) acc[mf][nf][q] = 0.f;

    gemm_core(sbase, m0, n0, tid, wm, wn, lane, A, Bh, Bl, acc);

    const int g = lane >> 2, tq = lane & 3;
    float2 bv[8];
#pragma unroll
    for (int nf = 0; nf < 8; nf++)
        bv[nf] = *(const float2*)(bias + n0 + wn * 64 + nf * 8 + 2 * tq);
#pragma unroll
    for (int mf = 0; mf < 2; mf++)
#pragma unroll
        for (int half = 0; half < 2; half++) {
            const int m = m0 + wm * 32 + mf * 16 + g + half * 8;
#pragma unroll
            for (int nf = 0; nf < 8; nf++) {
                const int n = n0 + wn * 64 + nf * 8 + 2 * tq;
                float2 v;
                v.x = acc[mf][nf][half * 2 + 0] + bv[nf].x;
                v.y = acc[mf][nf][half * 2 + 1] + bv[nf].y;
                *(float2*)(out + (size_t)m * HID_ + n) = v;
            }
        }
}

// ---------------- flash attention via mma.sync (bf16 3-product, unchanged core) ----------------
#define AQ_STRIDE 400u
#define AV_STRIDE 144u
#define SM_QH 0u
#define SM_QL 51200u
#define SM_KH 102400u
#define SM_KL 128000u
#define SM_VH 153600u
#define SM_VL 162816u
#define ATT_SMEM 172032

__global__ __launch_bounds__(256, 1)
void attn_mma(const float* __restrict__ rel,
              const __nv_bfloat16* __restrict__ Qh, const __nv_bfloat16* __restrict__ Ql,
              const __nv_bfloat16* __restrict__ Kh, const __nv_bfloat16* __restrict__ Kl,
              const __nv_bfloat16* __restrict__ Vth, const __nv_bfloat16* __restrict__ Vtl,
              __half* __restrict__ Of)
{
    extern __shared__ char smc[];
    const uint32_t sb = smem_u32(smc);
    const int qt = (int)gridDim.x - 1 - (int)blockIdx.x;   // heavy CTAs first
    const int bh = blockIdx.y;
    const int q0 = qt * 128;
    const int tid = threadIdx.x, wid = tid >> 5, lane = tid & 31;
    const int g = lane >> 2, tq = lane & 3;
    const int wrow = wid * 16;

    const __nv_bfloat16* qh_g = Qh  + (size_t)bh * L_ * DCAT;
    const __nv_bfloat16* ql_g = Ql  + (size_t)bh * L_ * DCAT;
    const __nv_bfloat16* kh_g = Kh  + (size_t)bh * L_ * DCAT;
    const __nv_bfloat16* kl_g = Kl  + (size_t)bh * L_ * DCAT;
    const __nv_bfloat16* vh_g = Vth + (size_t)bh * HD_ * L_;
    const __nv_bfloat16* vl_g = Vtl + (size_t)bh * HD_ * L_;
    const float* relg = rel + (size_t)bh * L_ * L_;

#pragma unroll
    for (int i = 0; i < 24; i++) {
        int idx = i * 256 + tid;
        int mat = idx >= 3072;
        int j = idx - mat * 3072;
        int r = j / 24, s2 = j % 24;
        cp16(sb + (mat ? SM_QL : SM_QH) + r * AQ_STRIDE + s2 * 16,
             (mat ? ql_g : qh_g) + (size_t)(q0 + r) * DCAT + s2 * 8);
    }
    asm volatile("cp.async.commit_group;");

    float m_i[2] = {-3.0e38f, -3.0e38f};
    float l_i[2] = {0.f, 0.f};
    float oacc[8][4];
#pragma unroll
    for (int nf = 0; nf < 8; nf++)
#pragma unroll
        for (int q = 0; q < 4; q++) oacc[nf][q] = 0.f;

    const uint32_t aoffQ = (uint32_t)(wrow + (lane & 7) + ((lane >> 3) & 1) * 8) * AQ_STRIDE
                         + (lane >> 4) * 16;
    const uint32_t boffK = (uint32_t)((lane & 7) + ((lane >> 4) & 1) * 8) * AQ_STRIDE
                         + ((lane >> 3) & 1) * 16;
    const uint32_t boffV = (uint32_t)((lane & 7) + ((lane >> 4) & 1) * 8) * AV_STRIDE
                         + ((lane >> 3) & 1) * 16;

    const int row0c = q0 + wrow + g;
    const int row1c = row0c + 8;

    const int ntiles = qt * 2 + 2;
    for (int kt = 0; kt < ntiles; kt++) {
        const int k0 = kt * 64;
        __syncthreads();
#pragma unroll
        for (int i = 0; i < 16; i++) {
            int idx = i * 256 + tid;
            if (idx < 3072) {
                int mat = idx >= 1536;
                int j = idx - mat * 1536;
                int r = j / 24, s2 = j % 24;
                cp16(sb + (mat ? SM_KL : SM_KH) + r * AQ_STRIDE + s2 * 16,
                     (mat ? kl_g : kh_g) + (size_t)(k0 + r) * DCAT + s2 * 8);
            } else {
                int j = idx - 3072;
                int mat = j >= 512;
                j -= mat * 512;
                int d = j / 8, s2 = j % 8;
                cp16(sb + (mat ? SM_VL : SM_VH) + d * AV_STRIDE + s2 * 16,
                     (mat ? vl_g : vh_g) + (size_t)d * L_ + k0 + s2 * 8);
            }
        }
        asm volatile("cp.async.commit_group;");
        asm volatile("cp.async.wait_group 0;" ::: "memory");
        __syncthreads();

        if (k0 > q0 + wrow + 15) continue;

        float2 rr0[8], rr1[8];
#pragma unroll
        for (int nf = 0; nf < 8; nf++) {
            const int col = k0 + nf * 8 + 2 * tq;
            rr0[nf] = *(const float2*)(relg + (size_t)row0c * L_ + col);
            rr1[nf] = *(const float2*)(relg + (size_t)row1c * L_ + col);
        }

        float sacc[8][4];
#pragma unroll
        for (int nf = 0; nf < 8; nf++)
#pragma unroll
            for (int q = 0; q < 4; q++) sacc[nf][q] = 0.f;

#pragma unroll
        for (int ks = 0; ks < 12; ks++) {
            const uint32_t koff = ks * 32;
            uint32_t aqh[4], aql[4], bqh[16], bql[16];
            ldm_x4(aqh, sb + SM_QH + aoffQ + koff);
            ldm_x4(aql, sb + SM_QL + aoffQ + koff);
#pragma unroll
            for (int np = 0; np < 4; np++) {
                ldm_x4(&bqh[np * 4], sb + SM_KH + boffK + np * 16 * AQ_STRIDE + koff);
                ldm_x4(&bql[np * 4], sb + SM_KL + boffK + np * 16 * AQ_STRIDE + koff);
            }
#pragma unroll
            for (int nf = 0; nf < 8; nf++) {
                const uint32_t* bh_ = &bqh[(nf >> 1) * 4 + (nf & 1) * 2];
                const uint32_t* bl_ = &bql[(nf >> 1) * 4 + (nf & 1) * 2];
                mma16816(sacc[nf], aqh, bh_);
                mma16816(sacc[nf], aqh, bl_);
                mma16816(sacc[nf], aql, bh_);
            }
        }

        const int row0 = row0c;
        const int row1 = row1c;
        const bool diag = (k0 + 63 > q0 + wrow);
        float pmax0 = -3.0e38f, pmax1 = -3.0e38f;
#pragma unroll
        for (int nf = 0; nf < 8; nf++) {
            const int col = k0 + nf * 8 + 2 * tq;
            float s0 = fmaf(sacc[nf][0], 0.125f, rr0[nf].x);
            float s1 = fmaf(sacc[nf][1], 0.125f, rr0[nf].y);
            float s2 = fmaf(sacc[nf][2], 0.125f, rr1[nf].x);
            float s3 = fmaf(sacc[nf][3], 0.125f, rr1[nf].y);
            if (diag) {
                if (col     > row0) s0 = -3.0e38f;
                if (col + 1 > row0) s1 = -3.0e38f;
                if (col     > row1) s2 = -3.0e38f;
                if (col + 1 > row1) s3 = -3.0e38f;
            }
            sacc[nf][0] = s0; sacc[nf][1] = s1; sacc[nf][2] = s2; sacc[nf][3] = s3;
            pmax0 = fmaxf(pmax0, fmaxf(s0, s1));
            pmax1 = fmaxf(pmax1, fmaxf(s2, s3));
        }
        {
            __half2 hm = __floats2half2_rn(pmax0, pmax1);
#pragma unroll
            for (int d = 1; d < 4; d <<= 1) {
                uint32_t u = *(uint32_t*)&hm;
                uint32_t v = __shfl_xor_sync(0xffffffffu, u, d);
                hm = __hmax2(hm, *(__half2*)&v);
            }
            float2 fm = __half22float2(hm);
            pmax0 = fm.x;  pmax1 = fm.y;
        }
        const float nm0 = fmaxf(m_i[0], pmax0);
        const float nm1 = fmaxf(m_i[1], pmax1);
        const float al0 = __expf(m_i[0] - nm0);
        const float al1 = __expf(m_i[1] - nm1);
        float rs0 = 0.f, rs1 = 0.f;
#pragma unroll
        for (int nf = 0; nf < 8; nf++) {
            sacc[nf][0] = __expf(sacc[nf][0] - nm0);
            sacc[nf][1] = __expf(sacc[nf][1] - nm0);
            sacc[nf][2] = __expf(sacc[nf][2] - nm1);
            sacc[nf][3] = __expf(sacc[nf][3] - nm1);
            rs0 += sacc[nf][0] + sacc[nf][1];
            rs1 += sacc[nf][2] + sacc[nf][3];
        }
#pragma unroll
        for (int d = 1; d < 4; d <<= 1) {
            rs0 += __shfl_xor_sync(0xffffffffu, rs0, d);
            rs1 += __shfl_xor_sync(0xffffffffu, rs1, d);
        }
        l_i[0] = l_i[0] * al0 + rs0;  m_i[0] = nm0;
        l_i[1] = l_i[1] * al1 + rs1;  m_i[1] = nm1;
#pragma unroll
        for (int nf = 0; nf < 8; nf++) {
            oacc[nf][0] *= al0; oacc[nf][1] *= al0;
            oacc[nf][2] *= al1; oacc[nf][3] *= al1;
        }

#pragma unroll
        for (int ks = 0; ks < 4; ks++) {
            uint32_t afh[4], afl[4];
            {
                float p00 = sacc[2*ks][0],   p01 = sacc[2*ks][1];
                float p02 = sacc[2*ks][2],   p03 = sacc[2*ks][3];
                float p10 = sacc[2*ks+1][0], p11 = sacc[2*ks+1][1];
                float p12 = sacc[2*ks+1][2], p13 = sacc[2*ks+1][3];
                afh[0] = pack_bf2(p00, p01);
                afh[1] = pack_bf2(p02, p03);
                afh[2] = pack_bf2(p10, p11);
                afh[3] = pack_bf2(p12, p13);
                __nv_bfloat162 h0 = *(__nv_bfloat162*)&afh[0];
                __nv_bfloat162 h1 = *(__nv_bfloat162*)&afh[1];
                __nv_bfloat162 h2 = *(__nv_bfloat162*)&afh[2];
                __nv_bfloat162 h3 = *(__nv_bfloat162*)&afh[3];
                afl[0] = pack_bf2(p00 - __bfloat162float(h0.x), p01 - __bfloat162float(h0.y));
                afl[1] = pack_bf2(p02 - __bfloat162float(h1.x), p03 - __bfloat162float(h1.y));
                afl[2] = pack_bf2(p10 - __bfloat162float(h2.x), p11 - __bfloat162float(h2.y));
                afl[3] = pack_bf2(p12 - __bfloat162float(h3.x), p13 - __bfloat162float(h3.y));
            }
            uint32_t bvh[16], bvl[16];
            const uint32_t koff = ks * 32;
#pragma unroll
            for (int np = 0; np < 4; np++) {
                ldm_x4(&bvh[np * 4], sb + SM_VH + boffV + np * 16 * AV_STRIDE + koff);
                ldm_x4(&bvl[np * 4], sb + SM_VL + boffV + np * 16 * AV_STRIDE + koff);
            }
#pragma unroll
            for (int nf = 0; nf < 8; nf++) {
                const uint32_t* bh_ = &bvh[(nf >> 1) * 4 + (nf & 1) * 2];
                const uint32_t* bl_ = &bvl[(nf >> 1) * 4 + (nf & 1) * 2];
                mma16816(oacc[nf], afh, bh_);
                mma16816(oacc[nf], afh, bl_);
                mma16816(oacc[nf], afl, bh_);
            }
        }
    }

    // ---- epilogue: normalize, fp16 write to [m][HID] ----
    const int b = bh >> 4, h = bh & 15;
    const float inv0 = 1.0f / l_i[0];
    const float inv1 = 1.0f / l_i[1];
    const size_t m0g = (size_t)(b * L_ + q0 + wrow + g) * HID_;
    const size_t m1g = m0g + 8 * HID_;
#pragma unroll
    for (int nf = 0; nf < 8; nf++) {
        const int col = h * 64 + nf * 8 + 2 * tq;
        __half2 o0 = __floats2half2_rn(oacc[nf][0] * inv0, oacc[nf][1] * inv0);
        __half2 o1 = __floats2half2_rn(oacc[nf][2] * inv1, oacc[nf][3] * inv1);
        *(__half2*)(Of + m0g + col) = o0;
        *(__half2*)(Of + m1g + col) = o1;
    }
}

// ---------------- launcher ----------------
extern "C" void kernel_launch(void* const* d_in, const int* in_sizes, int n_in,
                              void* d_out, int out_size)
{
    const float* rel = (const float*)d_in[5];
    float* out = (float*)d_out;

    __half *xf, *wfh, *wfl;
    __nv_bfloat16 *qh, *ql, *kh, *kl, *vth, *vtl;
    cudaGetSymbolAddress((void**)&xf, g_xf);
    cudaGetSymbolAddress((void**)&wfh, g_wfh);
    cudaGetSymbolAddress((void**)&wfl, g_wfl);
    cudaGetSymbolAddress((void**)&qh, g_qh);
    cudaGetSymbolAddress((void**)&ql, g_ql);
    cudaGetSymbolAddress((void**)&kh, g_kh);
    cudaGetSymbolAddress((void**)&kl, g_kl);
    cudaGetSymbolAddress((void**)&vth, g_vth);
    cudaGetSymbolAddress((void**)&vtl, g_vtl);

    cudaFuncSetAttribute(gemm_batch, cudaFuncAttributeMaxDynamicSharedMemorySize, GEMM_SMEM);
    cudaFuncSetAttribute(gemm_out, cudaFuncAttributeMaxDynamicSharedMemorySize, GEMM_SMEM);
    cudaFuncSetAttribute(attn_mma, cudaFuncAttributeMaxDynamicSharedMemorySize, ATT_SMEM);

    const int n4 = (int)(XN / 4);

    SplitSrc ss;
    ss.p[0] = (const float*)d_in[0];
    ss.p[1] = (const float*)d_in[1];
    ss.p[2] = (const float*)d_in[2];
    ss.p[3] = (const float*)d_in[3];
    split_f16<<<dim3((n4 + 255) / 256, 4), 256>>>(ss, xf, n4);

    WSrc ws;
    ws.p[0] = (const float*)d_in[6];   ws.p[1] = (const float*)d_in[8];
    ws.p[2] = (const float*)d_in[10];  ws.p[3] = (const float*)d_in[12];
    ws.p[4] = (const float*)d_in[14];  ws.p[5] = (const float*)d_in[16];
    ws.p[6] = (const float*)d_in[18];  ws.p[7] = (const float*)d_in[20];
    splitT_h<<<dim3(32, 32, 8), dim3(32, 8)>>>(ws, wfh, wfl);

    GemmB gb;
    const int ain[7]  = {0, 1, 2, 0, 1, 2, 3};
    const int wsl[7]  = {0, 3, 5, 1, 4, 6, 2};
    const int bidx[7] = {7, 13, 17, 9, 15, 19, 11};
    for (int z = 0; z < 7; z++) {
        gb.A[z]  = xf + (size_t)ain[z] * XN;
        gb.Bh[z] = wfh + (size_t)wsl[z] * WN;
        gb.Bl[z] = wfl + (size_t)wsl[z] * WN;
        gb.bias[z] = (const float*)d_in[bidx[z]];
    }
    gb.Oh[0] = qh;  gb.Ol[0] = ql;  gb.mode[0] = 0; gb.part[0] = 0;
    gb.Oh[1] = qh;  gb.Ol[1] = ql;  gb.mode[1] = 0; gb.part[1] = 1;
    gb.Oh[2] = qh;  gb.Ol[2] = ql;  gb.mode[2] = 0; gb.part[2] = 2;
    gb.Oh[3] = kh;  gb.Ol[3] = kl;  gb.mode[3] = 0; gb.part[3] = 0;
    gb.Oh[4] = kh;  gb.Ol[4] = kl;  gb.mode[4] = 0; gb.part[4] = 1;
    gb.Oh[5] = kh;  gb.Ol[5] = kl;  gb.mode[5] = 0; gb.part[5] = 2;
    gb.Oh[6] = vth; gb.Ol[6] = vtl; gb.mode[6] = 1; gb.part[6] = 0;
    gemm_batch<<<dim3(8, 64, 7), 256, GEMM_SMEM>>>(gb);

    attn_mma<<<dim3(4, 256), 256, ATT_SMEM>>>(rel, qh, ql, kh, kl, vth, vtl,
                                              xf + 4 * XN);

    gemm_out<<<dim3(8, 64), 256, GEMM_SMEM>>>(xf + 4 * XN,
                                              wfh + 7 * WN, wfl + 7 * WN,
                                              (const float*)d_in[21], out);
}

// round 9
// speedup vs baseline: 1.5206x; 1.0595x over previous
#include <cuda_runtime.h>
#include <cuda_bf16.h>
#include <cuda_fp16.h>
#include <cstdint>

#define B_    16
#define L_    512
#define HID_  1024
#define NH_   16
#define HD_   64
#define M_TOT (B_*L_)      // 8192
#define DCAT  192
#define XN    ((size_t)M_TOT*HID_)
#define WN    ((size_t)HID_*HID_)

// ---------------- scratch (static device arrays) ----------------
__device__ __half g_xf[5ULL*XN];            // fp16 activations: 4 inputs + attn-out
__device__ __half g_wfh[8ULL*WN];           // W^T fp16 hi
__device__ __half g_wfl[8ULL*WN];           // W^T fp16 lo (residual)
__device__ __nv_bfloat16 g_qh[(size_t)B_*NH_*L_*DCAT];
__device__ __nv_bfloat16 g_ql[(size_t)B_*NH_*L_*DCAT];
__device__ __nv_bfloat16 g_kh[(size_t)B_*NH_*L_*DCAT];
__device__ __nv_bfloat16 g_kl[(size_t)B_*NH_*L_*DCAT];
__device__ __nv_bfloat16 g_vth[(size_t)B_*NH_*HD_*L_];
__device__ __nv_bfloat16 g_vtl[(size_t)B_*NH_*HD_*L_];

// ---------------- PTX helpers (baseline ISA only) ----------------
__device__ __forceinline__ uint32_t smem_u32(const void* p) {
    uint32_t a;
    asm("{ .reg .u64 t; cvta.to.shared.u64 t, %1; cvt.u32.u64 %0, t; }" : "=r"(a) : "l"(p));
    return a;
}
__device__ __forceinline__ void cp16(uint32_t dst, const void* src) {
    asm volatile("cp.async.cg.shared.global [%0], [%1], 16;" :: "r"(dst), "l"(src));
}
__device__ __forceinline__ void ldm_x4(uint32_t* r, uint32_t addr) {
    asm volatile("ldmatrix.sync.aligned.m8n8.x4.shared.b16 {%0,%1,%2,%3}, [%4];"
                 : "=r"(r[0]), "=r"(r[1]), "=r"(r[2]), "=r"(r[3]) : "r"(addr));
}
// bf16 mma (attention)
__device__ __forceinline__ void mma16816(float* d, const uint32_t* a, const uint32_t* b) {
    asm volatile(
        "mma.sync.aligned.m16n8k16.row.col.f32.bf16.bf16.f32 "
        "{%0,%1,%2,%3}, {%4,%5,%6,%7}, {%8,%9}, {%0,%1,%2,%3};"
        : "+f"(d[0]), "+f"(d[1]), "+f"(d[2]), "+f"(d[3])
        : "r"(a[0]), "r"(a[1]), "r"(a[2]), "r"(a[3]), "r"(b[0]), "r"(b[1]));
}
// fp16 mma (projection / output GEMMs)
__device__ __forceinline__ void mma16816h(float* d, const uint32_t* a, const uint32_t* b) {
    asm volatile(
        "mma.sync.aligned.m16n8k16.row.col.f32.f16.f16.f32 "
        "{%0,%1,%2,%3}, {%4,%5,%6,%7}, {%8,%9}, {%0,%1,%2,%3};"
        : "+f"(d[0]), "+f"(d[1]), "+f"(d[2]), "+f"(d[3])
        : "r"(a[0]), "r"(a[1]), "r"(a[2]), "r"(a[3]), "r"(b[0]), "r"(b[1]));
}
__device__ __forceinline__ uint32_t pack_bf2(float a, float b) {
    __nv_bfloat162 t;
    t.x = __float2bfloat16(a); t.y = __float2bfloat16(b);
    return *(uint32_t*)&t;
}

// ---------------- batched fp32 -> fp16 ----------------
struct SplitSrc { const float* p[4]; };
__global__ __launch_bounds__(256)
void split_f16(SplitSrc s, __half* __restrict__ dst, int n4)
{
    int i = blockIdx.x * 256 + threadIdx.x;
    if (i >= n4) return;
    int z = blockIdx.y;
    const float* src = s.p[z];
    __half* dz = dst + (size_t)z * XN;
    float4 v = ((const float4*)src)[i];
    __half2 a = __floats2half2_rn(v.x, v.y);
    __half2 b = __floats2half2_rn(v.z, v.w);
    ((__half2*)dz)[i*2]   = a;
    ((__half2*)dz)[i*2+1] = b;
}

// ---------------- batched W[k][n] -> W^T[n][k] fp16 split ----------------
struct WSrc { const float* p[8]; };
__global__ __launch_bounds__(256)
void splitT_h(WSrc s, __half* __restrict__ hiT, __half* __restrict__ loT)
{
    __shared__ float t[32][33];
    int z = blockIdx.z;
    const float* W = s.p[z];
    __half* hz = hiT + (size_t)z * WN;
    __half* lz = loT + (size_t)z * WN;
    int bx = blockIdx.x * 32, by = blockIdx.y * 32;
    int tx = threadIdx.x, ty = threadIdx.y;
#pragma unroll
    for (int j = 0; j < 4; j++)
        t[ty + 8*j][tx] = W[(size_t)(by + ty + 8*j) * HID_ + bx + tx];
    __syncthreads();
#pragma unroll
    for (int j = 0; j < 4; j++) {
        float v = t[tx][ty + 8*j];
        int n = bx + ty + 8*j, k = by + tx;
        __half h = __float2half(v);
        hz[(size_t)n * HID_ + k] = h;
        lz[(size_t)n * HID_ + k] = __float2half(v - __half2float(h));
    }
}

// ---------------- GEMM core: load A once, apply Bh+Bl; CTA 128x128, 2-stage ----------------
#define KC        64
#define NCHUNKW   16
#define ROWB      144u
#define ATILE_B   (128u*ROWB)            // 18432
#define STAGE_B   (3u*ATILE_B)           // 55296 (A + Bh + Bl)
#define GEMM_SMEM (2*STAGE_B)            // 110592  -> occ 2

__device__ __forceinline__ void gemm_load_tile(
    uint32_t sbase, int stage, int c, int m0, int n0, int tid,
    const __half* A, const __half* Bh, const __half* Bl)
{
    const int k0 = c * KC;
    const uint32_t dstA = sbase + (uint32_t)stage * STAGE_B;
#pragma unroll
    for (int i = 0; i < 12; i++) {
        int idx = i * 256 + tid;                 // 0..3071 16B segments
        int r = (idx >> 3) & 127, c16 = idx & 7;
        if (idx < 1024)
            cp16(dstA + r * ROWB + c16 * 16,
                 A + (size_t)(m0 + r) * HID_ + k0 + c16 * 8);
        else if (idx < 2048)
            cp16(dstA + ATILE_B + r * ROWB + c16 * 16,
                 Bh + (size_t)(n0 + r) * HID_ + k0 + c16 * 8);
        else
            cp16(dstA + 2 * ATILE_B + r * ROWB + c16 * 16,
                 Bl + (size_t)(n0 + r) * HID_ + k0 + c16 * 8);
    }
    asm volatile("cp.async.commit_group;");
}

__device__ __forceinline__ void gemm_core(
    uint32_t sbase, int m0, int n0, int tid, int wm, int wn, int lane,
    const __half* A, const __half* Bh, const __half* Bl,
    float acc[2][8][4])
{
    const int arow = wm * 32 + (lane & 7) + ((lane >> 3) & 1) * 8;
    const uint32_t a_l = (uint32_t)arow * ROWB + ((lane >> 4) * 16);
    const int brow = wn * 64 + (lane & 7) + ((lane >> 4) & 1) * 8;
    const uint32_t b_l = (uint32_t)brow * ROWB + (((lane >> 3) & 1) * 16);

    gemm_load_tile(sbase, 0, 0, m0, n0, tid, A, Bh, Bl);

    for (int c = 0; c < NCHUNKW; c++) {
        // issue next-chunk load into the other stage (safe: its previous
        // consumer finished at the end-of-chunk sync of iteration c-1)
        if (c + 1 < NCHUNKW)
            gemm_load_tile(sbase, (c + 1) & 1, c + 1, m0, n0, tid, A, Bh, Bl);
        if (c + 1 < NCHUNKW) asm volatile("cp.async.wait_group 1;" ::: "memory");
        else                 asm volatile("cp.async.wait_group 0;" ::: "memory");
        __syncthreads();

        const uint32_t sb = sbase + (uint32_t)(c & 1) * STAGE_B;
        const uint32_t aBase  = sb + a_l;
        const uint32_t bhBase = sb + ATILE_B + b_l;
        const uint32_t blBase = sb + 2 * ATILE_B + b_l;
#pragma unroll
        for (int kk = 0; kk < KC / 16; kk++) {
            const uint32_t koff = kk * 32;
            uint32_t aq[2][4];
#pragma unroll
            for (int mf = 0; mf < 2; mf++)
                ldm_x4(aq[mf], aBase + mf * 16 * ROWB + koff);
            uint32_t bqh[16], bql[16];
#pragma unroll
            for (int np = 0; np < 4; np++) {
                ldm_x4(&bqh[np * 4], bhBase + np * 16 * ROWB + koff);
                ldm_x4(&bql[np * 4], blBase + np * 16 * ROWB + koff);
            }
#pragma unroll
            for (int mf = 0; mf < 2; mf++)
#pragma unroll
                for (int nf = 0; nf < 8; nf++) {
                    mma16816h(acc[mf][nf], aq[mf], &bqh[(nf >> 1) * 4 + (nf & 1) * 2]);
                    mma16816h(acc[mf][nf], aq[mf], &bql[(nf >> 1) * 4 + (nf & 1) * 2]);
                }
        }
        __syncthreads();   // all warps done with stage (c&1) before it is reloaded
    }
}

// ---------------- batched projection GEMMs (split-bf16 out for attention) ----------------
struct GemmB {
    const __half *A[7], *Bh[7], *Bl[7];
    const float* bias[7];
    __nv_bfloat16 *Oh[7], *Ol[7];
    int mode[7];
    int part[7];
};

__global__ __launch_bounds__(256, 2)
void gemm_batch(GemmB args)
{
    extern __shared__ char smem[];
    const uint32_t sbase = smem_u32(smem);
    const int z = blockIdx.z;
    const int tid = threadIdx.x;
    const int wid = tid >> 5, lane = tid & 31;
    const int m0 = blockIdx.y * 128, n0 = blockIdx.x * 128;
    const int wm = wid & 3, wn = wid >> 2;

    float acc[2][8][4];
#pragma unroll
    for (int mf = 0; mf < 2; mf++)
#pragma unroll
        for (int nf = 0; nf < 8; nf++)
#pragma unroll
            for (int q = 0; q < 4; q++) acc[mf][nf][q] = 0.f;

    gemm_core(sbase, m0, n0, tid, wm, wn, lane,
              args.A[z], args.Bh[z], args.Bl[z], acc);

    const float* bias = args.bias[z];
    __nv_bfloat16* Oh = args.Oh[z];
    __nv_bfloat16* Ol = args.Ol[z];
    const int mode = args.mode[z], part = args.part[z];

    const int g = lane >> 2, tq = lane & 3;
    float2 bv[8];
#pragma unroll
    for (int nf = 0; nf < 8; nf++)
        bv[nf] = *(const float2*)(bias + n0 + wn * 64 + nf * 8 + 2 * tq);

#pragma unroll
    for (int mf = 0; mf < 2; mf++) {
#pragma unroll
        for (int half = 0; half < 2; half++) {
            const int m = m0 + wm * 32 + mf * 16 + g + half * 8;
            const int bb = m >> 9, ll = m & 511;
#pragma unroll
            for (int nf = 0; nf < 8; nf++) {
                const int n = n0 + wn * 64 + nf * 8 + 2 * tq;
                const int h = n >> 6, dd = n & 63;
                float vx = acc[mf][nf][half * 2 + 0] + bv[nf].x;
                float vy = acc[mf][nf][half * 2 + 1] + bv[nf].y;
                __nv_bfloat16 hx = __float2bfloat16(vx), hy = __float2bfloat16(vy);
                __nv_bfloat16 lx = __float2bfloat16(vx - __bfloat162float(hx));
                __nv_bfloat16 ly = __float2bfloat16(vy - __bfloat162float(hy));
                if (mode == 0) {
                    size_t dst = ((((size_t)bb * NH_ + h) * L_ + ll) * DCAT)
                               + (size_t)part * 64 + dd;
                    __nv_bfloat162 hi2{hx, hy}, lo2{lx, ly};
                    *(__nv_bfloat162*)(Oh + dst) = hi2;
                    *(__nv_bfloat162*)(Ol + dst) = lo2;
                } else {
                    size_t dst = (((size_t)bb * NH_ + h) * HD_ + dd) * L_ + ll;
                    Oh[dst] = hx;  Ol[dst] = lx;
                    Oh[dst + L_] = hy;  Ol[dst + L_] = ly;
                }
            }
        }
    }
}

// ---------------- output projection GEMM (fp32 out) ----------------
__global__ __launch_bounds__(256, 2)
void gemm_out(const __half* __restrict__ A,
              const __half* __restrict__ Bh, const __half* __restrict__ Bl,
              const float* __restrict__ bias, float* __restrict__ out)
{
    extern __shared__ char smem[];
    const uint32_t sbase = smem_u32(smem);
    const int tid = threadIdx.x;
    const int wid = tid >> 5, lane = tid & 31;
    const int m0 = blockIdx.y * 128, n0 = blockIdx.x * 128;
    const int wm = wid & 3, wn = wid >> 2;

    float acc[2][8][4];
#pragma unroll
    for (int mf = 0; mf < 2; mf++)
#pragma unroll
        for (int nf = 0; nf < 8; nf++)
#pragma unroll
            for (int q = 0; q < 4; q++) acc[mf][nf][q] = 0.f;

    gemm_core(sbase, m0, n0, tid, wm, wn, lane, A, Bh, Bl, acc);

    const int g = lane >> 2, tq = lane & 3;
    float2 bv[8];
#pragma unroll
    for (int nf = 0; nf < 8; nf++)
        bv[nf] = *(const float2*)(bias + n0 + wn * 64 + nf * 8 + 2 * tq);
#pragma unroll
    for (int mf = 0; mf < 2; mf++)
#pragma unroll
        for (int half = 0; half < 2; half++) {
            const int m = m0 + wm * 32 + mf * 16 + g + half * 8;
#pragma unroll
            for (int nf = 0; nf < 8; nf++) {
                const int n = n0 + wn * 64 + nf * 8 + 2 * tq;
                float2 v;
                v.x = acc[mf][nf][half * 2 + 0] + bv[nf].x;
                v.y = acc[mf][nf][half * 2 + 1] + bv[nf].y;
                *(float2*)(out + (size_t)m * HID_ + n) = v;
            }
        }
}

// ---------------- flash attention via mma.sync (bf16 3-product, unchanged) ----------------
#define AQ_STRIDE 400u
#define AV_STRIDE 144u
#define SM_QH 0u
#define SM_QL 51200u
#define SM_KH 102400u
#define SM_KL 128000u
#define SM_VH 153600u
#define SM_VL 162816u
#define ATT_SMEM 172032

__global__ __launch_bounds__(256, 1)
void attn_mma(const float* __restrict__ rel,
              const __nv_bfloat16* __restrict__ Qh, const __nv_bfloat16* __restrict__ Ql,
              const __nv_bfloat16* __restrict__ Kh, const __nv_bfloat16* __restrict__ Kl,
              const __nv_bfloat16* __restrict__ Vth, const __nv_bfloat16* __restrict__ Vtl,
              __half* __restrict__ Of)
{
    extern __shared__ char smc[];
    const uint32_t sb = smem_u32(smc);
    const int qt = (int)gridDim.x - 1 - (int)blockIdx.x;   // heavy CTAs first
    const int bh = blockIdx.y;
    const int q0 = qt * 128;
    const int tid = threadIdx.x, wid = tid >> 5, lane = tid & 31;
    const int g = lane >> 2, tq = lane & 3;
    const int wrow = wid * 16;

    const __nv_bfloat16* qh_g = Qh  + (size_t)bh * L_ * DCAT;
    const __nv_bfloat16* ql_g = Ql  + (size_t)bh * L_ * DCAT;
    const __nv_bfloat16* kh_g = Kh  + (size_t)bh * L_ * DCAT;
    const __nv_bfloat16* kl_g = Kl  + (size_t)bh * L_ * DCAT;
    const __nv_bfloat16* vh_g = Vth + (size_t)bh * HD_ * L_;
    const __nv_bfloat16* vl_g = Vtl + (size_t)bh * HD_ * L_;
    const float* relg = rel + (size_t)bh * L_ * L_;

#pragma unroll
    for (int i = 0; i < 24; i++) {
        int idx = i * 256 + tid;
        int mat = idx >= 3072;
        int j = idx - mat * 3072;
        int r = j / 24, s2 = j % 24;
        cp16(sb + (mat ? SM_QL : SM_QH) + r * AQ_STRIDE + s2 * 16,
             (mat ? ql_g : qh_g) + (size_t)(q0 + r) * DCAT + s2 * 8);
    }
    asm volatile("cp.async.commit_group;");

    float m_i[2] = {-3.0e38f, -3.0e38f};
    float l_i[2] = {0.f, 0.f};
    float oacc[8][4];
#pragma unroll
    for (int nf = 0; nf < 8; nf++)
#pragma unroll
        for (int q = 0; q < 4; q++) oacc[nf][q] = 0.f;

    const uint32_t aoffQ = (uint32_t)(wrow + (lane & 7) + ((lane >> 3) & 1) * 8) * AQ_STRIDE
                         + (lane >> 4) * 16;
    const uint32_t boffK = (uint32_t)((lane & 7) + ((lane >> 4) & 1) * 8) * AQ_STRIDE
                         + ((lane >> 3) & 1) * 16;
    const uint32_t boffV = (uint32_t)((lane & 7) + ((lane >> 4) & 1) * 8) * AV_STRIDE
                         + ((lane >> 3) & 1) * 16;

    const int row0c = q0 + wrow + g;
    const int row1c = row0c + 8;

    const int ntiles = qt * 2 + 2;
    for (int kt = 0; kt < ntiles; kt++) {
        const int k0 = kt * 64;
        __syncthreads();
#pragma unroll
        for (int i = 0; i < 16; i++) {
            int idx = i * 256 + tid;
            if (idx < 3072) {
                int mat = idx >= 1536;
                int j = idx - mat * 1536;
                int r = j / 24, s2 = j % 24;
                cp16(sb + (mat ? SM_KL : SM_KH) + r * AQ_STRIDE + s2 * 16,
                     (mat ? kl_g : kh_g) + (size_t)(k0 + r) * DCAT + s2 * 8);
            } else {
                int j = idx - 3072;
                int mat = j >= 512;
                j -= mat * 512;
                int d = j / 8, s2 = j % 8;
                cp16(sb + (mat ? SM_VL : SM_VH) + d * AV_STRIDE + s2 * 16,
                     (mat ? vl_g : vh_g) + (size_t)d * L_ + k0 + s2 * 8);
            }
        }
        asm volatile("cp.async.commit_group;");
        asm volatile("cp.async.wait_group 0;" ::: "memory");
        __syncthreads();

        if (k0 > q0 + wrow + 15) continue;

        float2 rr0[8], rr1[8];
#pragma unroll
        for (int nf = 0; nf < 8; nf++) {
            const int col = k0 + nf * 8 + 2 * tq;
            rr0[nf] = *(const float2*)(relg + (size_t)row0c * L_ + col);
            rr1[nf] = *(const float2*)(relg + (size_t)row1c * L_ + col);
        }

        float sacc[8][4];
#pragma unroll
        for (int nf = 0; nf < 8; nf++)
#pragma unroll
            for (int q = 0; q < 4; q++) sacc[nf][q] = 0.f;

#pragma unroll
        for (int ks = 0; ks < 12; ks++) {
            const uint32_t koff = ks * 32;
            uint32_t aqh[4], aql[4], bqh[16], bql[16];
            ldm_x4(aqh, sb + SM_QH + aoffQ + koff);
            ldm_x4(aql, sb + SM_QL + aoffQ + koff);
#pragma unroll
            for (int np = 0; np < 4; np++) {
                ldm_x4(&bqh[np * 4], sb + SM_KH + boffK + np * 16 * AQ_STRIDE + koff);
                ldm_x4(&bql[np * 4], sb + SM_KL + boffK + np * 16 * AQ_STRIDE + koff);
            }
#pragma unroll
            for (int nf = 0; nf < 8; nf++) {
                const uint32_t* bh_ = &bqh[(nf >> 1) * 4 + (nf & 1) * 2];
                const uint32_t* bl_ = &bql[(nf >> 1) * 4 + (nf & 1) * 2];
                mma16816(sacc[nf], aqh, bh_);
                mma16816(sacc[nf], aqh, bl_);
                mma16816(sacc[nf], aql, bh_);
            }
        }

        const int row0 = row0c;
        const int row1 = row1c;
        const bool diag = (k0 + 63 > q0 + wrow);
        float pmax0 = -3.0e38f, pmax1 = -3.0e38f;
#pragma unroll
        for (int nf = 0; nf < 8; nf++) {
            const int col = k0 + nf * 8 + 2 * tq;
            float s0 = fmaf(sacc[nf][0], 0.125f, rr0[nf].x);
            float s1 = fmaf(sacc[nf][1], 0.125f, rr0[nf].y);
            float s2 = fmaf(sacc[nf][2], 0.125f, rr1[nf].x);
            float s3 = fmaf(sacc[nf][3], 0.125f, rr1[nf].y);
            if (diag) {
                if (col     > row0) s0 = -3.0e38f;
                if (col + 1 > row0) s1 = -3.0e38f;
                if (col     > row1) s2 = -3.0e38f;
                if (col + 1 > row1) s3 = -3.0e38f;
            }
            sacc[nf][0] = s0; sacc[nf][1] = s1; sacc[nf][2] = s2; sacc[nf][3] = s3;
            pmax0 = fmaxf(pmax0, fmaxf(s0, s1));
            pmax1 = fmaxf(pmax1, fmaxf(s2, s3));
        }
        {
            __half2 hm = __floats2half2_rn(pmax0, pmax1);
#pragma unroll
            for (int d = 1; d < 4; d <<= 1) {
                uint32_t u = *(uint32_t*)&hm;
                uint32_t v = __shfl_xor_sync(0xffffffffu, u, d);
                hm = __hmax2(hm, *(__half2*)&v);
            }
            float2 fm = __half22float2(hm);
            pmax0 = fm.x;  pmax1 = fm.y;
        }
        const float nm0 = fmaxf(m_i[0], pmax0);
        const float nm1 = fmaxf(m_i[1], pmax1);
        const float al0 = __expf(m_i[0] - nm0);
        const float al1 = __expf(m_i[1] - nm1);
        float rs0 = 0.f, rs1 = 0.f;
#pragma unroll
        for (int nf = 0; nf < 8; nf++) {
            sacc[nf][0] = __expf(sacc[nf][0] - nm0);
            sacc[nf][1] = __expf(sacc[nf][1] - nm0);
            sacc[nf][2] = __expf(sacc[nf][2] - nm1);
            sacc[nf][3] = __expf(sacc[nf][3] - nm1);
            rs0 += sacc[nf][0] + sacc[nf][1];
            rs1 += sacc[nf][2] + sacc[nf][3];
        }
#pragma unroll
        for (int d = 1; d < 4; d <<= 1) {
            rs0 += __shfl_xor_sync(0xffffffffu, rs0, d);
            rs1 += __shfl_xor_sync(0xffffffffu, rs1, d);
        }
        l_i[0] = l_i[0] * al0 + rs0;  m_i[0] = nm0;
        l_i[1] = l_i[1] * al1 + rs1;  m_i[1] = nm1;
#pragma unroll
        for (int nf = 0; nf < 8; nf++) {
            oacc[nf][0] *= al0; oacc[nf][1] *= al0;
            oacc[nf][2] *= al1; oacc[nf][3] *= al1;
        }

#pragma unroll
        for (int ks = 0; ks < 4; ks++) {
            uint32_t afh[4], afl[4];
            {
                float p00 = sacc[2*ks][0],   p01 = sacc[2*ks][1];
                float p02 = sacc[2*ks][2],   p03 = sacc[2*ks][3];
                float p10 = sacc[2*ks+1][0], p11 = sacc[2*ks+1][1];
                float p12 = sacc[2*ks+1][2], p13 = sacc[2*ks+1][3];
                afh[0] = pack_bf2(p00, p01);
                afh[1] = pack_bf2(p02, p03);
                afh[2] = pack_bf2(p10, p11);
                afh[3] = pack_bf2(p12, p13);
                __nv_bfloat162 h0 = *(__nv_bfloat162*)&afh[0];
                __nv_bfloat162 h1 = *(__nv_bfloat162*)&afh[1];
                __nv_bfloat162 h2 = *(__nv_bfloat162*)&afh[2];
                __nv_bfloat162 h3 = *(__nv_bfloat162*)&afh[3];
                afl[0] = pack_bf2(p00 - __bfloat162float(h0.x), p01 - __bfloat162float(h0.y));
                afl[1] = pack_bf2(p02 - __bfloat162float(h1.x), p03 - __bfloat162float(h1.y));
                afl[2] = pack_bf2(p10 - __bfloat162float(h2.x), p11 - __bfloat162float(h2.y));
                afl[3] = pack_bf2(p12 - __bfloat162float(h3.x), p13 - __bfloat162float(h3.y));
            }
            uint32_t bvh[16], bvl[16];
            const uint32_t koff = ks * 32;
#pragma unroll
            for (int np = 0; np < 4; np++) {
                ldm_x4(&bvh[np * 4], sb + SM_VH + boffV + np * 16 * AV_STRIDE + koff);
                ldm_x4(&bvl[np * 4], sb + SM_VL + boffV + np * 16 * AV_STRIDE + koff);
            }
#pragma unroll
            for (int nf = 0; nf < 8; nf++) {
                const uint32_t* bh_ = &bvh[(nf >> 1) * 4 + (nf & 1) * 2];
                const uint32_t* bl_ = &bvl[(nf >> 1) * 4 + (nf & 1) * 2];
                mma16816(oacc[nf], afh, bh_);
                mma16816(oacc[nf], afh, bl_);
                mma16816(oacc[nf], afl, bh_);
            }
        }
    }

    const int b = bh >> 4, h = bh & 15;
    const float inv0 = 1.0f / l_i[0];
    const float inv1 = 1.0f / l_i[1];
    const size_t m0g = (size_t)(b * L_ + q0 + wrow + g) * HID_;
    const size_t m1g = m0g + 8 * HID_;
#pragma unroll
    for (int nf = 0; nf < 8; nf++) {
        const int col = h * 64 + nf * 8 + 2 * tq;
        __half2 o0 = __floats2half2_rn(oacc[nf][0] * inv0, oacc[nf][1] * inv0);
        __half2 o1 = __floats2half2_rn(oacc[nf][2] * inv1, oacc[nf][3] * inv1);
        *(__half2*)(Of + m0g + col) = o0;
        *(__half2*)(Of + m1g + col) = o1;
    }
}

// ---------------- launcher ----------------
extern "C" void kernel_launch(void* const* d_in, const int* in_sizes, int n_in,
                              void* d_out, int out_size)
{
    const float* rel = (const float*)d_in[5];
    float* out = (float*)d_out;

    __half *xf, *wfh, *wfl;
    __nv_bfloat16 *qh, *ql, *kh, *kl, *vth, *vtl;
    cudaGetSymbolAddress((void**)&xf, g_xf);
    cudaGetSymbolAddress((void**)&wfh, g_wfh);
    cudaGetSymbolAddress((void**)&wfl, g_wfl);
    cudaGetSymbolAddress((void**)&qh, g_qh);
    cudaGetSymbolAddress((void**)&ql, g_ql);
    cudaGetSymbolAddress((void**)&kh, g_kh);
    cudaGetSymbolAddress((void**)&kl, g_kl);
    cudaGetSymbolAddress((void**)&vth, g_vth);
    cudaGetSymbolAddress((void**)&vtl, g_vtl);

    cudaFuncSetAttribute(gemm_batch, cudaFuncAttributeMaxDynamicSharedMemorySize, GEMM_SMEM);
    cudaFuncSetAttribute(gemm_out, cudaFuncAttributeMaxDynamicSharedMemorySize, GEMM_SMEM);
    cudaFuncSetAttribute(attn_mma, cudaFuncAttributeMaxDynamicSharedMemorySize, ATT_SMEM);

    const int n4 = (int)(XN / 4);

    SplitSrc ss;
    ss.p[0] = (const float*)d_in[0];
    ss.p[1] = (const float*)d_in[1];
    ss.p[2] = (const float*)d_in[2];
    ss.p[3] = (const float*)d_in[3];
    split_f16<<<dim3((n4 + 255) / 256, 4), 256>>>(ss, xf, n4);

    WSrc ws;
    ws.p[0] = (const float*)d_in[6];   ws.p[1] = (const float*)d_in[8];
    ws.p[2] = (const float*)d_in[10];  ws.p[3] = (const float*)d_in[12];
    ws.p[4] = (const float*)d_in[14];  ws.p[5] = (const float*)d_in[16];
    ws.p[6] = (const float*)d_in[18];  ws.p[7] = (const float*)d_in[20];
    splitT_h<<<dim3(32, 32, 8), dim3(32, 8)>>>(ws, wfh, wfl);

    GemmB gb;
    const int ain[7]  = {0, 1, 2, 0, 1, 2, 3};
    const int wsl[7]  = {0, 3, 5, 1, 4, 6, 2};
    const int bidx[7] = {7, 13, 17, 9, 15, 19, 11};
    for (int z = 0; z < 7; z++) {
        gb.A[z]  = xf + (size_t)ain[z] * XN;
        gb.Bh[z] = wfh + (size_t)wsl[z] * WN;
        gb.Bl[z] = wfl + (size_t)wsl[z] * WN;
        gb.bias[z] = (const float*)d_in[bidx[z]];
    }
    gb.Oh[0] = qh;  gb.Ol[0] = ql;  gb.mode[0] = 0; gb.part[0] = 0;
    gb.Oh[1] = qh;  gb.Ol[1] = ql;  gb.mode[1] = 0; gb.part[1] = 1;
    gb.Oh[2] = qh;  gb.Ol[2] = ql;  gb.mode[2] = 0; gb.part[2] = 2;
    gb.Oh[3] = kh;  gb.Ol[3] = kl;  gb.mode[3] = 0; gb.part[3] = 0;
    gb.Oh[4] = kh;  gb.Ol[4] = kl;  gb.mode[4] = 0; gb.part[4] = 1;
    gb.Oh[5] = kh;  gb.Ol[5] = kl;  gb.mode[5] = 0; gb.part[5] = 2;
    gb.Oh[6] = vth; gb.Ol[6] = vtl; gb.mode[6] = 1; gb.part[6] = 0;
    gemm_batch<<<dim3(8, 64, 7), 256, GEMM_SMEM>>>(gb);

    attn_mma<<<dim3(4, 256), 256, ATT_SMEM>>>(rel, qh, ql, kh, kl, vth, vtl,
                                              xf + 4 * XN);

    gemm_out<<<dim3(8, 64), 256, GEMM_SMEM>>>(xf + 4 * XN,
                                              wfh + 7 * WN, wfl + 7 * WN,
                                              (const float*)d_in[21], out);
}

// round 10
// speedup vs baseline: 1.5796x; 1.0388x over previous
#include <cuda_runtime.h>
#include <cuda_bf16.h>
#include <cuda_fp16.h>
#include <cstdint>

#define B_    16
#define L_    512
#define HID_  1024
#define NH_   16
#define HD_   64
#define M_TOT (B_*L_)      // 8192
#define DCAT  192
#define XN    ((size_t)M_TOT*HID_)
#define WN    ((size_t)HID_*HID_)

// ---------------- scratch (static device arrays) ----------------
__device__ __half g_xf[5ULL*XN];            // fp16 activations: 4 inputs + attn-out
__device__ __half g_wfh[8ULL*WN];           // W^T fp16 hi
__device__ __half g_wfl[8ULL*WN];           // W^T fp16 lo (residual)
__device__ __half g_qf [(size_t)B_*NH_*L_*DCAT];   // Q single fp16
__device__ __half g_k16h[(size_t)B_*NH_*L_*DCAT];  // K fp16 hi
__device__ __half g_k16l[(size_t)B_*NH_*L_*DCAT];  // K fp16 lo
__device__ __half g_v16h[(size_t)B_*NH_*HD_*L_];   // Vt fp16 hi
__device__ __half g_v16l[(size_t)B_*NH_*HD_*L_];   // Vt fp16 lo

// ---------------- PTX helpers (baseline ISA only) ----------------
__device__ __forceinline__ uint32_t smem_u32(const void* p) {
    uint32_t a;
    asm("{ .reg .u64 t; cvta.to.shared.u64 t, %1; cvt.u32.u64 %0, t; }" : "=r"(a) : "l"(p));
    return a;
}
__device__ __forceinline__ void cp16(uint32_t dst, const void* src) {
    asm volatile("cp.async.cg.shared.global [%0], [%1], 16;" :: "r"(dst), "l"(src));
}
__device__ __forceinline__ void ldm_x4(uint32_t* r, uint32_t addr) {
    asm volatile("ldmatrix.sync.aligned.m8n8.x4.shared.b16 {%0,%1,%2,%3}, [%4];"
                 : "=r"(r[0]), "=r"(r[1]), "=r"(r[2]), "=r"(r[3]) : "r"(addr));
}
// fp16 mma
__device__ __forceinline__ void mma16816h(float* d, const uint32_t* a, const uint32_t* b) {
    asm volatile(
        "mma.sync.aligned.m16n8k16.row.col.f32.f16.f16.f32 "
        "{%0,%1,%2,%3}, {%4,%5,%6,%7}, {%8,%9}, {%0,%1,%2,%3};"
        : "+f"(d[0]), "+f"(d[1]), "+f"(d[2]), "+f"(d[3])
        : "r"(a[0]), "r"(a[1]), "r"(a[2]), "r"(a[3]), "r"(b[0]), "r"(b[1]));
}
__device__ __forceinline__ uint32_t pack_h2(float a, float b) {
    __half2 t = __floats2half2_rn(a, b);
    return *(uint32_t*)&t;
}

// ---------------- batched fp32 -> fp16 ----------------
struct SplitSrc { const float* p[4]; };
__global__ __launch_bounds__(256)
void split_f16(SplitSrc s, __half* __restrict__ dst, int n4)
{
    int i = blockIdx.x * 256 + threadIdx.x;
    if (i >= n4) return;
    int z = blockIdx.y;
    const float* src = s.p[z];
    __half* dz = dst + (size_t)z * XN;
    float4 v = ((const float4*)src)[i];
    __half2 a = __floats2half2_rn(v.x, v.y);
    __half2 b = __floats2half2_rn(v.z, v.w);
    ((__half2*)dz)[i*2]   = a;
    ((__half2*)dz)[i*2+1] = b;
}

// ---------------- batched W[k][n] -> W^T[n][k] fp16 split ----------------
struct WSrc { const float* p[8]; };
__global__ __launch_bounds__(256)
void splitT_h(WSrc s, __half* __restrict__ hiT, __half* __restrict__ loT)
{
    __shared__ float t[32][33];
    int z = blockIdx.z;
    const float* W = s.p[z];
    __half* hz = hiT + (size_t)z * WN;
    __half* lz = loT + (size_t)z * WN;
    int bx = blockIdx.x * 32, by = blockIdx.y * 32;
    int tx = threadIdx.x, ty = threadIdx.y;
#pragma unroll
    for (int j = 0; j < 4; j++)
        t[ty + 8*j][tx] = W[(size_t)(by + ty + 8*j) * HID_ + bx + tx];
    __syncthreads();
#pragma unroll
    for (int j = 0; j < 4; j++) {
        float v = t[tx][ty + 8*j];
        int n = bx + ty + 8*j, k = by + tx;
        __half h = __float2half(v);
        hz[(size_t)n * HID_ + k] = h;
        lz[(size_t)n * HID_ + k] = __float2half(v - __half2float(h));
    }
}

// ---------------- GEMM core: load A once, apply Bh+Bl; CTA 128x128, 2-stage ----------------
#define KC        64
#define NCHUNKW   16
#define ROWB      144u
#define ATILE_B   (128u*ROWB)            // 18432
#define STAGE_B   (3u*ATILE_B)           // 55296 (A + Bh + Bl)
#define GEMM_SMEM (2*STAGE_B)            // 110592  -> occ 2

__device__ __forceinline__ void gemm_load_tile(
    uint32_t sbase, int stage, int c, int m0, int n0, int tid,
    const __half* A, const __half* Bh, const __half* Bl)
{
    const int k0 = c * KC;
    const uint32_t dstA = sbase + (uint32_t)stage * STAGE_B;
#pragma unroll
    for (int i = 0; i < 12; i++) {
        int idx = i * 256 + tid;                 // 0..3071 16B segments
        int r = (idx >> 3) & 127, c16 = idx & 7;
        if (idx < 1024)
            cp16(dstA + r * ROWB + c16 * 16,
                 A + (size_t)(m0 + r) * HID_ + k0 + c16 * 8);
        else if (idx < 2048)
            cp16(dstA + ATILE_B + r * ROWB + c16 * 16,
                 Bh + (size_t)(n0 + r) * HID_ + k0 + c16 * 8);
        else
            cp16(dstA + 2 * ATILE_B + r * ROWB + c16 * 16,
                 Bl + (size_t)(n0 + r) * HID_ + k0 + c16 * 8);
    }
    asm volatile("cp.async.commit_group;");
}

__device__ __forceinline__ void gemm_core(
    uint32_t sbase, int m0, int n0, int tid, int wm, int wn, int lane,
    const __half* A, const __half* Bh, const __half* Bl,
    float acc[2][8][4])
{
    const int arow = wm * 32 + (lane & 7) + ((lane >> 3) & 1) * 8;
    const uint32_t a_l = (uint32_t)arow * ROWB + ((lane >> 4) * 16);
    const int brow = wn * 64 + (lane & 7) + ((lane >> 4) & 1) * 8;
    const uint32_t b_l = (uint32_t)brow * ROWB + (((lane >> 3) & 1) * 16);

    gemm_load_tile(sbase, 0, 0, m0, n0, tid, A, Bh, Bl);

    for (int c = 0; c < NCHUNKW; c++) {
        if (c + 1 < NCHUNKW)
            gemm_load_tile(sbase, (c + 1) & 1, c + 1, m0, n0, tid, A, Bh, Bl);
        if (c + 1 < NCHUNKW) asm volatile("cp.async.wait_group 1;" ::: "memory");
        else                 asm volatile("cp.async.wait_group 0;" ::: "memory");
        __syncthreads();

        const uint32_t sb = sbase + (uint32_t)(c & 1) * STAGE_B;
        const uint32_t aBase  = sb + a_l;
        const uint32_t bhBase = sb + ATILE_B + b_l;
        const uint32_t blBase = sb + 2 * ATILE_B + b_l;
#pragma unroll
        for (int kk = 0; kk < KC / 16; kk++) {
            const uint32_t koff = kk * 32;
            uint32_t aq[2][4];
#pragma unroll
            for (int mf = 0; mf < 2; mf++)
                ldm_x4(aq[mf], aBase + mf * 16 * ROWB + koff);
            uint32_t bqh[16], bql[16];
#pragma unroll
            for (int np = 0; np < 4; np++) {
                ldm_x4(&bqh[np * 4], bhBase + np * 16 * ROWB + koff);
                ldm_x4(&bql[np * 4], blBase + np * 16 * ROWB + koff);
            }
#pragma unroll
            for (int mf = 0; mf < 2; mf++)
#pragma unroll
                for (int nf = 0; nf < 8; nf++) {
                    mma16816h(acc[mf][nf], aq[mf], &bqh[(nf >> 1) * 4 + (nf & 1) * 2]);
                    mma16816h(acc[mf][nf], aq[mf], &bql[(nf >> 1) * 4 + (nf & 1) * 2]);
                }
        }
        __syncthreads();
    }
}

// ---------------- batched projection GEMMs (fp16 outputs for attention) ----------------
// mode 0: Q scatter [bh][l][192], single fp16
// mode 1: K scatter [bh][l][192], fp16 hi+lo
// mode 2: V transpose [bh][d][l], fp16 hi+lo
struct GemmB {
    const __half *A[7], *Bh[7], *Bl[7];
    const float* bias[7];
    __half *Oh[7], *Ol[7];
    int mode[7];
    int part[7];
};

__global__ __launch_bounds__(256, 2)
void gemm_batch(GemmB args)
{
    extern __shared__ char smem[];
    const uint32_t sbase = smem_u32(smem);
    const int z = blockIdx.z;
    const int tid = threadIdx.x;
    const int wid = tid >> 5, lane = tid & 31;
    const int m0 = blockIdx.y * 128, n0 = blockIdx.x * 128;
    const int wm = wid & 3, wn = wid >> 2;

    float acc[2][8][4];
#pragma unroll
    for (int mf = 0; mf < 2; mf++)
#pragma unroll
        for (int nf = 0; nf < 8; nf++)
#pragma unroll
            for (int q = 0; q < 4; q++) acc[mf][nf][q] = 0.f;

    gemm_core(sbase, m0, n0, tid, wm, wn, lane,
              args.A[z], args.Bh[z], args.Bl[z], acc);

    const float* bias = args.bias[z];
    __half* Oh = args.Oh[z];
    __half* Ol = args.Ol[z];
    const int mode = args.mode[z], part = args.part[z];

    const int g = lane >> 2, tq = lane & 3;
    float2 bv[8];
#pragma unroll
    for (int nf = 0; nf < 8; nf++)
        bv[nf] = *(const float2*)(bias + n0 + wn * 64 + nf * 8 + 2 * tq);

#pragma unroll
    for (int mf = 0; mf < 2; mf++) {
#pragma unroll
        for (int half = 0; half < 2; half++) {
            const int m = m0 + wm * 32 + mf * 16 + g + half * 8;
            const int bb = m >> 9, ll = m & 511;
#pragma unroll
            for (int nf = 0; nf < 8; nf++) {
                const int n = n0 + wn * 64 + nf * 8 + 2 * tq;
                const int h = n >> 6, dd = n & 63;
                float vx = acc[mf][nf][half * 2 + 0] + bv[nf].x;
                float vy = acc[mf][nf][half * 2 + 1] + bv[nf].y;
                __half hx = __float2half(vx), hy = __float2half(vy);
                if (mode == 0) {
                    size_t dst = ((((size_t)bb * NH_ + h) * L_ + ll) * DCAT)
                               + (size_t)part * 64 + dd;
                    __half2 hi2; hi2.x = hx; hi2.y = hy;
                    *(__half2*)(Oh + dst) = hi2;
                } else {
                    __half lx = __float2half(vx - __half2float(hx));
                    __half ly = __float2half(vy - __half2float(hy));
                    if (mode == 1) {
                        size_t dst = ((((size_t)bb * NH_ + h) * L_ + ll) * DCAT)
                                   + (size_t)part * 64 + dd;
                        __half2 hi2; hi2.x = hx; hi2.y = hy;
                        __half2 lo2; lo2.x = lx; lo2.y = ly;
                        *(__half2*)(Oh + dst) = hi2;
                        *(__half2*)(Ol + dst) = lo2;
                    } else {
                        size_t dst = (((size_t)bb * NH_ + h) * HD_ + dd) * L_ + ll;
                        Oh[dst] = hx;  Ol[dst] = lx;
                        Oh[dst + L_] = hy;  Ol[dst + L_] = ly;
                    }
                }
            }
        }
    }
}

// ---------------- output projection GEMM (fp32 out) ----------------
__global__ __launch_bounds__(256, 2)
void gemm_out(const __half* __restrict__ A,
              const __half* __restrict__ Bh, const __half* __restrict__ Bl,
              const float* __restrict__ bias, float* __restrict__ out)
{
    extern __shared__ char smem[];
    const uint32_t sbase = smem_u32(smem);
    const int tid = threadIdx.x;
    const int wid = tid >> 5, lane = tid & 31;
    const int m0 = blockIdx.y * 128, n0 = blockIdx.x * 128;
    const int wm = wid & 3, wn = wid >> 2;

    float acc[2][8][4];
#pragma unroll
    for (int mf = 0; mf < 2; mf++)
#pragma unroll
        for (int nf = 0; nf < 8; nf++)
#pragma unroll
            for (int q = 0; q < 4; q++) acc[mf][nf][q] = 0.f;

    gemm_core(sbase, m0, n0, tid, wm, wn, lane, A, Bh, Bl, acc);

    const int g = lane >> 2, tq = lane & 3;
    float2 bv[8];
#pragma unroll
    for (int nf = 0; nf < 8; nf++)
        bv[nf] = *(const float2*)(bias + n0 + wn * 64 + nf * 8 + 2 * tq);
#pragma unroll
    for (int mf = 0; mf < 2; mf++)
#pragma unroll
        for (int half = 0; half < 2; half++) {
            const int m = m0 + wm * 32 + mf * 16 + g + half * 8;
#pragma unroll
            for (int nf = 0; nf < 8; nf++) {
                const int n = n0 + wn * 64 + nf * 8 + 2 * tq;
                float2 v;
                v.x = acc[mf][nf][half * 2 + 0] + bv[nf].x;
                v.y = acc[mf][nf][half * 2 + 1] + bv[nf].y;
                *(float2*)(out + (size_t)m * HID_ + n) = v;
            }
        }
}

// ---------------- flash attention: fp16 2-product QK and PV ----------------
#define AQ_STRIDE 400u
#define AV_STRIDE 144u
#define SM_Q  0u
#define SM_KH 51200u
#define SM_KL 76800u
#define SM_VH 102400u
#define SM_VL 111616u
#define ATT_SMEM 120832

__global__ __launch_bounds__(256, 1)
void attn_mma(const float* __restrict__ rel,
              const __half* __restrict__ Qf,
              const __half* __restrict__ Kh, const __half* __restrict__ Kl,
              const __half* __restrict__ Vth, const __half* __restrict__ Vtl,
              __half* __restrict__ Of)
{
    extern __shared__ char smc[];
    const uint32_t sb = smem_u32(smc);
    const int qt = (int)gridDim.x - 1 - (int)blockIdx.x;   // heavy CTAs first
    const int bh = blockIdx.y;
    const int q0 = qt * 128;
    const int tid = threadIdx.x, wid = tid >> 5, lane = tid & 31;
    const int g = lane >> 2, tq = lane & 3;
    const int wrow = wid * 16;

    const __half* qf_g = Qf  + (size_t)bh * L_ * DCAT;
    const __half* kh_g = Kh  + (size_t)bh * L_ * DCAT;
    const __half* kl_g = Kl  + (size_t)bh * L_ * DCAT;
    const __half* vh_g = Vth + (size_t)bh * HD_ * L_;
    const __half* vl_g = Vtl + (size_t)bh * HD_ * L_;
    const float* relg = rel + (size_t)bh * L_ * L_;

    // Q tile load: 128 rows x 24 16B-segs
#pragma unroll
    for (int i = 0; i < 12; i++) {
        int idx = i * 256 + tid;
        int r = idx / 24, s2 = idx % 24;
        cp16(sb + SM_Q + r * AQ_STRIDE + s2 * 16,
             qf_g + (size_t)(q0 + r) * DCAT + s2 * 8);
    }
    asm volatile("cp.async.commit_group;");

    float m_i[2] = {-3.0e38f, -3.0e38f};
    float l_i[2] = {0.f, 0.f};
    float oacc[8][4];
#pragma unroll
    for (int nf = 0; nf < 8; nf++)
#pragma unroll
        for (int q = 0; q < 4; q++) oacc[nf][q] = 0.f;

    const uint32_t aoffQ = (uint32_t)(wrow + (lane & 7) + ((lane >> 3) & 1) * 8) * AQ_STRIDE
                         + (lane >> 4) * 16;
    const uint32_t boffK = (uint32_t)((lane & 7) + ((lane >> 4) & 1) * 8) * AQ_STRIDE
                         + ((lane >> 3) & 1) * 16;
    const uint32_t boffV = (uint32_t)((lane & 7) + ((lane >> 4) & 1) * 8) * AV_STRIDE
                         + ((lane >> 3) & 1) * 16;

    const int row0c = q0 + wrow + g;
    const int row1c = row0c + 8;

    const int ntiles = qt * 2 + 2;
    for (int kt = 0; kt < ntiles; kt++) {
        const int k0 = kt * 64;
        __syncthreads();
        // K hi+lo: 64x24 segs each (3072); Vt hi+lo: 64x8 segs each (1024)
#pragma unroll
        for (int i = 0; i < 16; i++) {
            int idx = i * 256 + tid;
            if (idx < 3072) {
                int mat = idx >= 1536;
                int j = idx - mat * 1536;
                int r = j / 24, s2 = j % 24;
                cp16(sb + (mat ? SM_KL : SM_KH) + r * AQ_STRIDE + s2 * 16,
                     (mat ? kl_g : kh_g) + (size_t)(k0 + r) * DCAT + s2 * 8);
            } else {
                int j = idx - 3072;
                int mat = j >= 512;
                j -= mat * 512;
                int d = j >> 3, s2 = j & 7;
                cp16(sb + (mat ? SM_VL : SM_VH) + d * AV_STRIDE + s2 * 16,
                     (mat ? vl_g : vh_g) + (size_t)d * L_ + k0 + s2 * 8);
            }
        }
        asm volatile("cp.async.commit_group;");
        asm volatile("cp.async.wait_group 0;" ::: "memory");
        __syncthreads();

        if (k0 > q0 + wrow + 15) continue;

        // prefetch relative_time bias (hidden under QK mma)
        float2 rr0[8], rr1[8];
#pragma unroll
        for (int nf = 0; nf < 8; nf++) {
            const int col = k0 + nf * 8 + 2 * tq;
            rr0[nf] = *(const float2*)(relg + (size_t)row0c * L_ + col);
            rr1[nf] = *(const float2*)(relg + (size_t)row1c * L_ + col);
        }

        // ---- S = Q*(Kh + Kl) over k=192, fp16 ----
        float sacc[8][4];
#pragma unroll
        for (int nf = 0; nf < 8; nf++)
#pragma unroll
            for (int q = 0; q < 4; q++) sacc[nf][q] = 0.f;

#pragma unroll
        for (int ks = 0; ks < 12; ks++) {
            const uint32_t koff = ks * 32;
            uint32_t aq[4], bqh[16], bql[16];
            ldm_x4(aq, sb + SM_Q + aoffQ + koff);
#pragma unroll
            for (int np = 0; np < 4; np++) {
                ldm_x4(&bqh[np * 4], sb + SM_KH + boffK + np * 16 * AQ_STRIDE + koff);
                ldm_x4(&bql[np * 4], sb + SM_KL + boffK + np * 16 * AQ_STRIDE + koff);
            }
#pragma unroll
            for (int nf = 0; nf < 8; nf++) {
                mma16816h(sacc[nf], aq, &bqh[(nf >> 1) * 4 + (nf & 1) * 2]);
                mma16816h(sacc[nf], aq, &bql[(nf >> 1) * 4 + (nf & 1) * 2]);
            }
        }

        // ---- bias + mask + online softmax ----
        const int row0 = row0c;
        const int row1 = row1c;
        const bool diag = (k0 + 63 > q0 + wrow);
        float pmax0 = -3.0e38f, pmax1 = -3.0e38f;
#pragma unroll
        for (int nf = 0; nf < 8; nf++) {
            const int col = k0 + nf * 8 + 2 * tq;
            float s0 = fmaf(sacc[nf][0], 0.125f, rr0[nf].x);
            float s1 = fmaf(sacc[nf][1], 0.125f, rr0[nf].y);
            float s2 = fmaf(sacc[nf][2], 0.125f, rr1[nf].x);
            float s3 = fmaf(sacc[nf][3], 0.125f, rr1[nf].y);
            if (diag) {
                if (col     > row0) s0 = -3.0e38f;
                if (col + 1 > row0) s1 = -3.0e38f;
                if (col     > row1) s2 = -3.0e38f;
                if (col + 1 > row1) s3 = -3.0e38f;
            }
            sacc[nf][0] = s0; sacc[nf][1] = s1; sacc[nf][2] = s2; sacc[nf][3] = s3;
            pmax0 = fmaxf(pmax0, fmaxf(s0, s1));
            pmax1 = fmaxf(pmax1, fmaxf(s2, s3));
        }
        {
            __half2 hm = __floats2half2_rn(pmax0, pmax1);
#pragma unroll
            for (int d = 1; d < 4; d <<= 1) {
                uint32_t u = *(uint32_t*)&hm;
                uint32_t v = __shfl_xor_sync(0xffffffffu, u, d);
                hm = __hmax2(hm, *(__half2*)&v);
            }
            float2 fm = __half22float2(hm);
            pmax0 = fm.x;  pmax1 = fm.y;
        }
        const float nm0 = fmaxf(m_i[0], pmax0);
        const float nm1 = fmaxf(m_i[1], pmax1);
        const float al0 = __expf(m_i[0] - nm0);
        const float al1 = __expf(m_i[1] - nm1);
        float rs0 = 0.f, rs1 = 0.f;
#pragma unroll
        for (int nf = 0; nf < 8; nf++) {
            sacc[nf][0] = __expf(sacc[nf][0] - nm0);
            sacc[nf][1] = __expf(sacc[nf][1] - nm0);
            sacc[nf][2] = __expf(sacc[nf][2] - nm1);
            sacc[nf][3] = __expf(sacc[nf][3] - nm1);
            rs0 += sacc[nf][0] + sacc[nf][1];
            rs1 += sacc[nf][2] + sacc[nf][3];
        }
#pragma unroll
        for (int d = 1; d < 4; d <<= 1) {
            rs0 += __shfl_xor_sync(0xffffffffu, rs0, d);
            rs1 += __shfl_xor_sync(0xffffffffu, rs1, d);
        }
        l_i[0] = l_i[0] * al0 + rs0;  m_i[0] = nm0;
        l_i[1] = l_i[1] * al1 + rs1;  m_i[1] = nm1;
#pragma unroll
        for (int nf = 0; nf < 8; nf++) {
            oacc[nf][0] *= al0; oacc[nf][1] *= al0;
            oacc[nf][2] *= al1; oacc[nf][3] *= al1;
        }

        // ---- O += P*(Vh + Vl) over k=64, fp16 P ----
#pragma unroll
        for (int ks = 0; ks < 4; ks++) {
            uint32_t af[4];
            af[0] = pack_h2(sacc[2*ks][0],   sacc[2*ks][1]);
            af[1] = pack_h2(sacc[2*ks][2],   sacc[2*ks][3]);
            af[2] = pack_h2(sacc[2*ks+1][0], sacc[2*ks+1][1]);
            af[3] = pack_h2(sacc[2*ks+1][2], sacc[2*ks+1][3]);
            uint32_t bvh[16], bvl[16];
            const uint32_t koff = ks * 32;
#pragma unroll
            for (int np = 0; np < 4; np++) {
                ldm_x4(&bvh[np * 4], sb + SM_VH + boffV + np * 16 * AV_STRIDE + koff);
                ldm_x4(&bvl[np * 4], sb + SM_VL + boffV + np * 16 * AV_STRIDE + koff);
            }
#pragma unroll
            for (int nf = 0; nf < 8; nf++) {
                mma16816h(oacc[nf], af, &bvh[(nf >> 1) * 4 + (nf & 1) * 2]);
                mma16816h(oacc[nf], af, &bvl[(nf >> 1) * 4 + (nf & 1) * 2]);
            }
        }
    }

    // ---- epilogue: normalize, fp16 write to [m][HID] ----
    const int b = bh >> 4, h = bh & 15;
    const float inv0 = 1.0f / l_i[0];
    const float inv1 = 1.0f / l_i[1];
    const size_t m0g = (size_t)(b * L_ + q0 + wrow + g) * HID_;
    const size_t m1g = m0g + 8 * HID_;
#pragma unroll
    for (int nf = 0; nf < 8; nf++) {
        const int col = h * 64 + nf * 8 + 2 * tq;
        __half2 o0 = __floats2half2_rn(oacc[nf][0] * inv0, oacc[nf][1] * inv0);
        __half2 o1 = __floats2half2_rn(oacc[nf][2] * inv1, oacc[nf][3] * inv1);
        *(__half2*)(Of + m0g + col) = o0;
        *(__half2*)(Of + m1g + col) = o1;
    }
}

// ---------------- launcher ----------------
extern "C" void kernel_launch(void* const* d_in, const int* in_sizes, int n_in,
                              void* d_out, int out_size)
{
    const float* rel = (const float*)d_in[5];
    float* out = (float*)d_out;

    __half *xf, *wfh, *wfl, *qf, *k16h, *k16l, *v16h, *v16l;
    cudaGetSymbolAddress((void**)&xf, g_xf);
    cudaGetSymbolAddress((void**)&wfh, g_wfh);
    cudaGetSymbolAddress((void**)&wfl, g_wfl);
    cudaGetSymbolAddress((void**)&qf, g_qf);
    cudaGetSymbolAddress((void**)&k16h, g_k16h);
    cudaGetSymbolAddress((void**)&k16l, g_k16l);
    cudaGetSymbolAddress((void**)&v16h, g_v16h);
    cudaGetSymbolAddress((void**)&v16l, g_v16l);

    cudaFuncSetAttribute(gemm_batch, cudaFuncAttributeMaxDynamicSharedMemorySize, GEMM_SMEM);
    cudaFuncSetAttribute(gemm_out, cudaFuncAttributeMaxDynamicSharedMemorySize, GEMM_SMEM);
    cudaFuncSetAttribute(attn_mma, cudaFuncAttributeMaxDynamicSharedMemorySize, ATT_SMEM);

    const int n4 = (int)(XN / 4);

    SplitSrc ss;
    ss.p[0] = (const float*)d_in[0];
    ss.p[1] = (const float*)d_in[1];
    ss.p[2] = (const float*)d_in[2];
    ss.p[3] = (const float*)d_in[3];
    split_f16<<<dim3((n4 + 255) / 256, 4), 256>>>(ss, xf, n4);

    WSrc ws;
    ws.p[0] = (const float*)d_in[6];   ws.p[1] = (const float*)d_in[8];
    ws.p[2] = (const float*)d_in[10];  ws.p[3] = (const float*)d_in[12];
    ws.p[4] = (const float*)d_in[14];  ws.p[5] = (const float*)d_in[16];
    ws.p[6] = (const float*)d_in[18];  ws.p[7] = (const float*)d_in[20];
    splitT_h<<<dim3(32, 32, 8), dim3(32, 8)>>>(ws, wfh, wfl);

    GemmB gb;
    const int ain[7]  = {0, 1, 2, 0, 1, 2, 3};
    const int wsl[7]  = {0, 3, 5, 1, 4, 6, 2};
    const int bidx[7] = {7, 13, 17, 9, 15, 19, 11};
    for (int z = 0; z < 7; z++) {
        gb.A[z]  = xf + (size_t)ain[z] * XN;
        gb.Bh[z] = wfh + (size_t)wsl[z] * WN;
        gb.Bl[z] = wfl + (size_t)wsl[z] * WN;
        gb.bias[z] = (const float*)d_in[bidx[z]];
    }
    gb.Oh[0] = qf;   gb.Ol[0] = qf;    gb.mode[0] = 0; gb.part[0] = 0;
    gb.Oh[1] = qf;   gb.Ol[1] = qf;    gb.mode[1] = 0; gb.part[1] = 1;
    gb.Oh[2] = qf;   gb.Ol[2] = qf;    gb.mode[2] = 0; gb.part[2] = 2;
    gb.Oh[3] = k16h; gb.Ol[3] = k16l;  gb.mode[3] = 1; gb.part[3] = 0;
    gb.Oh[4] = k16h; gb.Ol[4] = k16l;  gb.mode[4] = 1; gb.part[4] = 1;
    gb.Oh[5] = k16h; gb.Ol[5] = k16l;  gb.mode[5] = 1; gb.part[5] = 2;
    gb.Oh[6] = v16h; gb.Ol[6] = v16l;  gb.mode[6] = 2; gb.part[6] = 0;
    gemm_batch<<<dim3(8, 64, 7), 256, GEMM_SMEM>>>(gb);

    attn_mma<<<dim3(4, 256), 256, ATT_SMEM>>>(rel, qf, k16h, k16l, v16h, v16l,
                                              xf + 4 * XN);

    gemm_out<<<dim3(8, 64), 256, GEMM_SMEM>>>(xf + 4 * XN,
                                              wfh + 7 * WN, wfl + 7 * WN,
                                              (const float*)d_in[21], out);
}

// round 11
// speedup vs baseline: 1.6163x; 1.0233x over previous
#include <cuda_runtime.h>
#include <cuda_bf16.h>
#include <cuda_fp16.h>
#include <cstdint>

#define B_    16
#define L_    512
#define HID_  1024
#define NH_   16
#define HD_   64
#define M_TOT (B_*L_)      // 8192
#define DCAT  192
#define XN    ((size_t)M_TOT*HID_)
#define WN    ((size_t)HID_*HID_)

// ---------------- scratch (static device arrays) ----------------
__device__ __half g_xf[5ULL*XN];            // fp16 activations: 4 inputs + attn-out
__device__ __half g_wfh[8ULL*WN];           // W^T fp16 hi
__device__ __half g_wfl[8ULL*WN];           // W^T fp16 lo (residual)
__device__ __half g_qf [(size_t)B_*NH_*L_*DCAT];   // Q single fp16
__device__ __half g_k16h[(size_t)B_*NH_*L_*DCAT];  // K fp16 hi
__device__ __half g_k16l[(size_t)B_*NH_*L_*DCAT];  // K fp16 lo
__device__ __half g_v16h[(size_t)B_*NH_*HD_*L_];   // Vt fp16 hi
__device__ __half g_v16l[(size_t)B_*NH_*HD_*L_];   // Vt fp16 lo

// ---------------- PTX helpers (baseline ISA only) ----------------
__device__ __forceinline__ uint32_t smem_u32(const void* p) {
    uint32_t a;
    asm("{ .reg .u64 t; cvta.to.shared.u64 t, %1; cvt.u32.u64 %0, t; }" : "=r"(a) : "l"(p));
    return a;
}
__device__ __forceinline__ void cp16(uint32_t dst, const void* src) {
    asm volatile("cp.async.cg.shared.global [%0], [%1], 16;" :: "r"(dst), "l"(src));
}
__device__ __forceinline__ void ldm_x4(uint32_t* r, uint32_t addr) {
    asm volatile("ldmatrix.sync.aligned.m8n8.x4.shared.b16 {%0,%1,%2,%3}, [%4];"
                 : "=r"(r[0]), "=r"(r[1]), "=r"(r[2]), "=r"(r[3]) : "r"(addr));
}
// fp16 mma
__device__ __forceinline__ void mma16816h(float* d, const uint32_t* a, const uint32_t* b) {
    asm volatile(
        "mma.sync.aligned.m16n8k16.row.col.f32.f16.f16.f32 "
        "{%0,%1,%2,%3}, {%4,%5,%6,%7}, {%8,%9}, {%0,%1,%2,%3};"
        : "+f"(d[0]), "+f"(d[1]), "+f"(d[2]), "+f"(d[3])
        : "r"(a[0]), "r"(a[1]), "r"(a[2]), "r"(a[3]), "r"(b[0]), "r"(b[1]));
}
__device__ __forceinline__ uint32_t pack_h2(float a, float b) {
    __half2 t = __floats2half2_rn(a, b);
    return *(uint32_t*)&t;
}

// ---------------- batched fp32 -> fp16 ----------------
struct SplitSrc { const float* p[4]; };
__global__ __launch_bounds__(256)
void split_f16(SplitSrc s, __half* __restrict__ dst, int n4)
{
    int i = blockIdx.x * 256 + threadIdx.x;
    if (i >= n4) return;
    int z = blockIdx.y;
    const float* src = s.p[z];
    __half* dz = dst + (size_t)z * XN;
    float4 v = ((const float4*)src)[i];
    __half2 a = __floats2half2_rn(v.x, v.y);
    __half2 b = __floats2half2_rn(v.z, v.w);
    ((__half2*)dz)[i*2]   = a;
    ((__half2*)dz)[i*2+1] = b;
}

// ---------------- batched W[k][n] -> W^T[n][k] fp16 split ----------------
struct WSrc { const float* p[8]; };
__global__ __launch_bounds__(256)
void splitT_h(WSrc s, __half* __restrict__ hiT, __half* __restrict__ loT)
{
    __shared__ float t[32][33];
    int z = blockIdx.z;
    const float* W = s.p[z];
    __half* hz = hiT + (size_t)z * WN;
    __half* lz = loT + (size_t)z * WN;
    int bx = blockIdx.x * 32, by = blockIdx.y * 32;
    int tx = threadIdx.x, ty = threadIdx.y;
#pragma unroll
    for (int j = 0; j < 4; j++)
        t[ty + 8*j][tx] = W[(size_t)(by + ty + 8*j) * HID_ + bx + tx];
    __syncthreads();
#pragma unroll
    for (int j = 0; j < 4; j++) {
        float v = t[tx][ty + 8*j];
        int n = bx + ty + 8*j, k = by + tx;
        __half h = __float2half(v);
        hz[(size_t)n * HID_ + k] = h;
        lz[(size_t)n * HID_ + k] = __float2half(v - __half2float(h));
    }
}

// ---------------- GEMM core: load A once, apply Bh+Bl; CTA 128x128, 2-stage ----------------
#define KC        64
#define NCHUNKW   16
#define ROWB      144u
#define ATILE_B   (128u*ROWB)            // 18432
#define STAGE_B   (3u*ATILE_B)           // 55296 (A + Bh + Bl)
#define GEMM_SMEM (2*STAGE_B)            // 110592  -> occ 2

__device__ __forceinline__ void gemm_load_tile(
    uint32_t sbase, int stage, int c, int m0, int n0, int tid,
    const __half* A, const __half* Bh, const __half* Bl)
{
    const int k0 = c * KC;
    const uint32_t dstA = sbase + (uint32_t)stage * STAGE_B;
#pragma unroll
    for (int i = 0; i < 12; i++) {
        int idx = i * 256 + tid;                 // 0..3071 16B segments
        int r = (idx >> 3) & 127, c16 = idx & 7;
        if (idx < 1024)
            cp16(dstA + r * ROWB + c16 * 16,
                 A + (size_t)(m0 + r) * HID_ + k0 + c16 * 8);
        else if (idx < 2048)
            cp16(dstA + ATILE_B + r * ROWB + c16 * 16,
                 Bh + (size_t)(n0 + r) * HID_ + k0 + c16 * 8);
        else
            cp16(dstA + 2 * ATILE_B + r * ROWB + c16 * 16,
                 Bl + (size_t)(n0 + r) * HID_ + k0 + c16 * 8);
    }
    asm volatile("cp.async.commit_group;");
}

__device__ __forceinline__ void gemm_core(
    uint32_t sbase, int m0, int n0, int tid, int wm, int wn, int lane,
    const __half* A, const __half* Bh, const __half* Bl,
    float acc[2][8][4])
{
    const int arow = wm * 32 + (lane & 7) + ((lane >> 3) & 1) * 8;
    const uint32_t a_l = (uint32_t)arow * ROWB + ((lane >> 4) * 16);
    const int brow = wn * 64 + (lane & 7) + ((lane >> 4) & 1) * 8;
    const uint32_t b_l = (uint32_t)brow * ROWB + (((lane >> 3) & 1) * 16);

    gemm_load_tile(sbase, 0, 0, m0, n0, tid, A, Bh, Bl);

    for (int c = 0; c < NCHUNKW; c++) {
        if (c + 1 < NCHUNKW)
            gemm_load_tile(sbase, (c + 1) & 1, c + 1, m0, n0, tid, A, Bh, Bl);
        if (c + 1 < NCHUNKW) asm volatile("cp.async.wait_group 1;" ::: "memory");
        else                 asm volatile("cp.async.wait_group 0;" ::: "memory");
        __syncthreads();

        const uint32_t sb = sbase + (uint32_t)(c & 1) * STAGE_B;
        const uint32_t aBase  = sb + a_l;
        const uint32_t bhBase = sb + ATILE_B + b_l;
        const uint32_t blBase = sb + 2 * ATILE_B + b_l;
#pragma unroll
        for (int kk = 0; kk < KC / 16; kk++) {
            const uint32_t koff = kk * 32;
            uint32_t aq[2][4];
#pragma unroll
            for (int mf = 0; mf < 2; mf++)
                ldm_x4(aq[mf], aBase + mf * 16 * ROWB + koff);
            uint32_t bqh[16], bql[16];
#pragma unroll
            for (int np = 0; np < 4; np++) {
                ldm_x4(&bqh[np * 4], bhBase + np * 16 * ROWB + koff);
                ldm_x4(&bql[np * 4], blBase + np * 16 * ROWB + koff);
            }
#pragma unroll
            for (int mf = 0; mf < 2; mf++)
#pragma unroll
                for (int nf = 0; nf < 8; nf++) {
                    mma16816h(acc[mf][nf], aq[mf], &bqh[(nf >> 1) * 4 + (nf & 1) * 2]);
                    mma16816h(acc[mf][nf], aq[mf], &bql[(nf >> 1) * 4 + (nf & 1) * 2]);
                }
        }
        __syncthreads();
    }
}

// ---------------- batched projection GEMMs (fp16 outputs for attention) ----------------
// mode 0: Q scatter [bh][l][192], single fp16
// mode 1: K scatter [bh][l][192], fp16 hi+lo
// mode 2: V transpose [bh][d][l], fp16 hi+lo
struct GemmB {
    const __half *A[7], *Bh[7], *Bl[7];
    const float* bias[7];
    __half *Oh[7], *Ol[7];
    int mode[7];
    int part[7];
};

__global__ __launch_bounds__(256, 2)
void gemm_batch(GemmB args)
{
    extern __shared__ char smem[];
    const uint32_t sbase = smem_u32(smem);
    const int z = blockIdx.z;
    const int tid = threadIdx.x;
    const int wid = tid >> 5, lane = tid & 31;
    const int m0 = blockIdx.y * 128, n0 = blockIdx.x * 128;
    const int wm = wid & 3, wn = wid >> 2;

    float acc[2][8][4];
#pragma unroll
    for (int mf = 0; mf < 2; mf++)
#pragma unroll
        for (int nf = 0; nf < 8; nf++)
#pragma unroll
            for (int q = 0; q < 4; q++) acc[mf][nf][q] = 0.f;

    gemm_core(sbase, m0, n0, tid, wm, wn, lane,
              args.A[z], args.Bh[z], args.Bl[z], acc);

    const float* bias = args.bias[z];
    __half* Oh = args.Oh[z];
    __half* Ol = args.Ol[z];
    const int mode = args.mode[z], part = args.part[z];

    const int g = lane >> 2, tq = lane & 3;
    float2 bv[8];
#pragma unroll
    for (int nf = 0; nf < 8; nf++)
        bv[nf] = *(const float2*)(bias + n0 + wn * 64 + nf * 8 + 2 * tq);

#pragma unroll
    for (int mf = 0; mf < 2; mf++) {
#pragma unroll
        for (int half = 0; half < 2; half++) {
            const int m = m0 + wm * 32 + mf * 16 + g + half * 8;
            const int bb = m >> 9, ll = m & 511;
#pragma unroll
            for (int nf = 0; nf < 8; nf++) {
                const int n = n0 + wn * 64 + nf * 8 + 2 * tq;
                const int h = n >> 6, dd = n & 63;
                float vx = acc[mf][nf][half * 2 + 0] + bv[nf].x;
                float vy = acc[mf][nf][half * 2 + 1] + bv[nf].y;
                __half hx = __float2half(vx), hy = __float2half(vy);
                if (mode == 0) {
                    size_t dst = ((((size_t)bb * NH_ + h) * L_ + ll) * DCAT)
                               + (size_t)part * 64 + dd;
                    __half2 hi2; hi2.x = hx; hi2.y = hy;
                    *(__half2*)(Oh + dst) = hi2;
                } else {
                    __half lx = __float2half(vx - __half2float(hx));
                    __half ly = __float2half(vy - __half2float(hy));
                    if (mode == 1) {
                        size_t dst = ((((size_t)bb * NH_ + h) * L_ + ll) * DCAT)
                                   + (size_t)part * 64 + dd;
                        __half2 hi2; hi2.x = hx; hi2.y = hy;
                        __half2 lo2; lo2.x = lx; lo2.y = ly;
                        *(__half2*)(Oh + dst) = hi2;
                        *(__half2*)(Ol + dst) = lo2;
                    } else {
                        size_t dst = (((size_t)bb * NH_ + h) * HD_ + dd) * L_ + ll;
                        Oh[dst] = hx;  Ol[dst] = lx;
                        Oh[dst + L_] = hy;  Ol[dst + L_] = ly;
                    }
                }
            }
        }
    }
}

// ---------------- output projection GEMM (fp32 out) ----------------
__global__ __launch_bounds__(256, 2)
void gemm_out(const __half* __restrict__ A,
              const __half* __restrict__ Bh, const __half* __restrict__ Bl,
              const float* __restrict__ bias, float* __restrict__ out)
{
    extern __shared__ char smem[];
    const uint32_t sbase = smem_u32(smem);
    const int tid = threadIdx.x;
    const int wid = tid >> 5, lane = tid & 31;
    const int m0 = blockIdx.y * 128, n0 = blockIdx.x * 128;
    const int wm = wid & 3, wn = wid >> 2;

    float acc[2][8][4];
#pragma unroll
    for (int mf = 0; mf < 2; mf++)
#pragma unroll
        for (int nf = 0; nf < 8; nf++)
#pragma unroll
            for (int q = 0; q < 4; q++) acc[mf][nf][q] = 0.f;

    gemm_core(sbase, m0, n0, tid, wm, wn, lane, A, Bh, Bl, acc);

    const int g = lane >> 2, tq = lane & 3;
    float2 bv[8];
#pragma unroll
    for (int nf = 0; nf < 8; nf++)
        bv[nf] = *(const float2*)(bias + n0 + wn * 64 + nf * 8 + 2 * tq);
#pragma unroll
    for (int mf = 0; mf < 2; mf++)
#pragma unroll
        for (int half = 0; half < 2; half++) {
            const int m = m0 + wm * 32 + mf * 16 + g + half * 8;
#pragma unroll
            for (int nf = 0; nf < 8; nf++) {
                const int n = n0 + wn * 64 + nf * 8 + 2 * tq;
                float2 v;
                v.x = acc[mf][nf][half * 2 + 0] + bv[nf].x;
                v.y = acc[mf][nf][half * 2 + 1] + bv[nf].y;
                *(float2*)(out + (size_t)m * HID_ + n) = v;
            }
        }
}

// ---------------- flash attention: fp16 2-product, 128-thread CTA, occ 2 ----------------
// CTA: 64 q-rows, 4 warps x 16 rows, k tiles of 64.
// smem: Q 64x400 = 25600 | KH 25600 | KL 25600 | VH 9216 | VL 9216 = 95232 -> 2 CTA/SM
#define AQ_STRIDE 400u
#define AV_STRIDE 144u
#define SM_Q  0u
#define SM_KH 25600u
#define SM_KL 51200u
#define SM_VH 76800u
#define SM_VL 86016u
#define ATT_SMEM 95232

__global__ __launch_bounds__(128, 2)
void attn_mma(const float* __restrict__ rel,
              const __half* __restrict__ Qf,
              const __half* __restrict__ Kh, const __half* __restrict__ Kl,
              const __half* __restrict__ Vth, const __half* __restrict__ Vtl,
              __half* __restrict__ Of)
{
    extern __shared__ char smc[];
    const uint32_t sb = smem_u32(smc);
    const int qt = (int)gridDim.x - 1 - (int)blockIdx.x;   // heavy CTAs first
    const int bh = blockIdx.y;
    const int q0 = qt * 64;
    const int tid = threadIdx.x, wid = tid >> 5, lane = tid & 31;
    const int g = lane >> 2, tq = lane & 3;
    const int wrow = wid * 16;

    const __half* qf_g = Qf  + (size_t)bh * L_ * DCAT;
    const __half* kh_g = Kh  + (size_t)bh * L_ * DCAT;
    const __half* kl_g = Kl  + (size_t)bh * L_ * DCAT;
    const __half* vh_g = Vth + (size_t)bh * HD_ * L_;
    const __half* vl_g = Vtl + (size_t)bh * HD_ * L_;
    const float* relg = rel + (size_t)bh * L_ * L_;

    // Q tile load: 64 rows x 24 16B-segs = 1536 segs over 128 threads
#pragma unroll
    for (int i = 0; i < 12; i++) {
        int idx = i * 128 + tid;
        int r = idx / 24, s2 = idx % 24;
        cp16(sb + SM_Q + r * AQ_STRIDE + s2 * 16,
             qf_g + (size_t)(q0 + r) * DCAT + s2 * 8);
    }
    asm volatile("cp.async.commit_group;");

    float m_i[2] = {-3.0e38f, -3.0e38f};
    float l_i[2] = {0.f, 0.f};
    float oacc[8][4];
#pragma unroll
    for (int nf = 0; nf < 8; nf++)
#pragma unroll
        for (int q = 0; q < 4; q++) oacc[nf][q] = 0.f;

    const uint32_t aoffQ = (uint32_t)(wrow + (lane & 7) + ((lane >> 3) & 1) * 8) * AQ_STRIDE
                         + (lane >> 4) * 16;
    const uint32_t boffK = (uint32_t)((lane & 7) + ((lane >> 4) & 1) * 8) * AQ_STRIDE
                         + ((lane >> 3) & 1) * 16;
    const uint32_t boffV = (uint32_t)((lane & 7) + ((lane >> 4) & 1) * 8) * AV_STRIDE
                         + ((lane >> 3) & 1) * 16;

    const int row0c = q0 + wrow + g;
    const int row1c = row0c + 8;

    const int ntiles = qt + 1;
    for (int kt = 0; kt < ntiles; kt++) {
        const int k0 = kt * 64;
        __syncthreads();
        // K hi+lo: 64x24 segs each (3072); Vt hi+lo: 64x8 segs each (1024) = 4096 segs
#pragma unroll
        for (int i = 0; i < 32; i++) {
            int idx = i * 128 + tid;
            if (idx < 3072) {
                int mat = idx >= 1536;
                int j = idx - mat * 1536;
                int r = j / 24, s2 = j % 24;
                cp16(sb + (mat ? SM_KL : SM_KH) + r * AQ_STRIDE + s2 * 16,
                     (mat ? kl_g : kh_g) + (size_t)(k0 + r) * DCAT + s2 * 8);
            } else {
                int j = idx - 3072;
                int mat = j >= 512;
                j -= mat * 512;
                int d = j >> 3, s2 = j & 7;
                cp16(sb + (mat ? SM_VL : SM_VH) + d * AV_STRIDE + s2 * 16,
                     (mat ? vl_g : vh_g) + (size_t)d * L_ + k0 + s2 * 8);
            }
        }
        asm volatile("cp.async.commit_group;");
        asm volatile("cp.async.wait_group 0;" ::: "memory");
        __syncthreads();

        if (k0 > q0 + wrow + 15) continue;

        // prefetch relative_time bias (hidden under QK mma)
        float2 rr0[8], rr1[8];
#pragma unroll
        for (int nf = 0; nf < 8; nf++) {
            const int col = k0 + nf * 8 + 2 * tq;
            rr0[nf] = *(const float2*)(relg + (size_t)row0c * L_ + col);
            rr1[nf] = *(const float2*)(relg + (size_t)row1c * L_ + col);
        }

        // ---- S = Q*(Kh + Kl) over k=192, fp16 ----
        float sacc[8][4];
#pragma unroll
        for (int nf = 0; nf < 8; nf++)
#pragma unroll
            for (int q = 0; q < 4; q++) sacc[nf][q] = 0.f;

#pragma unroll
        for (int ks = 0; ks < 12; ks++) {
            const uint32_t koff = ks * 32;
            uint32_t aq[4], bqh[16], bql[16];
            ldm_x4(aq, sb + SM_Q + aoffQ + koff);
#pragma unroll
            for (int np = 0; np < 4; np++) {
                ldm_x4(&bqh[np * 4], sb + SM_KH + boffK + np * 16 * AQ_STRIDE + koff);
                ldm_x4(&bql[np * 4], sb + SM_KL + boffK + np * 16 * AQ_STRIDE + koff);
            }
#pragma unroll
            for (int nf = 0; nf < 8; nf++) {
                mma16816h(sacc[nf], aq, &bqh[(nf >> 1) * 4 + (nf & 1) * 2]);
                mma16816h(sacc[nf], aq, &bql[(nf >> 1) * 4 + (nf & 1) * 2]);
            }
        }

        // ---- bias + mask + online softmax ----
        const int row0 = row0c;
        const int row1 = row1c;
        const bool diag = (k0 + 63 > q0 + wrow);
        float pmax0 = -3.0e38f, pmax1 = -3.0e38f;
#pragma unroll
        for (int nf = 0; nf < 8; nf++) {
            const int col = k0 + nf * 8 + 2 * tq;
            float s0 = fmaf(sacc[nf][0], 0.125f, rr0[nf].x);
            float s1 = fmaf(sacc[nf][1], 0.125f, rr0[nf].y);
            float s2 = fmaf(sacc[nf][2], 0.125f, rr1[nf].x);
            float s3 = fmaf(sacc[nf][3], 0.125f, rr1[nf].y);
            if (diag) {
                if (col     > row0) s0 = -3.0e38f;
                if (col + 1 > row0) s1 = -3.0e38f;
                if (col     > row1) s2 = -3.0e38f;
                if (col + 1 > row1) s3 = -3.0e38f;
            }
            sacc[nf][0] = s0; sacc[nf][1] = s1; sacc[nf][2] = s2; sacc[nf][3] = s3;
            pmax0 = fmaxf(pmax0, fmaxf(s0, s1));
            pmax1 = fmaxf(pmax1, fmaxf(s2, s3));
        }
        {
            __half2 hm = __floats2half2_rn(pmax0, pmax1);
#pragma unroll
            for (int d = 1; d < 4; d <<= 1) {
                uint32_t u = *(uint32_t*)&hm;
                uint32_t v = __shfl_xor_sync(0xffffffffu, u, d);
                hm = __hmax2(hm, *(__half2*)&v);
            }
            float2 fm = __half22float2(hm);
            pmax0 = fm.x;  pmax1 = fm.y;
        }
        const float nm0 = fmaxf(m_i[0], pmax0);
        const float nm1 = fmaxf(m_i[1], pmax1);
        const float al0 = __expf(m_i[0] - nm0);
        const float al1 = __expf(m_i[1] - nm1);
        float rs0 = 0.f, rs1 = 0.f;
#pragma unroll
        for (int nf = 0; nf < 8; nf++) {
            sacc[nf][0] = __expf(sacc[nf][0] - nm0);
            sacc[nf][1] = __expf(sacc[nf][1] - nm0);
            sacc[nf][2] = __expf(sacc[nf][2] - nm1);
            sacc[nf][3] = __expf(sacc[nf][3] - nm1);
            rs0 += sacc[nf][0] + sacc[nf][1];
            rs1 += sacc[nf][2] + sacc[nf][3];
        }
#pragma unroll
        for (int d = 1; d < 4; d <<= 1) {
            rs0 += __shfl_xor_sync(0xffffffffu, rs0, d);
            rs1 += __shfl_xor_sync(0xffffffffu, rs1, d);
        }
        l_i[0] = l_i[0] * al0 + rs0;  m_i[0] = nm0;
        l_i[1] = l_i[1] * al1 + rs1;  m_i[1] = nm1;
#pragma unroll
        for (int nf = 0; nf < 8; nf++) {
            oacc[nf][0] *= al0; oacc[nf][1] *= al0;
            oacc[nf][2] *= al1; oacc[nf][3] *= al1;
        }

        // ---- O += P*(Vh + Vl) over k=64, fp16 P ----
#pragma unroll
        for (int ks = 0; ks < 4; ks++) {
            uint32_t af[4];
            af[0] = pack_h2(sacc[2*ks][0],   sacc[2*ks][1]);
            af[1] = pack_h2(sacc[2*ks][2],   sacc[2*ks][3]);
            af[2] = pack_h2(sacc[2*ks+1][0], sacc[2*ks+1][1]);
            af[3] = pack_h2(sacc[2*ks+1][2], sacc[2*ks+1][3]);
            uint32_t bvh[16], bvl[16];
            const uint32_t koff = ks * 32;
#pragma unroll
            for (int np = 0; np < 4; np++) {
                ldm_x4(&bvh[np * 4], sb + SM_VH + boffV + np * 16 * AV_STRIDE + koff);
                ldm_x4(&bvl[np * 4], sb + SM_VL + boffV + np * 16 * AV_STRIDE + koff);
            }
#pragma unroll
            for (int nf = 0; nf < 8; nf++) {
                mma16816h(oacc[nf], af, &bvh[(nf >> 1) * 4 + (nf & 1) * 2]);
                mma16816h(oacc[nf], af, &bvl[(nf >> 1) * 4 + (nf & 1) * 2]);
            }
        }
    }

    // ---- epilogue: normalize, fp16 write to [m][HID] ----
    const int b = bh >> 4, h = bh & 15;
    const float inv0 = 1.0f / l_i[0];
    const float inv1 = 1.0f / l_i[1];
    const size_t m0g = (size_t)(b * L_ + q0 + wrow + g) * HID_;
    const size_t m1g = m0g + 8 * HID_;
#pragma unroll
    for (int nf = 0; nf < 8; nf++) {
        const int col = h * 64 + nf * 8 + 2 * tq;
        __half2 o0 = __floats2half2_rn(oacc[nf][0] * inv0, oacc[nf][1] * inv0);
        __half2 o1 = __floats2half2_rn(oacc[nf][2] * inv1, oacc[nf][3] * inv1);
        *(__half2*)(Of + m0g + col) = o0;
        *(__half2*)(Of + m1g + col) = o1;
    }
}

// ---------------- launcher ----------------
extern "C" void kernel_launch(void* const* d_in, const int* in_sizes, int n_in,
                              void* d_out, int out_size)
{
    const float* rel = (const float*)d_in[5];
    float* out = (float*)d_out;

    __half *xf, *wfh, *wfl, *qf, *k16h, *k16l, *v16h, *v16l;
    cudaGetSymbolAddress((void**)&xf, g_xf);
    cudaGetSymbolAddress((void**)&wfh, g_wfh);
    cudaGetSymbolAddress((void**)&wfl, g_wfl);
    cudaGetSymbolAddress((void**)&qf, g_qf);
    cudaGetSymbolAddress((void**)&k16h, g_k16h);
    cudaGetSymbolAddress((void**)&k16l, g_k16l);
    cudaGetSymbolAddress((void**)&v16h, g_v16h);
    cudaGetSymbolAddress((void**)&v16l, g_v16l);

    cudaFuncSetAttribute(gemm_batch, cudaFuncAttributeMaxDynamicSharedMemorySize, GEMM_SMEM);
    cudaFuncSetAttribute(gemm_out, cudaFuncAttributeMaxDynamicSharedMemorySize, GEMM_SMEM);
    cudaFuncSetAttribute(attn_mma, cudaFuncAttributeMaxDynamicSharedMemorySize, ATT_SMEM);

    const int n4 = (int)(XN / 4);

    SplitSrc ss;
    ss.p[0] = (const float*)d_in[0];
    ss.p[1] = (const float*)d_in[1];
    ss.p[2] = (const float*)d_in[2];
    ss.p[3] = (const float*)d_in[3];
    split_f16<<<dim3((n4 + 255) / 256, 4), 256>>>(ss, xf, n4);

    WSrc ws;
    ws.p[0] = (const float*)d_in[6];   ws.p[1] = (const float*)d_in[8];
    ws.p[2] = (const float*)d_in[10];  ws.p[3] = (const float*)d_in[12];
    ws.p[4] = (const float*)d_in[14];  ws.p[5] = (const float*)d_in[16];
    ws.p[6] = (const float*)d_in[18];  ws.p[7] = (const float*)d_in[20];
    splitT_h<<<dim3(32, 32, 8), dim3(32, 8)>>>(ws, wfh, wfl);

    GemmB gb;
    const int ain[7]  = {0, 1, 2, 0, 1, 2, 3};
    const int wsl[7]  = {0, 3, 5, 1, 4, 6, 2};
    const int bidx[7] = {7, 13, 17, 9, 15, 19, 11};
    for (int z = 0; z < 7; z++) {
        gb.A[z]  = xf + (size_t)ain[z] * XN;
        gb.Bh[z] = wfh + (size_t)wsl[z] * WN;
        gb.Bl[z] = wfl + (size_t)wsl[z] * WN;
        gb.bias[z] = (const float*)d_in[bidx[z]];
    }
    gb.Oh[0] = qf;   gb.Ol[0] = qf;    gb.mode[0] = 0; gb.part[0] = 0;
    gb.Oh[1] = qf;   gb.Ol[1] = qf;    gb.mode[1] = 0; gb.part[1] = 1;
    gb.Oh[2] = qf;   gb.Ol[2] = qf;    gb.mode[2] = 0; gb.part[2] = 2;
    gb.Oh[3] = k16h; gb.Ol[3] = k16l;  gb.mode[3] = 1; gb.part[3] = 0;
    gb.Oh[4] = k16h; gb.Ol[4] = k16l;  gb.mode[4] = 1; gb.part[4] = 1;
    gb.Oh[5] = k16h; gb.Ol[5] = k16l;  gb.mode[5] = 1; gb.part[5] = 2;
    gb.Oh[6] = v16h; gb.Ol[6] = v16l;  gb.mode[6] = 2; gb.part[6] = 0;
    gemm_batch<<<dim3(8, 64, 7), 256, GEMM_SMEM>>>(gb);

    attn_mma<<<dim3(8, 256), 128, ATT_SMEM>>>(rel, qf, k16h, k16l, v16h, v16l,
                                              xf + 4 * XN);

    gemm_out<<<dim3(8, 64), 256, GEMM_SMEM>>>(xf + 4 * XN,
                                              wfh + 7 * WN, wfl + 7 * WN,
                                              (const float*)d_in[21], out);
}

// round 12
// speedup vs baseline: 1.7966x; 1.1115x over previous
#include <cuda_runtime.h>
#include <cuda_bf16.h>
#include <cuda_fp16.h>
#include <cstdint>

#define B_    16
#define L_    512
#define HID_  1024
#define NH_   16
#define HD_   64
#define M_TOT (B_*L_)      // 8192
#define DCAT  192
#define XN    ((size_t)M_TOT*HID_)
#define WN    ((size_t)HID_*HID_)

// ---------------- scratch (static device arrays) ----------------
__device__ __half g_xf[5ULL*XN];            // fp16 activations: 4 inputs + attn-out
__device__ __half g_wfh[8ULL*WN];           // W^T fp16 hi
__device__ __half g_wfl[8ULL*WN];           // W^T fp16 lo (residual)
__device__ __half g_qf [(size_t)B_*NH_*L_*DCAT];   // Q single fp16
__device__ __half g_k16h[(size_t)B_*NH_*L_*DCAT];  // K fp16 hi
__device__ __half g_k16l[(size_t)B_*NH_*L_*DCAT];  // K fp16 lo
__device__ __half g_v16h[(size_t)B_*NH_*HD_*L_];   // Vt fp16 hi
__device__ __half g_v16l[(size_t)B_*NH_*HD_*L_];   // Vt fp16 lo

// ---------------- PTX helpers (baseline ISA only) ----------------
__device__ __forceinline__ uint32_t smem_u32(const void* p) {
    uint32_t a;
    asm("{ .reg .u64 t; cvta.to.shared.u64 t, %1; cvt.u32.u64 %0, t; }" : "=r"(a) : "l"(p));
    return a;
}
__device__ __forceinline__ void cp16(uint32_t dst, const void* src) {
    asm volatile("cp.async.cg.shared.global [%0], [%1], 16;" :: "r"(dst), "l"(src));
}
__device__ __forceinline__ void ldm_x4(uint32_t* r, uint32_t addr) {
    asm volatile("ldmatrix.sync.aligned.m8n8.x4.shared.b16 {%0,%1,%2,%3}, [%4];"
                 : "=r"(r[0]), "=r"(r[1]), "=r"(r[2]), "=r"(r[3]) : "r"(addr));
}
// fp16 mma
__device__ __forceinline__ void mma16816h(float* d, const uint32_t* a, const uint32_t* b) {
    asm volatile(
        "mma.sync.aligned.m16n8k16.row.col.f32.f16.f16.f32 "
        "{%0,%1,%2,%3}, {%4,%5,%6,%7}, {%8,%9}, {%0,%1,%2,%3};"
        : "+f"(d[0]), "+f"(d[1]), "+f"(d[2]), "+f"(d[3])
        : "r"(a[0]), "r"(a[1]), "r"(a[2]), "r"(a[3]), "r"(b[0]), "r"(b[1]));
}
__device__ __forceinline__ uint32_t pack_h2(float a, float b) {
    __half2 t = __floats2half2_rn(a, b);
    return *(uint32_t*)&t;
}

// ---------------- batched fp32 -> fp16 ----------------
struct SplitSrc { const float* p[4]; };
__global__ __launch_bounds__(256)
void split_f16(SplitSrc s, __half* __restrict__ dst, int n4)
{
    int i = blockIdx.x * 256 + threadIdx.x;
    if (i >= n4) return;
    int z = blockIdx.y;
    const float* src = s.p[z];
    __half* dz = dst + (size_t)z * XN;
    float4 v = ((const float4*)src)[i];
    __half2 a = __floats2half2_rn(v.x, v.y);
    __half2 b = __floats2half2_rn(v.z, v.w);
    ((__half2*)dz)[i*2]   = a;
    ((__half2*)dz)[i*2+1] = b;
}

// ---------------- batched W[k][n] -> W^T[n][k] fp16 split ----------------
struct WSrc { const float* p[8]; };
__global__ __launch_bounds__(256)
void splitT_h(WSrc s, __half* __restrict__ hiT, __half* __restrict__ loT)
{
    __shared__ float t[32][33];
    int z = blockIdx.z;
    const float* W = s.p[z];
    __half* hz = hiT + (size_t)z * WN;
    __half* lz = loT + (size_t)z * WN;
    int bx = blockIdx.x * 32, by = blockIdx.y * 32;
    int tx = threadIdx.x, ty = threadIdx.y;
#pragma unroll
    for (int j = 0; j < 4; j++)
        t[ty + 8*j][tx] = W[(size_t)(by + ty + 8*j) * HID_ + bx + tx];
    __syncthreads();
#pragma unroll
    for (int j = 0; j < 4; j++) {
        float v = t[tx][ty + 8*j];
        int n = bx + ty + 8*j, k = by + tx;
        __half h = __float2half(v);
        hz[(size_t)n * HID_ + k] = h;
        lz[(size_t)n * HID_ + k] = __float2half(v - __half2float(h));
    }
}

// ---------------- GEMM core: load A once, apply Bh (+Bl); CTA 128x128, 2-stage ----------------
#define KC        64
#define NCHUNKW   16
#define ROWB      144u
#define ATILE_B   (128u*ROWB)            // 18432
#define STAGE_B   (3u*ATILE_B)           // 55296 (A + Bh + Bl)
#define GEMM_SMEM (2*STAGE_B)            // 110592  -> occ 2

__device__ __forceinline__ void gemm_load_tile(
    uint32_t sbase, int stage, int c, int m0, int n0, int tid, int nprod,
    const __half* A, const __half* Bh, const __half* Bl)
{
    const int k0 = c * KC;
    const uint32_t dstA = sbase + (uint32_t)stage * STAGE_B;
#pragma unroll
    for (int i = 0; i < 8; i++) {
        int idx = i * 256 + tid;                 // 0..2047
        int r = (idx >> 3) & 127, c16 = idx & 7;
        if (idx < 1024)
            cp16(dstA + r * ROWB + c16 * 16,
                 A + (size_t)(m0 + r) * HID_ + k0 + c16 * 8);
        else
            cp16(dstA + ATILE_B + r * ROWB + c16 * 16,
                 Bh + (size_t)(n0 + r) * HID_ + k0 + c16 * 8);
    }
    if (nprod == 2) {
#pragma unroll
        for (int i = 0; i < 4; i++) {
            int idx = i * 256 + tid;             // 0..1023
            int r = idx >> 3, c16 = idx & 7;
            cp16(dstA + 2 * ATILE_B + r * ROWB + c16 * 16,
                 Bl + (size_t)(n0 + r) * HID_ + k0 + c16 * 8);
        }
    }
    asm volatile("cp.async.commit_group;");
}

__device__ __forceinline__ void gemm_core(
    uint32_t sbase, int m0, int n0, int tid, int wm, int wn, int lane, int nprod,
    const __half* A, const __half* Bh, const __half* Bl,
    float acc[2][8][4])
{
    const int arow = wm * 32 + (lane & 7) + ((lane >> 3) & 1) * 8;
    const uint32_t a_l = (uint32_t)arow * ROWB + ((lane >> 4) * 16);
    const int brow = wn * 64 + (lane & 7) + ((lane >> 4) & 1) * 8;
    const uint32_t b_l = (uint32_t)brow * ROWB + (((lane >> 3) & 1) * 16);

    gemm_load_tile(sbase, 0, 0, m0, n0, tid, nprod, A, Bh, Bl);

    for (int c = 0; c < NCHUNKW; c++) {
        if (c + 1 < NCHUNKW)
            gemm_load_tile(sbase, (c + 1) & 1, c + 1, m0, n0, tid, nprod, A, Bh, Bl);
        if (c + 1 < NCHUNKW) asm volatile("cp.async.wait_group 1;" ::: "memory");
        else                 asm volatile("cp.async.wait_group 0;" ::: "memory");
        __syncthreads();

        const uint32_t sb = sbase + (uint32_t)(c & 1) * STAGE_B;
        const uint32_t aBase  = sb + a_l;
        const uint32_t bhBase = sb + ATILE_B + b_l;
        const uint32_t blBase = sb + 2 * ATILE_B + b_l;
#pragma unroll
        for (int kk = 0; kk < KC / 16; kk++) {
            const uint32_t koff = kk * 32;
            uint32_t aq[2][4];
#pragma unroll
            for (int mf = 0; mf < 2; mf++)
                ldm_x4(aq[mf], aBase + mf * 16 * ROWB + koff);
            uint32_t bqh[16];
#pragma unroll
            for (int np = 0; np < 4; np++)
                ldm_x4(&bqh[np * 4], bhBase + np * 16 * ROWB + koff);
#pragma unroll
            for (int mf = 0; mf < 2; mf++)
#pragma unroll
                for (int nf = 0; nf < 8; nf++)
                    mma16816h(acc[mf][nf], aq[mf], &bqh[(nf >> 1) * 4 + (nf & 1) * 2]);
            if (nprod == 2) {
                uint32_t bql[16];
#pragma unroll
                for (int np = 0; np < 4; np++)
                    ldm_x4(&bql[np * 4], blBase + np * 16 * ROWB + koff);
#pragma unroll
                for (int mf = 0; mf < 2; mf++)
#pragma unroll
                    for (int nf = 0; nf < 8; nf++)
                        mma16816h(acc[mf][nf], aq[mf], &bql[(nf >> 1) * 4 + (nf & 1) * 2]);
            }
        }
        __syncthreads();
    }
}

// ---------------- batched projection GEMMs (fp16 outputs for attention) ----------------
// mode 0: Q scatter [bh][l][192], single fp16  (nprod=1: X*Wh only)
// mode 1: K scatter [bh][l][192], fp16 hi+lo   (nprod=2)
// mode 2: V transpose [bh][d][l], fp16 hi+lo   (nprod=2)
struct GemmB {
    const __half *A[7], *Bh[7], *Bl[7];
    const float* bias[7];
    __half *Oh[7], *Ol[7];
    int mode[7];
    int part[7];
    int nprod[7];
};

__global__ __launch_bounds__(256, 2)
void gemm_batch(GemmB args)
{
    extern __shared__ char smem[];
    const uint32_t sbase = smem_u32(smem);
    const int z = blockIdx.z;
    const int tid = threadIdx.x;
    const int wid = tid >> 5, lane = tid & 31;
    const int m0 = blockIdx.y * 128, n0 = blockIdx.x * 128;
    const int wm = wid & 3, wn = wid >> 2;

    float acc[2][8][4];
#pragma unroll
    for (int mf = 0; mf < 2; mf++)
#pragma unroll
        for (int nf = 0; nf < 8; nf++)
#pragma unroll
            for (int q = 0; q < 4; q++) acc[mf][nf][q] = 0.f;

    gemm_core(sbase, m0, n0, tid, wm, wn, lane, args.nprod[z],
              args.A[z], args.Bh[z], args.Bl[z], acc);

    const float* bias = args.bias[z];
    __half* Oh = args.Oh[z];
    __half* Ol = args.Ol[z];
    const int mode = args.mode[z], part = args.part[z];

    const int g = lane >> 2, tq = lane & 3;
    float2 bv[8];
#pragma unroll
    for (int nf = 0; nf < 8; nf++)
        bv[nf] = *(const float2*)(bias + n0 + wn * 64 + nf * 8 + 2 * tq);

#pragma unroll
    for (int mf = 0; mf < 2; mf++) {
#pragma unroll
        for (int half = 0; half < 2; half++) {
            const int m = m0 + wm * 32 + mf * 16 + g + half * 8;
            const int bb = m >> 9, ll = m & 511;
#pragma unroll
            for (int nf = 0; nf < 8; nf++) {
                const int n = n0 + wn * 64 + nf * 8 + 2 * tq;
                const int h = n >> 6, dd = n & 63;
                float vx = acc[mf][nf][half * 2 + 0] + bv[nf].x;
                float vy = acc[mf][nf][half * 2 + 1] + bv[nf].y;
                __half hx = __float2half(vx), hy = __float2half(vy);
                if (mode == 0) {
                    size_t dst = ((((size_t)bb * NH_ + h) * L_ + ll) * DCAT)
                               + (size_t)part * 64 + dd;
                    __half2 hi2; hi2.x = hx; hi2.y = hy;
                    *(__half2*)(Oh + dst) = hi2;
                } else {
                    __half lx = __float2half(vx - __half2float(hx));
                    __half ly = __float2half(vy - __half2float(hy));
                    if (mode == 1) {
                        size_t dst = ((((size_t)bb * NH_ + h) * L_ + ll) * DCAT)
                                   + (size_t)part * 64 + dd;
                        __half2 hi2; hi2.x = hx; hi2.y = hy;
                        __half2 lo2; lo2.x = lx; lo2.y = ly;
                        *(__half2*)(Oh + dst) = hi2;
                        *(__half2*)(Ol + dst) = lo2;
                    } else {
                        size_t dst = (((size_t)bb * NH_ + h) * HD_ + dd) * L_ + ll;
                        Oh[dst] = hx;  Ol[dst] = lx;
                        Oh[dst + L_] = hy;  Ol[dst + L_] = ly;
                    }
                }
            }
        }
    }
}

// ---------------- output projection GEMM (fp32 out) ----------------
__global__ __launch_bounds__(256, 2)
void gemm_out(const __half* __restrict__ A,
              const __half* __restrict__ Bh, const __half* __restrict__ Bl,
              const float* __restrict__ bias, float* __restrict__ out)
{
    extern __shared__ char smem[];
    const uint32_t sbase = smem_u32(smem);
    const int tid = threadIdx.x;
    const int wid = tid >> 5, lane = tid & 31;
    const int m0 = blockIdx.y * 128, n0 = blockIdx.x * 128;
    const int wm = wid & 3, wn = wid >> 2;

    float acc[2][8][4];
#pragma unroll
    for (int mf = 0; mf < 2; mf++)
#pragma unroll
        for (int nf = 0; nf < 8; nf++)
#pragma unroll
            for (int q = 0; q < 4; q++) acc[mf][nf][q] = 0.f;

    gemm_core(sbase, m0, n0, tid, wm, wn, lane, 2, A, Bh, Bl, acc);

    const int g = lane >> 2, tq = lane & 3;
    float2 bv[8];
#pragma unroll
    for (int nf = 0; nf < 8; nf++)
        bv[nf] = *(const float2*)(bias + n0 + wn * 64 + nf * 8 + 2 * tq);
#pragma unroll
    for (int mf = 0; mf < 2; mf++)
#pragma unroll
        for (int half = 0; half < 2; half++) {
            const int m = m0 + wm * 32 + mf * 16 + g + half * 8;
#pragma unroll
            for (int nf = 0; nf < 8; nf++) {
                const int n = n0 + wn * 64 + nf * 8 + 2 * tq;
                float2 v;
                v.x = acc[mf][nf][half * 2 + 0] + bv[nf].x;
                v.y = acc[mf][nf][half * 2 + 1] + bv[nf].y;
                *(float2*)(out + (size_t)m * HID_ + n) = v;
            }
        }
}

// ---------------- flash attention: fp16 2-product, 128-thread CTA ----------------
#define AQ_STRIDE 400u
#define AV_STRIDE 144u
#define SM_Q  0u
#define SM_KH 25600u
#define SM_KL 51200u
#define SM_VH 76800u
#define SM_VL 86016u
#define ATT_SMEM 95232

__global__ __launch_bounds__(128, 2)
void attn_mma(const float* __restrict__ rel,
              const __half* __restrict__ Qf,
              const __half* __restrict__ Kh, const __half* __restrict__ Kl,
              const __half* __restrict__ Vth, const __half* __restrict__ Vtl,
              __half* __restrict__ Of)
{
    extern __shared__ char smc[];
    const uint32_t sb = smem_u32(smc);
    const int qt = (int)gridDim.x - 1 - (int)blockIdx.x;   // heavy CTAs first
    const int bh = blockIdx.y;
    const int q0 = qt * 64;
    const int tid = threadIdx.x, wid = tid >> 5, lane = tid & 31;
    const int g = lane >> 2, tq = lane & 3;
    const int wrow = wid * 16;

    const __half* qf_g = Qf  + (size_t)bh * L_ * DCAT;
    const __half* kh_g = Kh  + (size_t)bh * L_ * DCAT;
    const __half* kl_g = Kl  + (size_t)bh * L_ * DCAT;
    const __half* vh_g = Vth + (size_t)bh * HD_ * L_;
    const __half* vl_g = Vtl + (size_t)bh * HD_ * L_;
    const float* relg = rel + (size_t)bh * L_ * L_;

#pragma unroll
    for (int i = 0; i < 12; i++) {
        int idx = i * 128 + tid;
        int r = idx / 24, s2 = idx % 24;
        cp16(sb + SM_Q + r * AQ_STRIDE + s2 * 16,
             qf_g + (size_t)(q0 + r) * DCAT + s2 * 8);
    }
    asm volatile("cp.async.commit_group;");

    float m_i[2] = {-3.0e38f, -3.0e38f};
    float l_i[2] = {0.f, 0.f};
    float oacc[8][4];
#pragma unroll
    for (int nf = 0; nf < 8; nf++)
#pragma unroll
        for (int q = 0; q < 4; q++) oacc[nf][q] = 0.f;

    const uint32_t aoffQ = (uint32_t)(wrow + (lane & 7) + ((lane >> 3) & 1) * 8) * AQ_STRIDE
                         + (lane >> 4) * 16;
    const uint32_t boffK = (uint32_t)((lane & 7) + ((lane >> 4) & 1) * 8) * AQ_STRIDE
                         + ((lane >> 3) & 1) * 16;
    const uint32_t boffV = (uint32_t)((lane & 7) + ((lane >> 4) & 1) * 8) * AV_STRIDE
                         + ((lane >> 3) & 1) * 16;

    const int row0c = q0 + wrow + g;
    const int row1c = row0c + 8;

    const int ntiles = qt + 1;
    for (int kt = 0; kt < ntiles; kt++) {
        const int k0 = kt * 64;
        __syncthreads();
#pragma unroll
        for (int i = 0; i < 32; i++) {
            int idx = i * 128 + tid;
            if (idx < 3072) {
                int mat = idx >= 1536;
                int j = idx - mat * 1536;
                int r = j / 24, s2 = j % 24;
                cp16(sb + (mat ? SM_KL : SM_KH) + r * AQ_STRIDE + s2 * 16,
                     (mat ? kl_g : kh_g) + (size_t)(k0 + r) * DCAT + s2 * 8);
            } else {
                int j = idx - 3072;
                int mat = j >= 512;
                j -= mat * 512;
                int d = j >> 3, s2 = j & 7;
                cp16(sb + (mat ? SM_VL : SM_VH) + d * AV_STRIDE + s2 * 16,
                     (mat ? vl_g : vh_g) + (size_t)d * L_ + k0 + s2 * 8);
            }
        }
        asm volatile("cp.async.commit_group;");
        asm volatile("cp.async.wait_group 0;" ::: "memory");
        __syncthreads();

        if (k0 > q0 + wrow + 15) continue;

        float2 rr0[8], rr1[8];
#pragma unroll
        for (int nf = 0; nf < 8; nf++) {
            const int col = k0 + nf * 8 + 2 * tq;
            rr0[nf] = *(const float2*)(relg + (size_t)row0c * L_ + col);
            rr1[nf] = *(const float2*)(relg + (size_t)row1c * L_ + col);
        }

        float sacc[8][4];
#pragma unroll
        for (int nf = 0; nf < 8; nf++)
#pragma unroll
            for (int q = 0; q < 4; q++) sacc[nf][q] = 0.f;

#pragma unroll
        for (int ks = 0; ks < 12; ks++) {
            const uint32_t koff = ks * 32;
            uint32_t aq[4], bqh[16], bql[16];
            ldm_x4(aq, sb + SM_Q + aoffQ + koff);
#pragma unroll
            for (int np = 0; np < 4; np++) {
                ldm_x4(&bqh[np * 4], sb + SM_KH + boffK + np * 16 * AQ_STRIDE + koff);
                ldm_x4(&bql[np * 4], sb + SM_KL + boffK + np * 16 * AQ_STRIDE + koff);
            }
#pragma unroll
            for (int nf = 0; nf < 8; nf++) {
                mma16816h(sacc[nf], aq, &bqh[(nf >> 1) * 4 + (nf & 1) * 2]);
                mma16816h(sacc[nf], aq, &bql[(nf >> 1) * 4 + (nf & 1) * 2]);
            }
        }

        const int row0 = row0c;
        const int row1 = row1c;
        const bool diag = (k0 + 63 > q0 + wrow);
        float pmax0 = -3.0e38f, pmax1 = -3.0e38f;
#pragma unroll
        for (int nf = 0; nf < 8; nf++) {
            const int col = k0 + nf * 8 + 2 * tq;
            float s0 = fmaf(sacc[nf][0], 0.125f, rr0[nf].x);
            float s1 = fmaf(sacc[nf][1], 0.125f, rr0[nf].y);
            float s2 = fmaf(sacc[nf][2], 0.125f, rr1[nf].x);
            float s3 = fmaf(sacc[nf][3], 0.125f, rr1[nf].y);
            if (diag) {
                if (col     > row0) s0 = -3.0e38f;
                if (col + 1 > row0) s1 = -3.0e38f;
                if (col     > row1) s2 = -3.0e38f;
                if (col + 1 > row1) s3 = -3.0e38f;
            }
            sacc[nf][0] = s0; sacc[nf][1] = s1; sacc[nf][2] = s2; sacc[nf][3] = s3;
            pmax0 = fmaxf(pmax0, fmaxf(s0, s1));
            pmax1 = fmaxf(pmax1, fmaxf(s2, s3));
        }
        {
            __half2 hm = __floats2half2_rn(pmax0, pmax1);
#pragma unroll
            for (int d = 1; d < 4; d <<= 1) {
                uint32_t u = *(uint32_t*)&hm;
                uint32_t v = __shfl_xor_sync(0xffffffffu, u, d);
                hm = __hmax2(hm, *(__half2*)&v);
            }
            float2 fm = __half22float2(hm);
            pmax0 = fm.x;  pmax1 = fm.y;
        }
        const float nm0 = fmaxf(m_i[0], pmax0);
        const float nm1 = fmaxf(m_i[1], pmax1);
        const float al0 = __expf(m_i[0] - nm0);
        const float al1 = __expf(m_i[1] - nm1);
        float rs0 = 0.f, rs1 = 0.f;
#pragma unroll
        for (int nf = 0; nf < 8; nf++) {
            sacc[nf][0] = __expf(sacc[nf][0] - nm0);
            sacc[nf][1] = __expf(sacc[nf][1] - nm0);
            sacc[nf][2] = __expf(sacc[nf][2] - nm1);
            sacc[nf][3] = __expf(sacc[nf][3] - nm1);
            rs0 += sacc[nf][0] + sacc[nf][1];
            rs1 += sacc[nf][2] + sacc[nf][3];
        }
#pragma unroll
        for (int d = 1; d < 4; d <<= 1) {
            rs0 += __shfl_xor_sync(0xffffffffu, rs0, d);
            rs1 += __shfl_xor_sync(0xffffffffu, rs1, d);
        }
        l_i[0] = l_i[0] * al0 + rs0;  m_i[0] = nm0;
        l_i[1] = l_i[1] * al1 + rs1;  m_i[1] = nm1;
#pragma unroll
        for (int nf = 0; nf < 8; nf++) {
            oacc[nf][0] *= al0; oacc[nf][1] *= al0;
            oacc[nf][2] *= al1; oacc[nf][3] *= al1;
        }

#pragma unroll
        for (int ks = 0; ks < 4; ks++) {
            uint32_t af[4];
            af[0] = pack_h2(sacc[2*ks][0],   sacc[2*ks][1]);
            af[1] = pack_h2(sacc[2*ks][2],   sacc[2*ks][3]);
            af[2] = pack_h2(sacc[2*ks+1][0], sacc[2*ks+1][1]);
            af[3] = pack_h2(sacc[2*ks+1][2], sacc[2*ks+1][3]);
            uint32_t bvh[16], bvl[16];
            const uint32_t koff = ks * 32;
#pragma unroll
            for (int np = 0; np < 4; np++) {
                ldm_x4(&bvh[np * 4], sb + SM_VH + boffV + np * 16 * AV_STRIDE + koff);
                ldm_x4(&bvl[np * 4], sb + SM_VL + boffV + np * 16 * AV_STRIDE + koff);
            }
#pragma unroll
            for (int nf = 0; nf < 8; nf++) {
                mma16816h(oacc[nf], af, &bvh[(nf >> 1) * 4 + (nf & 1) * 2]);
                mma16816h(oacc[nf], af, &bvl[(nf >> 1) * 4 + (nf & 1) * 2]);
            }
        }
    }

    const int b = bh >> 4, h = bh & 15;
    const float inv0 = 1.0f / l_i[0];
    const float inv1 = 1.0f / l_i[1];
    const size_t m0g = (size_t)(b * L_ + q0 + wrow + g) * HID_;
    const size_t m1g = m0g + 8 * HID_;
#pragma unroll
    for (int nf = 0; nf < 8; nf++) {
        const int col = h * 64 + nf * 8 + 2 * tq;
        __half2 o0 = __floats2half2_rn(oacc[nf][0] * inv0, oacc[nf][1] * inv0);
        __half2 o1 = __floats2half2_rn(oacc[nf][2] * inv1, oacc[nf][3] * inv1);
        *(__half2*)(Of + m0g + col) = o0;
        *(__half2*)(Of + m1g + col) = o1;
    }
}

// ---------------- launcher ----------------
extern "C" void kernel_launch(void* const* d_in, const int* in_sizes, int n_in,
                              void* d_out, int out_size)
{
    const float* rel = (const float*)d_in[5];
    float* out = (float*)d_out;

    __half *xf, *wfh, *wfl, *qf, *k16h, *k16l, *v16h, *v16l;
    cudaGetSymbolAddress((void**)&xf, g_xf);
    cudaGetSymbolAddress((void**)&wfh, g_wfh);
    cudaGetSymbolAddress((void**)&wfl, g_wfl);
    cudaGetSymbolAddress((void**)&qf, g_qf);
    cudaGetSymbolAddress((void**)&k16h, g_k16h);
    cudaGetSymbolAddress((void**)&k16l, g_k16l);
    cudaGetSymbolAddress((void**)&v16h, g_v16h);
    cudaGetSymbolAddress((void**)&v16l, g_v16l);

    cudaFuncSetAttribute(gemm_batch, cudaFuncAttributeMaxDynamicSharedMemorySize, GEMM_SMEM);
    cudaFuncSetAttribute(gemm_out, cudaFuncAttributeMaxDynamicSharedMemorySize, GEMM_SMEM);
    cudaFuncSetAttribute(attn_mma, cudaFuncAttributeMaxDynamicSharedMemorySize, ATT_SMEM);

    const int n4 = (int)(XN / 4);

    SplitSrc ss;
    ss.p[0] = (const float*)d_in[0];
    ss.p[1] = (const float*)d_in[1];
    ss.p[2] = (const float*)d_in[2];
    ss.p[3] = (const float*)d_in[3];
    split_f16<<<dim3((n4 + 255) / 256, 4), 256>>>(ss, xf, n4);

    WSrc ws;
    ws.p[0] = (const float*)d_in[6];   ws.p[1] = (const float*)d_in[8];
    ws.p[2] = (const float*)d_in[10];  ws.p[3] = (const float*)d_in[12];
    ws.p[4] = (const float*)d_in[14];  ws.p[5] = (const float*)d_in[16];
    ws.p[6] = (const float*)d_in[18];  ws.p[7] = (const float*)d_in[20];
    splitT_h<<<dim3(32, 32, 8), dim3(32, 8)>>>(ws, wfh, wfl);

    GemmB gb;
    const int ain[7]  = {0, 1, 2, 0, 1, 2, 3};
    const int wsl[7]  = {0, 3, 5, 1, 4, 6, 2};
    const int bidx[7] = {7, 13, 17, 9, 15, 19, 11};
    for (int z = 0; z < 7; z++) {
        gb.A[z]  = xf + (size_t)ain[z] * XN;
        gb.Bh[z] = wfh + (size_t)wsl[z] * WN;
        gb.Bl[z] = wfl + (size_t)wsl[z] * WN;
        gb.bias[z] = (const float*)d_in[bidx[z]];
    }
    // Q projections: single-product (Q is consumed as fp16 anyway)
    gb.Oh[0] = qf;   gb.Ol[0] = qf;    gb.mode[0] = 0; gb.part[0] = 0; gb.nprod[0] = 1;
    gb.Oh[1] = qf;   gb.Ol[1] = qf;    gb.mode[1] = 0; gb.part[1] = 1; gb.nprod[1] = 1;
    gb.Oh[2] = qf;   gb.Ol[2] = qf;    gb.mode[2] = 0; gb.part[2] = 2; gb.nprod[2] = 1;
    gb.Oh[3] = k16h; gb.Ol[3] = k16l;  gb.mode[3] = 1; gb.part[3] = 0; gb.nprod[3] = 2;
    gb.Oh[4] = k16h; gb.Ol[4] = k16l;  gb.mode[4] = 1; gb.part[4] = 1; gb.nprod[4] = 2;
    gb.Oh[5] = k16h; gb.Ol[5] = k16l;  gb.mode[5] = 1; gb.part[5] = 2; gb.nprod[5] = 2;
    gb.Oh[6] = v16h; gb.Ol[6] = v16l;  gb.mode[6] = 2; gb.part[6] = 0; gb.nprod[6] = 2;
    gemm_batch<<<dim3(8, 64, 7), 256, GEMM_SMEM>>>(gb);

    attn_mma<<<dim3(8, 256), 128, ATT_SMEM>>>(rel, qf, k16h, k16l, v16h, v16l,
                                              xf + 4 * XN);

    gemm_out<<<dim3(8, 64), 256, GEMM_SMEM>>>(xf + 4 * XN,
                                              wfh + 7 * WN, wfl + 7 * WN,
                                              (const float*)d_in[21], out);
}

// round 13
// speedup vs baseline: 2.1723x; 1.2091x over previous
#include <cuda_runtime.h>
#include <cuda_bf16.h>
#include <cuda_fp16.h>
#include <cstdint>

#define B_    16
#define L_    512
#define HID_  1024
#define NH_   16
#define HD_   64
#define M_TOT (B_*L_)      // 8192
#define DCAT  192
#define XN    ((size_t)M_TOT*HID_)
#define WN    ((size_t)HID_*HID_)

// ---------------- scratch (static device arrays) ----------------
__device__ __half g_xf[5ULL*XN];            // fp16 activations: 4 inputs + attn-out
__device__ __half g_wfh[8ULL*WN];           // W^T fp16 hi
__device__ __half g_wfl[8ULL*WN];           // W^T fp16 lo (residual)
__device__ __half g_qf [(size_t)B_*NH_*L_*DCAT];   // Q single fp16
__device__ __half g_kf [(size_t)B_*NH_*L_*DCAT];   // K single fp16
__device__ __half g_v16h[(size_t)B_*NH_*HD_*L_];   // Vt fp16 hi
__device__ __half g_v16l[(size_t)B_*NH_*HD_*L_];   // Vt fp16 lo

// ---------------- PTX helpers (baseline ISA only) ----------------
__device__ __forceinline__ uint32_t smem_u32(const void* p) {
    uint32_t a;
    asm("{ .reg .u64 t; cvta.to.shared.u64 t, %1; cvt.u32.u64 %0, t; }" : "=r"(a) : "l"(p));
    return a;
}
__device__ __forceinline__ void cp16(uint32_t dst, const void* src) {
    asm volatile("cp.async.cg.shared.global [%0], [%1], 16;" :: "r"(dst), "l"(src));
}
__device__ __forceinline__ void ldm_x4(uint32_t* r, uint32_t addr) {
    asm volatile("ldmatrix.sync.aligned.m8n8.x4.shared.b16 {%0,%1,%2,%3}, [%4];"
                 : "=r"(r[0]), "=r"(r[1]), "=r"(r[2]), "=r"(r[3]) : "r"(addr));
}
// fp16 mma
__device__ __forceinline__ void mma16816h(float* d, const uint32_t* a, const uint32_t* b) {
    asm volatile(
        "mma.sync.aligned.m16n8k16.row.col.f32.f16.f16.f32 "
        "{%0,%1,%2,%3}, {%4,%5,%6,%7}, {%8,%9}, {%0,%1,%2,%3};"
        : "+f"(d[0]), "+f"(d[1]), "+f"(d[2]), "+f"(d[3])
        : "r"(a[0]), "r"(a[1]), "r"(a[2]), "r"(a[3]), "r"(b[0]), "r"(b[1]));
}
__device__ __forceinline__ uint32_t pack_h2(float a, float b) {
    __half2 t = __floats2half2_rn(a, b);
    return *(uint32_t*)&t;
}

// ---------------- batched fp32 -> fp16 ----------------
struct SplitSrc { const float* p[4]; };
__global__ __launch_bounds__(256)
void split_f16(SplitSrc s, __half* __restrict__ dst, int n4)
{
    int i = blockIdx.x * 256 + threadIdx.x;
    if (i >= n4) return;
    int z = blockIdx.y;
    const float* src = s.p[z];
    __half* dz = dst + (size_t)z * XN;
    float4 v = ((const float4*)src)[i];
    __half2 a = __floats2half2_rn(v.x, v.y);
    __half2 b = __floats2half2_rn(v.z, v.w);
    ((__half2*)dz)[i*2]   = a;
    ((__half2*)dz)[i*2+1] = b;
}

// ---------------- batched W[k][n] -> W^T[n][k] fp16 split ----------------
struct WSrc { const float* p[8]; };
__global__ __launch_bounds__(256)
void splitT_h(WSrc s, __half* __restrict__ hiT, __half* __restrict__ loT)
{
    __shared__ float t[32][33];
    int z = blockIdx.z;
    const float* W = s.p[z];
    __half* hz = hiT + (size_t)z * WN;
    __half* lz = loT + (size_t)z * WN;
    int bx = blockIdx.x * 32, by = blockIdx.y * 32;
    int tx = threadIdx.x, ty = threadIdx.y;
#pragma unroll
    for (int j = 0; j < 4; j++)
        t[ty + 8*j][tx] = W[(size_t)(by + ty + 8*j) * HID_ + bx + tx];
    __syncthreads();
#pragma unroll
    for (int j = 0; j < 4; j++) {
        float v = t[tx][ty + 8*j];
        int n = bx + ty + 8*j, k = by + tx;
        __half h = __float2half(v);
        hz[(size_t)n * HID_ + k] = h;
        lz[(size_t)n * HID_ + k] = __float2half(v - __half2float(h));
    }
}

// ---------------- GEMM core: load A once, apply Bh (+Bl); CTA 128x128, 2-stage ----------------
#define KC        64
#define NCHUNKW   16
#define ROWB      144u
#define ATILE_B   (128u*ROWB)            // 18432
#define STAGE_B   (3u*ATILE_B)           // 55296 (A + Bh + Bl)
#define GEMM_SMEM (2*STAGE_B)            // 110592  -> occ 2

__device__ __forceinline__ void gemm_load_tile(
    uint32_t sbase, int stage, int c, int m0, int n0, int tid, int nprod,
    const __half* A, const __half* Bh, const __half* Bl)
{
    const int k0 = c * KC;
    const uint32_t dstA = sbase + (uint32_t)stage * STAGE_B;
#pragma unroll
    for (int i = 0; i < 8; i++) {
        int idx = i * 256 + tid;                 // 0..2047
        int r = (idx >> 3) & 127, c16 = idx & 7;
        if (idx < 1024)
            cp16(dstA + r * ROWB + c16 * 16,
                 A + (size_t)(m0 + r) * HID_ + k0 + c16 * 8);
        else
            cp16(dstA + ATILE_B + r * ROWB + c16 * 16,
                 Bh + (size_t)(n0 + r) * HID_ + k0 + c16 * 8);
    }
    if (nprod == 2) {
#pragma unroll
        for (int i = 0; i < 4; i++) {
            int idx = i * 256 + tid;             // 0..1023
            int r = idx >> 3, c16 = idx & 7;
            cp16(dstA + 2 * ATILE_B + r * ROWB + c16 * 16,
                 Bl + (size_t)(n0 + r) * HID_ + k0 + c16 * 8);
        }
    }
    asm volatile("cp.async.commit_group;");
}

__device__ __forceinline__ void gemm_core(
    uint32_t sbase, int m0, int n0, int tid, int wm, int wn, int lane, int nprod,
    const __half* A, const __half* Bh, const __half* Bl,
    float acc[2][8][4])
{
    const int arow = wm * 32 + (lane & 7) + ((lane >> 3) & 1) * 8;
    const uint32_t a_l = (uint32_t)arow * ROWB + ((lane >> 4) * 16);
    const int brow = wn * 64 + (lane & 7) + ((lane >> 4) & 1) * 8;
    const uint32_t b_l = (uint32_t)brow * ROWB + (((lane >> 3) & 1) * 16);

    gemm_load_tile(sbase, 0, 0, m0, n0, tid, nprod, A, Bh, Bl);

    for (int c = 0; c < NCHUNKW; c++) {
        if (c + 1 < NCHUNKW)
            gemm_load_tile(sbase, (c + 1) & 1, c + 1, m0, n0, tid, nprod, A, Bh, Bl);
        if (c + 1 < NCHUNKW) asm volatile("cp.async.wait_group 1;" ::: "memory");
        else                 asm volatile("cp.async.wait_group 0;" ::: "memory");
        __syncthreads();

        const uint32_t sb = sbase + (uint32_t)(c & 1) * STAGE_B;
        const uint32_t aBase  = sb + a_l;
        const uint32_t bhBase = sb + ATILE_B + b_l;
        const uint32_t blBase = sb + 2 * ATILE_B + b_l;
#pragma unroll
        for (int kk = 0; kk < KC / 16; kk++) {
            const uint32_t koff = kk * 32;
            uint32_t aq[2][4];
#pragma unroll
            for (int mf = 0; mf < 2; mf++)
                ldm_x4(aq[mf], aBase + mf * 16 * ROWB + koff);
            uint32_t bqh[16];
#pragma unroll
            for (int np = 0; np < 4; np++)
                ldm_x4(&bqh[np * 4], bhBase + np * 16 * ROWB + koff);
#pragma unroll
            for (int mf = 0; mf < 2; mf++)
#pragma unroll
                for (int nf = 0; nf < 8; nf++)
                    mma16816h(acc[mf][nf], aq[mf], &bqh[(nf >> 1) * 4 + (nf & 1) * 2]);
            if (nprod == 2) {
                uint32_t bql[16];
#pragma unroll
                for (int np = 0; np < 4; np++)
                    ldm_x4(&bql[np * 4], blBase + np * 16 * ROWB + koff);
#pragma unroll
                for (int mf = 0; mf < 2; mf++)
#pragma unroll
                    for (int nf = 0; nf < 8; nf++)
                        mma16816h(acc[mf][nf], aq[mf], &bql[(nf >> 1) * 4 + (nf & 1) * 2]);
            }
        }
        __syncthreads();
    }
}

// ---------------- batched projection GEMMs (fp16 outputs for attention) ----------------
// mode 0: scatter [bh][l][192], single fp16 (Q and K)
// mode 2: V transpose [bh][d][l], fp16 hi+lo
struct GemmB {
    const __half *A[7], *Bh[7], *Bl[7];
    const float* bias[7];
    __half *Oh[7], *Ol[7];
    int mode[7];
    int part[7];
    int nprod[7];
};

__global__ __launch_bounds__(256, 2)
void gemm_batch(GemmB args)
{
    extern __shared__ char smem[];
    const uint32_t sbase = smem_u32(smem);
    const int z = blockIdx.z;
    const int tid = threadIdx.x;
    const int wid = tid >> 5, lane = tid & 31;
    const int m0 = blockIdx.y * 128, n0 = blockIdx.x * 128;
    const int wm = wid & 3, wn = wid >> 2;

    float acc[2][8][4];
#pragma unroll
    for (int mf = 0; mf < 2; mf++)
#pragma unroll
        for (int nf = 0; nf < 8; nf++)
#pragma unroll
            for (int q = 0; q < 4; q++) acc[mf][nf][q] = 0.f;

    gemm_core(sbase, m0, n0, tid, wm, wn, lane, args.nprod[z],
              args.A[z], args.Bh[z], args.Bl[z], acc);

    const float* bias = args.bias[z];
    __half* Oh = args.Oh[z];
    __half* Ol = args.Ol[z];
    const int mode = args.mode[z], part = args.part[z];

    const int g = lane >> 2, tq = lane & 3;
    float2 bv[8];
#pragma unroll
    for (int nf = 0; nf < 8; nf++)
        bv[nf] = *(const float2*)(bias + n0 + wn * 64 + nf * 8 + 2 * tq);

#pragma unroll
    for (int mf = 0; mf < 2; mf++) {
#pragma unroll
        for (int half = 0; half < 2; half++) {
            const int m = m0 + wm * 32 + mf * 16 + g + half * 8;
            const int bb = m >> 9, ll = m & 511;
#pragma unroll
            for (int nf = 0; nf < 8; nf++) {
                const int n = n0 + wn * 64 + nf * 8 + 2 * tq;
                const int h = n >> 6, dd = n & 63;
                float vx = acc[mf][nf][half * 2 + 0] + bv[nf].x;
                float vy = acc[mf][nf][half * 2 + 1] + bv[nf].y;
                __half hx = __float2half(vx), hy = __float2half(vy);
                if (mode == 0) {
                    size_t dst = ((((size_t)bb * NH_ + h) * L_ + ll) * DCAT)
                               + (size_t)part * 64 + dd;
                    __half2 hi2; hi2.x = hx; hi2.y = hy;
                    *(__half2*)(Oh + dst) = hi2;
                } else {
                    __half lx = __float2half(vx - __half2float(hx));
                    __half ly = __float2half(vy - __half2float(hy));
                    size_t dst = (((size_t)bb * NH_ + h) * HD_ + dd) * L_ + ll;
                    Oh[dst] = hx;  Ol[dst] = lx;
                    Oh[dst + L_] = hy;  Ol[dst + L_] = ly;
                }
            }
        }
    }
}

// ---------------- output projection GEMM (fp32 out) ----------------
__global__ __launch_bounds__(256, 2)
void gemm_out(const __half* __restrict__ A,
              const __half* __restrict__ Bh, const __half* __restrict__ Bl,
              const float* __restrict__ bias, float* __restrict__ out)
{
    extern __shared__ char smem[];
    const uint32_t sbase = smem_u32(smem);
    const int tid = threadIdx.x;
    const int wid = tid >> 5, lane = tid & 31;
    const int m0 = blockIdx.y * 128, n0 = blockIdx.x * 128;
    const int wm = wid & 3, wn = wid >> 2;

    float acc[2][8][4];
#pragma unroll
    for (int mf = 0; mf < 2; mf++)
#pragma unroll
        for (int nf = 0; nf < 8; nf++)
#pragma unroll
            for (int q = 0; q < 4; q++) acc[mf][nf][q] = 0.f;

    gemm_core(sbase, m0, n0, tid, wm, wn, lane, 2, A, Bh, Bl, acc);

    const int g = lane >> 2, tq = lane & 3;
    float2 bv[8];
#pragma unroll
    for (int nf = 0; nf < 8; nf++)
        bv[nf] = *(const float2*)(bias + n0 + wn * 64 + nf * 8 + 2 * tq);
#pragma unroll
    for (int mf = 0; mf < 2; mf++)
#pragma unroll
        for (int half = 0; half < 2; half++) {
            const int m = m0 + wm * 32 + mf * 16 + g + half * 8;
#pragma unroll
            for (int nf = 0; nf < 8; nf++) {
                const int n = n0 + wn * 64 + nf * 8 + 2 * tq;
                float2 v;
                v.x = acc[mf][nf][half * 2 + 0] + bv[nf].x;
                v.y = acc[mf][nf][half * 2 + 1] + bv[nf].y;
                *(float2*)(out + (size_t)m * HID_ + n) = v;
            }
        }
}

// ---------------- flash attention: single-fp16 QK, 2-product PV, 128-thr CTA ----------------
// smem: Q 64x400 = 25600 | K 25600 | VH 9216 | VL 9216 = 69632
#define AQ_STRIDE 400u
#define AV_STRIDE 144u
#define SM_Q  0u
#define SM_K  25600u
#define SM_VH 51200u
#define SM_VL 60416u
#define ATT_SMEM 69632

__global__ __launch_bounds__(128, 2)
void attn_mma(const float* __restrict__ rel,
              const __half* __restrict__ Qf, const __half* __restrict__ Kf,
              const __half* __restrict__ Vth, const __half* __restrict__ Vtl,
              __half* __restrict__ Of)
{
    extern __shared__ char smc[];
    const uint32_t sb = smem_u32(smc);
    const int qt = (int)gridDim.x - 1 - (int)blockIdx.x;   // heavy CTAs first
    const int bh = blockIdx.y;
    const int q0 = qt * 64;
    const int tid = threadIdx.x, wid = tid >> 5, lane = tid & 31;
    const int g = lane >> 2, tq = lane & 3;
    const int wrow = wid * 16;

    const __half* qf_g = Qf  + (size_t)bh * L_ * DCAT;
    const __half* kf_g = Kf  + (size_t)bh * L_ * DCAT;
    const __half* vh_g = Vth + (size_t)bh * HD_ * L_;
    const __half* vl_g = Vtl + (size_t)bh * HD_ * L_;
    const float* relg = rel + (size_t)bh * L_ * L_;

    // Q tile load: 64 rows x 24 segs = 1536 over 128 threads
#pragma unroll
    for (int i = 0; i < 12; i++) {
        int idx = i * 128 + tid;
        int r = idx / 24, s2 = idx % 24;
        cp16(sb + SM_Q + r * AQ_STRIDE + s2 * 16,
             qf_g + (size_t)(q0 + r) * DCAT + s2 * 8);
    }
    asm volatile("cp.async.commit_group;");

    float m_i[2] = {-3.0e38f, -3.0e38f};
    float l_i[2] = {0.f, 0.f};
    float oacc[8][4];
#pragma unroll
    for (int nf = 0; nf < 8; nf++)
#pragma unroll
        for (int q = 0; q < 4; q++) oacc[nf][q] = 0.f;

    const uint32_t aoffQ = (uint32_t)(wrow + (lane & 7) + ((lane >> 3) & 1) * 8) * AQ_STRIDE
                         + (lane >> 4) * 16;
    const uint32_t boffK = (uint32_t)((lane & 7) + ((lane >> 4) & 1) * 8) * AQ_STRIDE
                         + ((lane >> 3) & 1) * 16;
    const uint32_t boffV = (uint32_t)((lane & 7) + ((lane >> 4) & 1) * 8) * AV_STRIDE
                         + ((lane >> 3) & 1) * 16;

    const int row0c = q0 + wrow + g;
    const int row1c = row0c + 8;

    const int ntiles = qt + 1;
    for (int kt = 0; kt < ntiles; kt++) {
        const int k0 = kt * 64;
        __syncthreads();
        // K: 64x24 segs (1536); Vt hi+lo: 64x8 segs each (1024) -> 2560 segs
#pragma unroll
        for (int i = 0; i < 20; i++) {
            int idx = i * 128 + tid;
            if (idx < 1536) {
                int r = idx / 24, s2 = idx % 24;
                cp16(sb + SM_K + r * AQ_STRIDE + s2 * 16,
                     kf_g + (size_t)(k0 + r) * DCAT + s2 * 8);
            } else {
                int j = idx - 1536;
                int mat = j >= 512;
                j -= mat * 512;
                int d = j >> 3, s2 = j & 7;
                cp16(sb + (mat ? SM_VL : SM_VH) + d * AV_STRIDE + s2 * 16,
                     (mat ? vl_g : vh_g) + (size_t)d * L_ + k0 + s2 * 8);
            }
        }
        asm volatile("cp.async.commit_group;");
        asm volatile("cp.async.wait_group 0;" ::: "memory");
        __syncthreads();

        if (k0 > q0 + wrow + 15) continue;

        // prefetch relative_time bias (hidden under QK mma)
        float2 rr0[8], rr1[8];
#pragma unroll
        for (int nf = 0; nf < 8; nf++) {
            const int col = k0 + nf * 8 + 2 * tq;
            rr0[nf] = *(const float2*)(relg + (size_t)row0c * L_ + col);
            rr1[nf] = *(const float2*)(relg + (size_t)row1c * L_ + col);
        }

        // ---- S = Q*K over k=192, single fp16 ----
        float sacc[8][4];
#pragma unroll
        for (int nf = 0; nf < 8; nf++)
#pragma unroll
            for (int q = 0; q < 4; q++) sacc[nf][q] = 0.f;

#pragma unroll
        for (int ks = 0; ks < 12; ks++) {
            const uint32_t koff = ks * 32;
            uint32_t aq[4], bq[16];
            ldm_x4(aq, sb + SM_Q + aoffQ + koff);
#pragma unroll
            for (int np = 0; np < 4; np++)
                ldm_x4(&bq[np * 4], sb + SM_K + boffK + np * 16 * AQ_STRIDE + koff);
#pragma unroll
            for (int nf = 0; nf < 8; nf++)
                mma16816h(sacc[nf], aq, &bq[(nf >> 1) * 4 + (nf & 1) * 2]);
        }

        // ---- bias + mask + online softmax ----
        const int row0 = row0c;
        const int row1 = row1c;
        const bool diag = (k0 + 63 > q0 + wrow);
        float pmax0 = -3.0e38f, pmax1 = -3.0e38f;
#pragma unroll
        for (int nf = 0; nf < 8; nf++) {
            const int col = k0 + nf * 8 + 2 * tq;
            float s0 = fmaf(sacc[nf][0], 0.125f, rr0[nf].x);
            float s1 = fmaf(sacc[nf][1], 0.125f, rr0[nf].y);
            float s2 = fmaf(sacc[nf][2], 0.125f, rr1[nf].x);
            float s3 = fmaf(sacc[nf][3], 0.125f, rr1[nf].y);
            if (diag) {
                if (col     > row0) s0 = -3.0e38f;
                if (col + 1 > row0) s1 = -3.0e38f;
                if (col     > row1) s2 = -3.0e38f;
                if (col + 1 > row1) s3 = -3.0e38f;
            }
            sacc[nf][0] = s0; sacc[nf][1] = s1; sacc[nf][2] = s2; sacc[nf][3] = s3;
            pmax0 = fmaxf(pmax0, fmaxf(s0, s1));
            pmax1 = fmaxf(pmax1, fmaxf(s2, s3));
        }
        {
            __half2 hm = __floats2half2_rn(pmax0, pmax1);
#pragma unroll
            for (int d = 1; d < 4; d <<= 1) {
                uint32_t u = *(uint32_t*)&hm;
                uint32_t v = __shfl_xor_sync(0xffffffffu, u, d);
                hm = __hmax2(hm, *(__half2*)&v);
            }
            float2 fm = __half22float2(hm);
            pmax0 = fm.x;  pmax1 = fm.y;
        }
        const float nm0 = fmaxf(m_i[0], pmax0);
        const float nm1 = fmaxf(m_i[1], pmax1);
        const float al0 = __expf(m_i[0] - nm0);
        const float al1 = __expf(m_i[1] - nm1);
        float rs0 = 0.f, rs1 = 0.f;
#pragma unroll
        for (int nf = 0; nf < 8; nf++) {
            sacc[nf][0] = __expf(sacc[nf][0] - nm0);
            sacc[nf][1] = __expf(sacc[nf][1] - nm0);
            sacc[nf][2] = __expf(sacc[nf][2] - nm1);
            sacc[nf][3] = __expf(sacc[nf][3] - nm1);
            rs0 += sacc[nf][0] + sacc[nf][1];
            rs1 += sacc[nf][2] + sacc[nf][3];
        }
#pragma unroll
        for (int d = 1; d < 4; d <<= 1) {
            rs0 += __shfl_xor_sync(0xffffffffu, rs0, d);
            rs1 += __shfl_xor_sync(0xffffffffu, rs1, d);
        }
        l_i[0] = l_i[0] * al0 + rs0;  m_i[0] = nm0;
        l_i[1] = l_i[1] * al1 + rs1;  m_i[1] = nm1;
#pragma unroll
        for (int nf = 0; nf < 8; nf++) {
            oacc[nf][0] *= al0; oacc[nf][1] *= al0;
            oacc[nf][2] *= al1; oacc[nf][3] *= al1;
        }

        // ---- O += P*(Vh + Vl) over k=64, fp16 P ----
#pragma unroll
        for (int ks = 0; ks < 4; ks++) {
            uint32_t af[4];
            af[0] = pack_h2(sacc[2*ks][0],   sacc[2*ks][1]);
            af[1] = pack_h2(sacc[2*ks][2],   sacc[2*ks][3]);
            af[2] = pack_h2(sacc[2*ks+1][0], sacc[2*ks+1][1]);
            af[3] = pack_h2(sacc[2*ks+1][2], sacc[2*ks+1][3]);
            uint32_t bvh[16], bvl[16];
            const uint32_t koff = ks * 32;
#pragma unroll
            for (int np = 0; np < 4; np++) {
                ldm_x4(&bvh[np * 4], sb + SM_VH + boffV + np * 16 * AV_STRIDE + koff);
                ldm_x4(&bvl[np * 4], sb + SM_VL + boffV + np * 16 * AV_STRIDE + koff);
            }
#pragma unroll
            for (int nf = 0; nf < 8; nf++) {
                mma16816h(oacc[nf], af, &bvh[(nf >> 1) * 4 + (nf & 1) * 2]);
                mma16816h(oacc[nf], af, &bvl[(nf >> 1) * 4 + (nf & 1) * 2]);
            }
        }
    }

    // ---- epilogue: normalize, fp16 write to [m][HID] ----
    const int b = bh >> 4, h = bh & 15;
    const float inv0 = 1.0f / l_i[0];
    const float inv1 = 1.0f / l_i[1];
    const size_t m0g = (size_t)(b * L_ + q0 + wrow + g) * HID_;
    const size_t m1g = m0g + 8 * HID_;
#pragma unroll
    for (int nf = 0; nf < 8; nf++) {
        const int col = h * 64 + nf * 8 + 2 * tq;
        __half2 o0 = __floats2half2_rn(oacc[nf][0] * inv0, oacc[nf][1] * inv0);
        __half2 o1 = __floats2half2_rn(oacc[nf][2] * inv1, oacc[nf][3] * inv1);
        *(__half2*)(Of + m0g + col) = o0;
        *(__half2*)(Of + m1g + col) = o1;
    }
}

// ---------------- launcher ----------------
extern "C" void kernel_launch(void* const* d_in, const int* in_sizes, int n_in,
                              void* d_out, int out_size)
{
    const float* rel = (const float*)d_in[5];
    float* out = (float*)d_out;

    __half *xf, *wfh, *wfl, *qf, *kf, *v16h, *v16l;
    cudaGetSymbolAddress((void**)&xf, g_xf);
    cudaGetSymbolAddress((void**)&wfh, g_wfh);
    cudaGetSymbolAddress((void**)&wfl, g_wfl);
    cudaGetSymbolAddress((void**)&qf, g_qf);
    cudaGetSymbolAddress((void**)&kf, g_kf);
    cudaGetSymbolAddress((void**)&v16h, g_v16h);
    cudaGetSymbolAddress((void**)&v16l, g_v16l);

    cudaFuncSetAttribute(gemm_batch, cudaFuncAttributeMaxDynamicSharedMemorySize, GEMM_SMEM);
    cudaFuncSetAttribute(gemm_out, cudaFuncAttributeMaxDynamicSharedMemorySize, GEMM_SMEM);
    cudaFuncSetAttribute(attn_mma, cudaFuncAttributeMaxDynamicSharedMemorySize, ATT_SMEM);

    const int n4 = (int)(XN / 4);

    SplitSrc ss;
    ss.p[0] = (const float*)d_in[0];
    ss.p[1] = (const float*)d_in[1];
    ss.p[2] = (const float*)d_in[2];
    ss.p[3] = (const float*)d_in[3];
    split_f16<<<dim3((n4 + 255) / 256, 4), 256>>>(ss, xf, n4);

    WSrc ws;
    ws.p[0] = (const float*)d_in[6];   ws.p[1] = (const float*)d_in[8];
    ws.p[2] = (const float*)d_in[10];  ws.p[3] = (const float*)d_in[12];
    ws.p[4] = (const float*)d_in[14];  ws.p[5] = (const float*)d_in[16];
    ws.p[6] = (const float*)d_in[18];  ws.p[7] = (const float*)d_in[20];
    splitT_h<<<dim3(32, 32, 8), dim3(32, 8)>>>(ws, wfh, wfl);

    GemmB gb;
    const int ain[7]  = {0, 1, 2, 0, 1, 2, 3};
    const int wsl[7]  = {0, 3, 5, 1, 4, 6, 2};
    const int bidx[7] = {7, 13, 17, 9, 15, 19, 11};
    for (int z = 0; z < 7; z++) {
        gb.A[z]  = xf + (size_t)ain[z] * XN;
        gb.Bh[z] = wfh + (size_t)wsl[z] * WN;
        gb.Bl[z] = wfl + (size_t)wsl[z] * WN;
        gb.bias[z] = (const float*)d_in[bidx[z]];
    }
    // Q and K projections: single-product, single-fp16 output
    gb.Oh[0] = qf;   gb.Ol[0] = qf;    gb.mode[0] = 0; gb.part[0] = 0; gb.nprod[0] = 1;
    gb.Oh[1] = qf;   gb.Ol[1] = qf;    gb.mode[1] = 0; gb.part[1] = 1; gb.nprod[1] = 1;
    gb.Oh[2] = qf;   gb.Ol[2] = qf;    gb.mode[2] = 0; gb.part[2] = 2; gb.nprod[2] = 1;
    gb.Oh[3] = kf;   gb.Ol[3] = kf;    gb.mode[3] = 0; gb.part[3] = 0; gb.nprod[3] = 1;
    gb.Oh[4] = kf;   gb.Ol[4] = kf;    gb.mode[4] = 0; gb.part[4] = 1; gb.nprod[4] = 1;
    gb.Oh[5] = kf;   gb.Ol[5] = kf;    gb.mode[5] = 0; gb.part[5] = 2; gb.nprod[5] = 1;
    gb.Oh[6] = v16h; gb.Ol[6] = v16l;  gb.mode[6] = 2; gb.part[6] = 0; gb.nprod[6] = 2;
    gemm_batch<<<dim3(8, 64, 7), 256, GEMM_SMEM>>>(gb);

    attn_mma<<<dim3(8, 256), 128, ATT_SMEM>>>(rel, qf, kf, v16h, v16l,
                                              xf + 4 * XN);

    gemm_out<<<dim3(8, 64), 256, GEMM_SMEM>>>(xf + 4 * XN,
                                              wfh + 7 * WN, wfl + 7 * WN,
                                              (const float*)d_in[21], out);
}

// round 14
// speedup vs baseline: 2.3589x; 1.0859x over previous
#include <cuda_runtime.h>
#include <cuda_bf16.h>
#include <cuda_fp16.h>
#include <cstdint>

#define B_    16
#define L_    512
#define HID_  1024
#define NH_   16
#define HD_   64
#define M_TOT (B_*L_)      // 8192
#define DCAT  192
#define XN    ((size_t)M_TOT*HID_)
#define WN    ((size_t)HID_*HID_)

// ---------------- scratch (static device arrays) ----------------
__device__ __half g_xf[5ULL*XN];            // fp16 activations: 4 inputs + attn-out
__device__ __half g_wfh[8ULL*WN];           // W^T fp16 hi
__device__ __half g_wfl[8ULL*WN];           // W^T fp16 lo (residual)
__device__ __half g_qf [(size_t)B_*NH_*L_*DCAT];   // Q single fp16
__device__ __half g_kf [(size_t)B_*NH_*L_*DCAT];   // K single fp16
__device__ __half g_vf [(size_t)B_*NH_*HD_*L_];    // Vt single fp16

// ---------------- PTX helpers (baseline ISA only) ----------------
__device__ __forceinline__ uint32_t smem_u32(const void* p) {
    uint32_t a;
    asm("{ .reg .u64 t; cvta.to.shared.u64 t, %1; cvt.u32.u64 %0, t; }" : "=r"(a) : "l"(p));
    return a;
}
__device__ __forceinline__ void cp16(uint32_t dst, const void* src) {
    asm volatile("cp.async.cg.shared.global [%0], [%1], 16;" :: "r"(dst), "l"(src));
}
__device__ __forceinline__ void ldm_x4(uint32_t* r, uint32_t addr) {
    asm volatile("ldmatrix.sync.aligned.m8n8.x4.shared.b16 {%0,%1,%2,%3}, [%4];"
                 : "=r"(r[0]), "=r"(r[1]), "=r"(r[2]), "=r"(r[3]) : "r"(addr));
}
// fp16 mma
__device__ __forceinline__ void mma16816h(float* d, const uint32_t* a, const uint32_t* b) {
    asm volatile(
        "mma.sync.aligned.m16n8k16.row.col.f32.f16.f16.f32 "
        "{%0,%1,%2,%3}, {%4,%5,%6,%7}, {%8,%9}, {%0,%1,%2,%3};"
        : "+f"(d[0]), "+f"(d[1]), "+f"(d[2]), "+f"(d[3])
        : "r"(a[0]), "r"(a[1]), "r"(a[2]), "r"(a[3]), "r"(b[0]), "r"(b[1]));
}
__device__ __forceinline__ uint32_t pack_h2(float a, float b) {
    __half2 t = __floats2half2_rn(a, b);
    return *(uint32_t*)&t;
}

// ---------------- batched fp32 -> fp16 ----------------
struct SplitSrc { const float* p[4]; };
__global__ __launch_bounds__(256)
void split_f16(SplitSrc s, __half* __restrict__ dst, int n4)
{
    int i = blockIdx.x * 256 + threadIdx.x;
    if (i >= n4) return;
    int z = blockIdx.y;
    const float* src = s.p[z];
    __half* dz = dst + (size_t)z * XN;
    float4 v = ((const float4*)src)[i];
    __half2 a = __floats2half2_rn(v.x, v.y);
    __half2 b = __floats2half2_rn(v.z, v.w);
    ((__half2*)dz)[i*2]   = a;
    ((__half2*)dz)[i*2+1] = b;
}

// ---------------- batched W[k][n] -> W^T[n][k] fp16 split ----------------
struct WSrc { const float* p[8]; };
__global__ __launch_bounds__(256)
void splitT_h(WSrc s, __half* __restrict__ hiT, __half* __restrict__ loT)
{
    __shared__ float t[32][33];
    int z = blockIdx.z;
    const float* W = s.p[z];
    __half* hz = hiT + (size_t)z * WN;
    __half* lz = loT + (size_t)z * WN;
    int bx = blockIdx.x * 32, by = blockIdx.y * 32;
    int tx = threadIdx.x, ty = threadIdx.y;
#pragma unroll
    for (int j = 0; j < 4; j++)
        t[ty + 8*j][tx] = W[(size_t)(by + ty + 8*j) * HID_ + bx + tx];
    __syncthreads();
#pragma unroll
    for (int j = 0; j < 4; j++) {
        float v = t[tx][ty + 8*j];
        int n = bx + ty + 8*j, k = by + tx;
        __half h = __float2half(v);
        hz[(size_t)n * HID_ + k] = h;
        lz[(size_t)n * HID_ + k] = __float2half(v - __half2float(h));
    }
}

// ---------------- GEMM core: load A once, apply Bh (+Bl); CTA 128x128, 2-stage ----------------
#define KC        64
#define NCHUNKW   16
#define ROWB      144u
#define ATILE_B   (128u*ROWB)            // 18432
#define STAGE_B   (3u*ATILE_B)           // 55296 (A + Bh + Bl)
#define GEMM_SMEM (2*STAGE_B)            // 110592  -> occ 2

__device__ __forceinline__ void gemm_load_tile(
    uint32_t sbase, int stage, int c, int m0, int n0, int tid, int nprod,
    const __half* A, const __half* Bh, const __half* Bl)
{
    const int k0 = c * KC;
    const uint32_t dstA = sbase + (uint32_t)stage * STAGE_B;
#pragma unroll
    for (int i = 0; i < 8; i++) {
        int idx = i * 256 + tid;                 // 0..2047
        int r = (idx >> 3) & 127, c16 = idx & 7;
        if (idx < 1024)
            cp16(dstA + r * ROWB + c16 * 16,
                 A + (size_t)(m0 + r) * HID_ + k0 + c16 * 8);
        else
            cp16(dstA + ATILE_B + r * ROWB + c16 * 16,
                 Bh + (size_t)(n0 + r) * HID_ + k0 + c16 * 8);
    }
    if (nprod == 2) {
#pragma unroll
        for (int i = 0; i < 4; i++) {
            int idx = i * 256 + tid;             // 0..1023
            int r = idx >> 3, c16 = idx & 7;
            cp16(dstA + 2 * ATILE_B + r * ROWB + c16 * 16,
                 Bl + (size_t)(n0 + r) * HID_ + k0 + c16 * 8);
        }
    }
    asm volatile("cp.async.commit_group;");
}

__device__ __forceinline__ void gemm_core(
    uint32_t sbase, int m0, int n0, int tid, int wm, int wn, int lane, int nprod,
    const __half* A, const __half* Bh, const __half* Bl,
    float acc[2][8][4])
{
    const int arow = wm * 32 + (lane & 7) + ((lane >> 3) & 1) * 8;
    const uint32_t a_l = (uint32_t)arow * ROWB + ((lane >> 4) * 16);
    const int brow = wn * 64 + (lane & 7) + ((lane >> 4) & 1) * 8;
    const uint32_t b_l = (uint32_t)brow * ROWB + (((lane >> 3) & 1) * 16);

    gemm_load_tile(sbase, 0, 0, m0, n0, tid, nprod, A, Bh, Bl);

    for (int c = 0; c < NCHUNKW; c++) {
        if (c + 1 < NCHUNKW)
            gemm_load_tile(sbase, (c + 1) & 1, c + 1, m0, n0, tid, nprod, A, Bh, Bl);
        if (c + 1 < NCHUNKW) asm volatile("cp.async.wait_group 1;" ::: "memory");
        else                 asm volatile("cp.async.wait_group 0;" ::: "memory");
        __syncthreads();

        const uint32_t sb = sbase + (uint32_t)(c & 1) * STAGE_B;
        const uint32_t aBase  = sb + a_l;
        const uint32_t bhBase = sb + ATILE_B + b_l;
        const uint32_t blBase = sb + 2 * ATILE_B + b_l;
#pragma unroll
        for (int kk = 0; kk < KC / 16; kk++) {
            const uint32_t koff = kk * 32;
            uint32_t aq[2][4];
#pragma unroll
            for (int mf = 0; mf < 2; mf++)
                ldm_x4(aq[mf], aBase + mf * 16 * ROWB + koff);
            uint32_t bqh[16];
#pragma unroll
            for (int np = 0; np < 4; np++)
                ldm_x4(&bqh[np * 4], bhBase + np * 16 * ROWB + koff);
#pragma unroll
            for (int mf = 0; mf < 2; mf++)
#pragma unroll
                for (int nf = 0; nf < 8; nf++)
                    mma16816h(acc[mf][nf], aq[mf], &bqh[(nf >> 1) * 4 + (nf & 1) * 2]);
            if (nprod == 2) {
                uint32_t bql[16];
#pragma unroll
                for (int np = 0; np < 4; np++)
                    ldm_x4(&bql[np * 4], blBase + np * 16 * ROWB + koff);
#pragma unroll
                for (int mf = 0; mf < 2; mf++)
#pragma unroll
                    for (int nf = 0; nf < 8; nf++)
                        mma16816h(acc[mf][nf], aq[mf], &bql[(nf >> 1) * 4 + (nf & 1) * 2]);
            }
        }
        __syncthreads();
    }
}

// ---------------- batched projection GEMMs (fp16 outputs for attention) ----------------
// mode 0: scatter [bh][l][192], single fp16 (Q and K)
// mode 2: V transpose [bh][d][l], single fp16
struct GemmB {
    const __half *A[7], *Bh[7], *Bl[7];
    const float* bias[7];
    __half *Oh[7];
    int mode[7];
    int part[7];
    int nprod[7];
};

__global__ __launch_bounds__(256, 2)
void gemm_batch(GemmB args)
{
    extern __shared__ char smem[];
    const uint32_t sbase = smem_u32(smem);
    const int z = blockIdx.z;
    const int tid = threadIdx.x;
    const int wid = tid >> 5, lane = tid & 31;
    const int m0 = blockIdx.y * 128, n0 = blockIdx.x * 128;
    const int wm = wid & 3, wn = wid >> 2;

    float acc[2][8][4];
#pragma unroll
    for (int mf = 0; mf < 2; mf++)
#pragma unroll
        for (int nf = 0; nf < 8; nf++)
#pragma unroll
            for (int q = 0; q < 4; q++) acc[mf][nf][q] = 0.f;

    gemm_core(sbase, m0, n0, tid, wm, wn, lane, args.nprod[z],
              args.A[z], args.Bh[z], args.Bl[z], acc);

    const float* bias = args.bias[z];
    __half* Oh = args.Oh[z];
    const int mode = args.mode[z], part = args.part[z];

    const int g = lane >> 2, tq = lane & 3;
    float2 bv[8];
#pragma unroll
    for (int nf = 0; nf < 8; nf++)
        bv[nf] = *(const float2*)(bias + n0 + wn * 64 + nf * 8 + 2 * tq);

#pragma unroll
    for (int mf = 0; mf < 2; mf++) {
#pragma unroll
        for (int half = 0; half < 2; half++) {
            const int m = m0 + wm * 32 + mf * 16 + g + half * 8;
            const int bb = m >> 9, ll = m & 511;
#pragma unroll
            for (int nf = 0; nf < 8; nf++) {
                const int n = n0 + wn * 64 + nf * 8 + 2 * tq;
                const int h = n >> 6, dd = n & 63;
                float vx = acc[mf][nf][half * 2 + 0] + bv[nf].x;
                float vy = acc[mf][nf][half * 2 + 1] + bv[nf].y;
                __half hx = __float2half(vx), hy = __float2half(vy);
                if (mode == 0) {
                    size_t dst = ((((size_t)bb * NH_ + h) * L_ + ll) * DCAT)
                               + (size_t)part * 64 + dd;
                    __half2 hi2; hi2.x = hx; hi2.y = hy;
                    *(__half2*)(Oh + dst) = hi2;
                } else {
                    size_t dst = (((size_t)bb * NH_ + h) * HD_ + dd) * L_ + ll;
                    Oh[dst] = hx;
                    Oh[dst + L_] = hy;
                }
            }
        }
    }
}

// ---------------- output projection GEMM (fp32 out, 2-product) ----------------
__global__ __launch_bounds__(256, 2)
void gemm_out(const __half* __restrict__ A,
              const __half* __restrict__ Bh, const __half* __restrict__ Bl,
              const float* __restrict__ bias, float* __restrict__ out)
{
    extern __shared__ char smem[];
    const uint32_t sbase = smem_u32(smem);
    const int tid = threadIdx.x;
    const int wid = tid >> 5, lane = tid & 31;
    const int m0 = blockIdx.y * 128, n0 = blockIdx.x * 128;
    const int wm = wid & 3, wn = wid >> 2;

    float acc[2][8][4];
#pragma unroll
    for (int mf = 0; mf < 2; mf++)
#pragma unroll
        for (int nf = 0; nf < 8; nf++)
#pragma unroll
            for (int q = 0; q < 4; q++) acc[mf][nf][q] = 0.f;

    gemm_core(sbase, m0, n0, tid, wm, wn, lane, 2, A, Bh, Bl, acc);

    const int g = lane >> 2, tq = lane & 3;
    float2 bv[8];
#pragma unroll
    for (int nf = 0; nf < 8; nf++)
        bv[nf] = *(const float2*)(bias + n0 + wn * 64 + nf * 8 + 2 * tq);
#pragma unroll
    for (int mf = 0; mf < 2; mf++)
#pragma unroll
        for (int half = 0; half < 2; half++) {
            const int m = m0 + wm * 32 + mf * 16 + g + half * 8;
#pragma unroll
            for (int nf = 0; nf < 8; nf++) {
                const int n = n0 + wn * 64 + nf * 8 + 2 * tq;
                float2 v;
                v.x = acc[mf][nf][half * 2 + 0] + bv[nf].x;
                v.y = acc[mf][nf][half * 2 + 1] + bv[nf].y;
                *(float2*)(out + (size_t)m * HID_ + n) = v;
            }
        }
}

// ---------------- flash attention: single-fp16 QK and PV, 128-thr CTA ----------------
// smem: Q 64x400 = 25600 | K 25600 | V 9216 = 60416
#define AQ_STRIDE 400u
#define AV_STRIDE 144u
#define SM_Q  0u
#define SM_K  25600u
#define SM_V  51200u
#define ATT_SMEM 60416

__global__ __launch_bounds__(128, 2)
void attn_mma(const float* __restrict__ rel,
              const __half* __restrict__ Qf, const __half* __restrict__ Kf,
              const __half* __restrict__ Vtf,
              __half* __restrict__ Of)
{
    extern __shared__ char smc[];
    const uint32_t sb = smem_u32(smc);
    const int qt = (int)gridDim.x - 1 - (int)blockIdx.x;   // heavy CTAs first
    const int bh = blockIdx.y;
    const int q0 = qt * 64;
    const int tid = threadIdx.x, wid = tid >> 5, lane = tid & 31;
    const int g = lane >> 2, tq = lane & 3;
    const int wrow = wid * 16;

    const __half* qf_g = Qf  + (size_t)bh * L_ * DCAT;
    const __half* kf_g = Kf  + (size_t)bh * L_ * DCAT;
    const __half* vf_g = Vtf + (size_t)bh * HD_ * L_;
    const float* relg = rel + (size_t)bh * L_ * L_;

    // Q tile load: 64 rows x 24 segs = 1536 over 128 threads
#pragma unroll
    for (int i = 0; i < 12; i++) {
        int idx = i * 128 + tid;
        int r = idx / 24, s2 = idx % 24;
        cp16(sb + SM_Q + r * AQ_STRIDE + s2 * 16,
             qf_g + (size_t)(q0 + r) * DCAT + s2 * 8);
    }
    asm volatile("cp.async.commit_group;");

    float m_i[2] = {-3.0e38f, -3.0e38f};
    float l_i[2] = {0.f, 0.f};
    float oacc[8][4];
#pragma unroll
    for (int nf = 0; nf < 8; nf++)
#pragma unroll
        for (int q = 0; q < 4; q++) oacc[nf][q] = 0.f;

    const uint32_t aoffQ = (uint32_t)(wrow + (lane & 7) + ((lane >> 3) & 1) * 8) * AQ_STRIDE
                         + (lane >> 4) * 16;
    const uint32_t boffK = (uint32_t)((lane & 7) + ((lane >> 4) & 1) * 8) * AQ_STRIDE
                         + ((lane >> 3) & 1) * 16;
    const uint32_t boffV = (uint32_t)((lane & 7) + ((lane >> 4) & 1) * 8) * AV_STRIDE
                         + ((lane >> 3) & 1) * 16;

    const int row0c = q0 + wrow + g;
    const int row1c = row0c + 8;

    const int ntiles = qt + 1;
    for (int kt = 0; kt < ntiles; kt++) {
        const int k0 = kt * 64;
        __syncthreads();
        // K: 64x24 segs (1536); Vt: 64x8 segs (512) -> 2048 segs
#pragma unroll
        for (int i = 0; i < 16; i++) {
            int idx = i * 128 + tid;
            if (idx < 1536) {
                int r = idx / 24, s2 = idx % 24;
                cp16(sb + SM_K + r * AQ_STRIDE + s2 * 16,
                     kf_g + (size_t)(k0 + r) * DCAT + s2 * 8);
            } else {
                int j = idx - 1536;
                int d = j >> 3, s2 = j & 7;
                cp16(sb + SM_V + d * AV_STRIDE + s2 * 16,
                     vf_g + (size_t)d * L_ + k0 + s2 * 8);
            }
        }
        asm volatile("cp.async.commit_group;");
        asm volatile("cp.async.wait_group 0;" ::: "memory");
        __syncthreads();

        if (k0 > q0 + wrow + 15) continue;

        // prefetch relative_time bias (hidden under QK mma)
        float2 rr0[8], rr1[8];
#pragma unroll
        for (int nf = 0; nf < 8; nf++) {
            const int col = k0 + nf * 8 + 2 * tq;
            rr0[nf] = *(const float2*)(relg + (size_t)row0c * L_ + col);
            rr1[nf] = *(const float2*)(relg + (size_t)row1c * L_ + col);
        }

        // ---- S = Q*K over k=192, single fp16 ----
        float sacc[8][4];
#pragma unroll
        for (int nf = 0; nf < 8; nf++)
#pragma unroll
            for (int q = 0; q < 4; q++) sacc[nf][q] = 0.f;

#pragma unroll
        for (int ks = 0; ks < 12; ks++) {
            const uint32_t koff = ks * 32;
            uint32_t aq[4], bq[16];
            ldm_x4(aq, sb + SM_Q + aoffQ + koff);
#pragma unroll
            for (int np = 0; np < 4; np++)
                ldm_x4(&bq[np * 4], sb + SM_K + boffK + np * 16 * AQ_STRIDE + koff);
#pragma unroll
            for (int nf = 0; nf < 8; nf++)
                mma16816h(sacc[nf], aq, &bq[(nf >> 1) * 4 + (nf & 1) * 2]);
        }

        // ---- bias + mask + online softmax ----
        const int row0 = row0c;
        const int row1 = row1c;
        const bool diag = (k0 + 63 > q0 + wrow);
        float pmax0 = -3.0e38f, pmax1 = -3.0e38f;
#pragma unroll
        for (int nf = 0; nf < 8; nf++) {
            const int col = k0 + nf * 8 + 2 * tq;
            float s0 = fmaf(sacc[nf][0], 0.125f, rr0[nf].x);
            float s1 = fmaf(sacc[nf][1], 0.125f, rr0[nf].y);
            float s2 = fmaf(sacc[nf][2], 0.125f, rr1[nf].x);
            float s3 = fmaf(sacc[nf][3], 0.125f, rr1[nf].y);
            if (diag) {
                if (col     > row0) s0 = -3.0e38f;
                if (col + 1 > row0) s1 = -3.0e38f;
                if (col     > row1) s2 = -3.0e38f;
                if (col + 1 > row1) s3 = -3.0e38f;
            }
            sacc[nf][0] = s0; sacc[nf][1] = s1; sacc[nf][2] = s2; sacc[nf][3] = s3;
            pmax0 = fmaxf(pmax0, fmaxf(s0, s1));
            pmax1 = fmaxf(pmax1, fmaxf(s2, s3));
        }
        {
            __half2 hm = __floats2half2_rn(pmax0, pmax1);
#pragma unroll
            for (int d = 1; d < 4; d <<= 1) {
                uint32_t u = *(uint32_t*)&hm;
                uint32_t v = __shfl_xor_sync(0xffffffffu, u, d);
                hm = __hmax2(hm, *(__half2*)&v);
            }
            float2 fm = __half22float2(hm);
            pmax0 = fm.x;  pmax1 = fm.y;
        }
        const float nm0 = fmaxf(m_i[0], pmax0);
        const float nm1 = fmaxf(m_i[1], pmax1);
        const float al0 = __expf(m_i[0] - nm0);
        const float al1 = __expf(m_i[1] - nm1);
        float rs0 = 0.f, rs1 = 0.f;
#pragma unroll
        for (int nf = 0; nf < 8; nf++) {
            sacc[nf][0] = __expf(sacc[nf][0] - nm0);
            sacc[nf][1] = __expf(sacc[nf][1] - nm0);
            sacc[nf][2] = __expf(sacc[nf][2] - nm1);
            sacc[nf][3] = __expf(sacc[nf][3] - nm1);
            rs0 += sacc[nf][0] + sacc[nf][1];
            rs1 += sacc[nf][2] + sacc[nf][3];
        }
#pragma unroll
        for (int d = 1; d < 4; d <<= 1) {
            rs0 += __shfl_xor_sync(0xffffffffu, rs0, d);
            rs1 += __shfl_xor_sync(0xffffffffu, rs1, d);
        }
        l_i[0] = l_i[0] * al0 + rs0;  m_i[0] = nm0;
        l_i[1] = l_i[1] * al1 + rs1;  m_i[1] = nm1;
#pragma unroll
        for (int nf = 0; nf < 8; nf++) {
            oacc[nf][0] *= al0; oacc[nf][1] *= al0;
            oacc[nf][2] *= al1; oacc[nf][3] *= al1;
        }

        // ---- O += P*V over k=64, single fp16 ----
#pragma unroll
        for (int ks = 0; ks < 4; ks++) {
            uint32_t af[4];
            af[0] = pack_h2(sacc[2*ks][0],   sacc[2*ks][1]);
            af[1] = pack_h2(sacc[2*ks][2],   sacc[2*ks][3]);
            af[2] = pack_h2(sacc[2*ks+1][0], sacc[2*ks+1][1]);
            af[3] = pack_h2(sacc[2*ks+1][2], sacc[2*ks+1][3]);
            uint32_t bv[16];
            const uint32_t koff = ks * 32;
#pragma unroll
            for (int np = 0; np < 4; np++)
                ldm_x4(&bv[np * 4], sb + SM_V + boffV + np * 16 * AV_STRIDE + koff);
#pragma unroll
            for (int nf = 0; nf < 8; nf++)
                mma16816h(oacc[nf], af, &bv[(nf >> 1) * 4 + (nf & 1) * 2]);
        }
    }

    // ---- epilogue: normalize, fp16 write to [m][HID] ----
    const int b = bh >> 4, h = bh & 15;
    const float inv0 = 1.0f / l_i[0];
    const float inv1 = 1.0f / l_i[1];
    const size_t m0g = (size_t)(b * L_ + q0 + wrow + g) * HID_;
    const size_t m1g = m0g + 8 * HID_;
#pragma unroll
    for (int nf = 0; nf < 8; nf++) {
        const int col = h * 64 + nf * 8 + 2 * tq;
        __half2 o0 = __floats2half2_rn(oacc[nf][0] * inv0, oacc[nf][1] * inv0);
        __half2 o1 = __floats2half2_rn(oacc[nf][2] * inv1, oacc[nf][3] * inv1);
        *(__half2*)(Of + m0g + col) = o0;
        *(__half2*)(Of + m1g + col) = o1;
    }
}

// ---------------- launcher ----------------
extern "C" void kernel_launch(void* const* d_in, const int* in_sizes, int n_in,
                              void* d_out, int out_size)
{
    const float* rel = (const float*)d_in[5];
    float* out = (float*)d_out;

    __half *xf, *wfh, *wfl, *qf, *kf, *vf;
    cudaGetSymbolAddress((void**)&xf, g_xf);
    cudaGetSymbolAddress((void**)&wfh, g_wfh);
    cudaGetSymbolAddress((void**)&wfl, g_wfl);
    cudaGetSymbolAddress((void**)&qf, g_qf);
    cudaGetSymbolAddress((void**)&kf, g_kf);
    cudaGetSymbolAddress((void**)&vf, g_vf);

    cudaFuncSetAttribute(gemm_batch, cudaFuncAttributeMaxDynamicSharedMemorySize, GEMM_SMEM);
    cudaFuncSetAttribute(gemm_out, cudaFuncAttributeMaxDynamicSharedMemorySize, GEMM_SMEM);
    cudaFuncSetAttribute(attn_mma, cudaFuncAttributeMaxDynamicSharedMemorySize, ATT_SMEM);

    const int n4 = (int)(XN / 4);

    SplitSrc ss;
    ss.p[0] = (const float*)d_in[0];
    ss.p[1] = (const float*)d_in[1];
    ss.p[2] = (const float*)d_in[2];
    ss.p[3] = (const float*)d_in[3];
    split_f16<<<dim3((n4 + 255) / 256, 4), 256>>>(ss, xf, n4);

    WSrc ws;
    ws.p[0] = (const float*)d_in[6];   ws.p[1] = (const float*)d_in[8];
    ws.p[2] = (const float*)d_in[10];  ws.p[3] = (const float*)d_in[12];
    ws.p[4] = (const float*)d_in[14];  ws.p[5] = (const float*)d_in[16];
    ws.p[6] = (const float*)d_in[18];  ws.p[7] = (const float*)d_in[20];
    splitT_h<<<dim3(32, 32, 8), dim3(32, 8)>>>(ws, wfh, wfl);

    GemmB gb;
    const int ain[7]  = {0, 1, 2, 0, 1, 2, 3};
    const int wsl[7]  = {0, 3, 5, 1, 4, 6, 2};
    const int bidx[7] = {7, 13, 17, 9, 15, 19, 11};
    for (int z = 0; z < 7; z++) {
        gb.A[z]  = xf + (size_t)ain[z] * XN;
        gb.Bh[z] = wfh + (size_t)wsl[z] * WN;
        gb.Bl[z] = wfl + (size_t)wsl[z] * WN;
        gb.bias[z] = (const float*)d_in[bidx[z]];
    }
    // all projections single-product, single-fp16 output
    gb.Oh[0] = qf; gb.mode[0] = 0; gb.part[0] = 0; gb.nprod[0] = 1;
    gb.Oh[1] = qf; gb.mode[1] = 0; gb.part[1] = 1; gb.nprod[1] = 1;
    gb.Oh[2] = qf; gb.mode[2] = 0; gb.part[2] = 2; gb.nprod[2] = 1;
    gb.Oh[3] = kf; gb.mode[3] = 0; gb.part[3] = 0; gb.nprod[3] = 1;
    gb.Oh[4] = kf; gb.mode[4] = 0; gb.part[4] = 1; gb.nprod[4] = 1;
    gb.Oh[5] = kf; gb.mode[5] = 0; gb.part[5] = 2; gb.nprod[5] = 1;
    gb.Oh[6] = vf; gb.mode[6] = 2; gb.part[6] = 0; gb.nprod[6] = 1;
    gemm_batch<<<dim3(8, 64, 7), 256, GEMM_SMEM>>>(gb);

    attn_mma<<<dim3(8, 256), 128, ATT_SMEM>>>(rel, qf, kf, vf, xf + 4 * XN);

    gemm_out<<<dim3(8, 64), 256, GEMM_SMEM>>>(xf + 4 * XN,
                                              wfh + 7 * WN, wfl + 7 * WN,
                                              (const float*)d_in[21], out);
}

// round 15
// speedup vs baseline: 2.6377x; 1.1182x over previous
#include <cuda_runtime.h>
#include <cuda_bf16.h>
#include <cuda_fp16.h>
#include <cstdint>

#define B_    16
#define L_    512
#define HID_  1024
#define NH_   16
#define HD_   64
#define M_TOT (B_*L_)      // 8192
#define DCAT  192
#define XN    ((size_t)M_TOT*HID_)
#define WN    ((size_t)HID_*HID_)

// ---------------- scratch (static device arrays) ----------------
__device__ __half g_xf[5ULL*XN];            // fp16 activations: 4 inputs + attn-out
__device__ __half g_wfh[8ULL*WN];           // W^T fp16 hi
__device__ __half g_wfl[8ULL*WN];           // W^T fp16 lo (residual; unused now but kept)
__device__ __half g_qf [(size_t)B_*NH_*L_*DCAT];   // Q single fp16
__device__ __half g_kf [(size_t)B_*NH_*L_*DCAT];   // K single fp16
__device__ __half g_vf [(size_t)B_*NH_*HD_*L_];    // Vt single fp16

// ---------------- PTX helpers (baseline ISA only) ----------------
__device__ __forceinline__ uint32_t smem_u32(const void* p) {
    uint32_t a;
    asm("{ .reg .u64 t; cvta.to.shared.u64 t, %1; cvt.u32.u64 %0, t; }" : "=r"(a) : "l"(p));
    return a;
}
__device__ __forceinline__ void cp16(uint32_t dst, const void* src) {
    asm volatile("cp.async.cg.shared.global [%0], [%1], 16;" :: "r"(dst), "l"(src));
}
__device__ __forceinline__ void ldm_x4(uint32_t* r, uint32_t addr) {
    asm volatile("ldmatrix.sync.aligned.m8n8.x4.shared.b16 {%0,%1,%2,%3}, [%4];"
                 : "=r"(r[0]), "=r"(r[1]), "=r"(r[2]), "=r"(r[3]) : "r"(addr));
}
// fp16 mma
__device__ __forceinline__ void mma16816h(float* d, const uint32_t* a, const uint32_t* b) {
    asm volatile(
        "mma.sync.aligned.m16n8k16.row.col.f32.f16.f16.f32 "
        "{%0,%1,%2,%3}, {%4,%5,%6,%7}, {%8,%9}, {%0,%1,%2,%3};"
        : "+f"(d[0]), "+f"(d[1]), "+f"(d[2]), "+f"(d[3])
        : "r"(a[0]), "r"(a[1]), "r"(a[2]), "r"(a[3]), "r"(b[0]), "r"(b[1]));
}
__device__ __forceinline__ uint32_t pack_h2(float a, float b) {
    __half2 t = __floats2half2_rn(a, b);
    return *(uint32_t*)&t;
}

// ---------------- batched fp32 -> fp16 ----------------
struct SplitSrc { const float* p[4]; };
__global__ __launch_bounds__(256)
void split_f16(SplitSrc s, __half* __restrict__ dst, int n4)
{
    int i = blockIdx.x * 256 + threadIdx.x;
    if (i >= n4) return;
    int z = blockIdx.y;
    const float* src = s.p[z];
    __half* dz = dst + (size_t)z * XN;
    float4 v = ((const float4*)src)[i];
    __half2 a = __floats2half2_rn(v.x, v.y);
    __half2 b = __floats2half2_rn(v.z, v.w);
    ((__half2*)dz)[i*2]   = a;
    ((__half2*)dz)[i*2+1] = b;
}

// ---------------- batched W[k][n] -> W^T[n][k] fp16 (hi only needed now) ----------------
struct WSrc { const float* p[8]; };
__global__ __launch_bounds__(256)
void splitT_h(WSrc s, __half* __restrict__ hiT, __half* __restrict__ loT)
{
    __shared__ float t[32][33];
    int z = blockIdx.z;
    const float* W = s.p[z];
    __half* hz = hiT + (size_t)z * WN;
    int bx = blockIdx.x * 32, by = blockIdx.y * 32;
    int tx = threadIdx.x, ty = threadIdx.y;
#pragma unroll
    for (int j = 0; j < 4; j++)
        t[ty + 8*j][tx] = W[(size_t)(by + ty + 8*j) * HID_ + bx + tx];
    __syncthreads();
#pragma unroll
    for (int j = 0; j < 4; j++) {
        float v = t[tx][ty + 8*j];
        int n = bx + ty + 8*j, k = by + tx;
        hz[(size_t)n * HID_ + k] = __float2half(v);
    }
}

// ---------------- GEMM core: single-product C = A*Bh; CTA 128x128, 2-stage ----------------
#define KC        64
#define NCHUNKW   16
#define ROWB      144u
#define ATILE_B   (128u*ROWB)            // 18432
#define STAGE_B   (2u*ATILE_B)           // 36864 (A + Bh)
#define GEMM_SMEM (3*STAGE_B)            // 110592 -> 3-stage, occ 2

__device__ __forceinline__ void gemm_load_tile(
    uint32_t sbase, int stage, int c, int m0, int n0, int tid,
    const __half* A, const __half* Bh)
{
    const int k0 = c * KC;
    const uint32_t dstA = sbase + (uint32_t)stage * STAGE_B;
#pragma unroll
    for (int i = 0; i < 8; i++) {
        int idx = i * 256 + tid;                 // 0..2047
        int r = (idx >> 3) & 127, c16 = idx & 7;
        if (idx < 1024)
            cp16(dstA + r * ROWB + c16 * 16,
                 A + (size_t)(m0 + r) * HID_ + k0 + c16 * 8);
        else
            cp16(dstA + ATILE_B + r * ROWB + c16 * 16,
                 Bh + (size_t)(n0 + r) * HID_ + k0 + c16 * 8);
    }
    asm volatile("cp.async.commit_group;");
}

__device__ __forceinline__ void gemm_core(
    uint32_t sbase, int m0, int n0, int tid, int wm, int wn, int lane,
    const __half* A, const __half* Bh,
    float acc[2][8][4])
{
    const int arow = wm * 32 + (lane & 7) + ((lane >> 3) & 1) * 8;
    const uint32_t a_l = (uint32_t)arow * ROWB + ((lane >> 4) * 16);
    const int brow = wn * 64 + (lane & 7) + ((lane >> 4) & 1) * 8;
    const uint32_t b_l = (uint32_t)brow * ROWB + (((lane >> 3) & 1) * 16);

    gemm_load_tile(sbase, 0, 0, m0, n0, tid, A, Bh);
    gemm_load_tile(sbase, 1, 1, m0, n0, tid, A, Bh);

    for (int c = 0; c < NCHUNKW; c++) {
        if (c < NCHUNKW - 1) asm volatile("cp.async.wait_group 1;" ::: "memory");
        else                 asm volatile("cp.async.wait_group 0;" ::: "memory");
        __syncthreads();
        if (c + 2 < NCHUNKW)
            gemm_load_tile(sbase, (c + 2) % 3, c + 2, m0, n0, tid, A, Bh);

        const uint32_t sb = sbase + (uint32_t)(c % 3) * STAGE_B;
        const uint32_t aBase  = sb + a_l;
        const uint32_t bhBase = sb + ATILE_B + b_l;
#pragma unroll
        for (int kk = 0; kk < KC / 16; kk++) {
            const uint32_t koff = kk * 32;
            uint32_t aq[2][4];
#pragma unroll
            for (int mf = 0; mf < 2; mf++)
                ldm_x4(aq[mf], aBase + mf * 16 * ROWB + koff);
            uint32_t bqh[16];
#pragma unroll
            for (int np = 0; np < 4; np++)
                ldm_x4(&bqh[np * 4], bhBase + np * 16 * ROWB + koff);
#pragma unroll
            for (int mf = 0; mf < 2; mf++)
#pragma unroll
                for (int nf = 0; nf < 8; nf++)
                    mma16816h(acc[mf][nf], aq[mf], &bqh[(nf >> 1) * 4 + (nf & 1) * 2]);
        }
        __syncthreads();
    }
}

// ---------------- batched projection GEMMs (fp16 outputs for attention) ----------------
// mode 0: scatter [bh][l][192] (Q and K); mode 2: V transpose [bh][d][l]
struct GemmB {
    const __half *A[7], *Bh[7];
    const float* bias[7];
    __half *Oh[7];
    int mode[7];
    int part[7];
};

__global__ __launch_bounds__(256, 2)
void gemm_batch(GemmB args)
{
    extern __shared__ char smem[];
    const uint32_t sbase = smem_u32(smem);
    const int z = blockIdx.z;
    const int tid = threadIdx.x;
    const int wid = tid >> 5, lane = tid & 31;
    const int m0 = blockIdx.y * 128, n0 = blockIdx.x * 128;
    const int wm = wid & 3, wn = wid >> 2;

    float acc[2][8][4];
#pragma unroll
    for (int mf = 0; mf < 2; mf++)
#pragma unroll
        for (int nf = 0; nf < 8; nf++)
#pragma unroll
            for (int q = 0; q < 4; q++) acc[mf][nf][q] = 0.f;

    gemm_core(sbase, m0, n0, tid, wm, wn, lane, args.A[z], args.Bh[z], acc);

    const float* bias = args.bias[z];
    __half* Oh = args.Oh[z];
    const int mode = args.mode[z], part = args.part[z];

    const int g = lane >> 2, tq = lane & 3;
    float2 bv[8];
#pragma unroll
    for (int nf = 0; nf < 8; nf++)
        bv[nf] = *(const float2*)(bias + n0 + wn * 64 + nf * 8 + 2 * tq);

#pragma unroll
    for (int mf = 0; mf < 2; mf++) {
#pragma unroll
        for (int half = 0; half < 2; half++) {
            const int m = m0 + wm * 32 + mf * 16 + g + half * 8;
            const int bb = m >> 9, ll = m & 511;
#pragma unroll
            for (int nf = 0; nf < 8; nf++) {
                const int n = n0 + wn * 64 + nf * 8 + 2 * tq;
                const int h = n >> 6, dd = n & 63;
                float vx = acc[mf][nf][half * 2 + 0] + bv[nf].x;
                float vy = acc[mf][nf][half * 2 + 1] + bv[nf].y;
                __half hx = __float2half(vx), hy = __float2half(vy);
                if (mode == 0) {
                    size_t dst = ((((size_t)bb * NH_ + h) * L_ + ll) * DCAT)
                               + (size_t)part * 64 + dd;
                    __half2 hi2; hi2.x = hx; hi2.y = hy;
                    *(__half2*)(Oh + dst) = hi2;
                } else {
                    size_t dst = (((size_t)bb * NH_ + h) * HD_ + dd) * L_ + ll;
                    Oh[dst] = hx;
                    Oh[dst + L_] = hy;
                }
            }
        }
    }
}

// ---------------- output projection GEMM (fp32 out, single product) ----------------
__global__ __launch_bounds__(256, 2)
void gemm_out(const __half* __restrict__ A, const __half* __restrict__ Bh,
              const float* __restrict__ bias, float* __restrict__ out)
{
    extern __shared__ char smem[];
    const uint32_t sbase = smem_u32(smem);
    const int tid = threadIdx.x;
    const int wid = tid >> 5, lane = tid & 31;
    const int m0 = blockIdx.y * 128, n0 = blockIdx.x * 128;
    const int wm = wid & 3, wn = wid >> 2;

    float acc[2][8][4];
#pragma unroll
    for (int mf = 0; mf < 2; mf++)
#pragma unroll
        for (int nf = 0; nf < 8; nf++)
#pragma unroll
            for (int q = 0; q < 4; q++) acc[mf][nf][q] = 0.f;

    gemm_core(sbase, m0, n0, tid, wm, wn, lane, A, Bh, acc);

    const int g = lane >> 2, tq = lane & 3;
    float2 bv[8];
#pragma unroll
    for (int nf = 0; nf < 8; nf++)
        bv[nf] = *(const float2*)(bias + n0 + wn * 64 + nf * 8 + 2 * tq);
#pragma unroll
    for (int mf = 0; mf < 2; mf++)
#pragma unroll
        for (int half = 0; half < 2; half++) {
            const int m = m0 + wm * 32 + mf * 16 + g + half * 8;
#pragma unroll
            for (int nf = 0; nf < 8; nf++) {
                const int n = n0 + wn * 64 + nf * 8 + 2 * tq;
                float2 v;
                v.x = acc[mf][nf][half * 2 + 0] + bv[nf].x;
                v.y = acc[mf][nf][half * 2 + 1] + bv[nf].y;
                *(float2*)(out + (size_t)m * HID_ + n) = v;
            }
        }
}

// ---------------- flash attention: fp16 QK+PV, double-buffered K/V tiles ----------------
// smem: Q 25600 | 2 x (K 25600 + V 9216) = 95232 -> 2 CTA/SM
#define AQ_STRIDE 400u
#define AV_STRIDE 144u
#define SM_Q    0u
#define KV_STG0 25600u
#define KV_STGB 34816u        // stage size: K 25600 + V 9216
#define ATT_SMEM (25600 + 2*34816)

__global__ __launch_bounds__(128, 2)
void attn_mma(const float* __restrict__ rel,
              const __half* __restrict__ Qf, const __half* __restrict__ Kf,
              const __half* __restrict__ Vtf,
              __half* __restrict__ Of)
{
    extern __shared__ char smc[];
    const uint32_t sb = smem_u32(smc);
    const int qt = (int)gridDim.x - 1 - (int)blockIdx.x;   // heavy CTAs first
    const int bh = blockIdx.y;
    const int q0 = qt * 64;
    const int tid = threadIdx.x, wid = tid >> 5, lane = tid & 31;
    const int g = lane >> 2, tq = lane & 3;
    const int wrow = wid * 16;

    const __half* qf_g = Qf  + (size_t)bh * L_ * DCAT;
    const __half* kf_g = Kf  + (size_t)bh * L_ * DCAT;
    const __half* vf_g = Vtf + (size_t)bh * HD_ * L_;
    const float* relg = rel + (size_t)bh * L_ * L_;

    // Q tile load (group 0)
#pragma unroll
    for (int i = 0; i < 12; i++) {
        int idx = i * 128 + tid;
        int r = idx / 24, s2 = idx % 24;
        cp16(sb + SM_Q + r * AQ_STRIDE + s2 * 16,
             qf_g + (size_t)(q0 + r) * DCAT + s2 * 8);
    }
    asm volatile("cp.async.commit_group;");

    // K/V tile loader into stage s
    auto load_tile = [&](int kt, int s) {
        const int k0 = kt * 64;
        const uint32_t stg = sb + KV_STG0 + (uint32_t)s * KV_STGB;
#pragma unroll
        for (int i = 0; i < 16; i++) {
            int idx = i * 128 + tid;
            if (idx < 1536) {
                int r = idx / 24, s2 = idx % 24;
                cp16(stg + r * AQ_STRIDE + s2 * 16,
                     kf_g + (size_t)(k0 + r) * DCAT + s2 * 8);
            } else {
                int j = idx - 1536;
                int d = j >> 3, s2 = j & 7;
                cp16(stg + 25600u + d * AV_STRIDE + s2 * 16,
                     vf_g + (size_t)d * L_ + k0 + s2 * 8);
            }
        }
        asm volatile("cp.async.commit_group;");
    };

    const int ntiles = qt + 1;
    load_tile(0, 0);

    float m_i[2] = {-3.0e38f, -3.0e38f};
    float l_i[2] = {0.f, 0.f};
    float oacc[8][4];
#pragma unroll
    for (int nf = 0; nf < 8; nf++)
#pragma unroll
        for (int q = 0; q < 4; q++) oacc[nf][q] = 0.f;

    const uint32_t aoffQ = (uint32_t)(wrow + (lane & 7) + ((lane >> 3) & 1) * 8) * AQ_STRIDE
                         + (lane >> 4) * 16;
    const uint32_t boffK = (uint32_t)((lane & 7) + ((lane >> 4) & 1) * 8) * AQ_STRIDE
                         + ((lane >> 3) & 1) * 16;
    const uint32_t boffV = (uint32_t)((lane & 7) + ((lane >> 4) & 1) * 8) * AV_STRIDE
                         + ((lane >> 3) & 1) * 16;

    const int row0c = q0 + wrow + g;
    const int row1c = row0c + 8;

    for (int kt = 0; kt < ntiles; kt++) {
        const int k0 = kt * 64;
        // issue next tile's load into the other stage (its previous consumer
        // finished at the end-of-iteration sync of kt-1)
        if (kt + 1 < ntiles) load_tile(kt + 1, (kt + 1) & 1);
        if (kt + 1 < ntiles) asm volatile("cp.async.wait_group 1;" ::: "memory");
        else                 asm volatile("cp.async.wait_group 0;" ::: "memory");
        __syncthreads();

        const bool active = (k0 <= q0 + wrow + 15);
        if (active) {
            const uint32_t stg = sb + KV_STG0 + (uint32_t)(kt & 1) * KV_STGB;
            const uint32_t kBase = stg;
            const uint32_t vBase = stg + 25600u;

            // prefetch relative_time bias (hidden under QK mma)
            float2 rr0[8], rr1[8];
#pragma unroll
            for (int nf = 0; nf < 8; nf++) {
                const int col = k0 + nf * 8 + 2 * tq;
                rr0[nf] = *(const float2*)(relg + (size_t)row0c * L_ + col);
                rr1[nf] = *(const float2*)(relg + (size_t)row1c * L_ + col);
            }

            // ---- S = Q*K over k=192 ----
            float sacc[8][4];
#pragma unroll
            for (int nf = 0; nf < 8; nf++)
#pragma unroll
                for (int q = 0; q < 4; q++) sacc[nf][q] = 0.f;

#pragma unroll
            for (int ks = 0; ks < 12; ks++) {
                const uint32_t koff = ks * 32;
                uint32_t aq[4], bq[16];
                ldm_x4(aq, sb + SM_Q + aoffQ + koff);
#pragma unroll
                for (int np = 0; np < 4; np++)
                    ldm_x4(&bq[np * 4], kBase + boffK + np * 16 * AQ_STRIDE + koff);
#pragma unroll
                for (int nf = 0; nf < 8; nf++)
                    mma16816h(sacc[nf], aq, &bq[(nf >> 1) * 4 + (nf & 1) * 2]);
            }

            // ---- bias + mask + online softmax ----
            const int row0 = row0c;
            const int row1 = row1c;
            const bool diag = (k0 + 63 > q0 + wrow);
            float pmax0 = -3.0e38f, pmax1 = -3.0e38f;
#pragma unroll
            for (int nf = 0; nf < 8; nf++) {
                const int col = k0 + nf * 8 + 2 * tq;
                float s0 = fmaf(sacc[nf][0], 0.125f, rr0[nf].x);
                float s1 = fmaf(sacc[nf][1], 0.125f, rr0[nf].y);
                float s2 = fmaf(sacc[nf][2], 0.125f, rr1[nf].x);
                float s3 = fmaf(sacc[nf][3], 0.125f, rr1[nf].y);
                if (diag) {
                    if (col     > row0) s0 = -3.0e38f;
                    if (col + 1 > row0) s1 = -3.0e38f;
                    if (col     > row1) s2 = -3.0e38f;
                    if (col + 1 > row1) s3 = -3.0e38f;
                }
                sacc[nf][0] = s0; sacc[nf][1] = s1; sacc[nf][2] = s2; sacc[nf][3] = s3;
                pmax0 = fmaxf(pmax0, fmaxf(s0, s1));
                pmax1 = fmaxf(pmax1, fmaxf(s2, s3));
            }
            {
                __half2 hm = __floats2half2_rn(pmax0, pmax1);
#pragma unroll
                for (int d = 1; d < 4; d <<= 1) {
                    uint32_t u = *(uint32_t*)&hm;
                    uint32_t v = __shfl_xor_sync(0xffffffffu, u, d);
                    hm = __hmax2(hm, *(__half2*)&v);
                }
                float2 fm = __half22float2(hm);
                pmax0 = fm.x;  pmax1 = fm.y;
            }
            const float nm0 = fmaxf(m_i[0], pmax0);
            const float nm1 = fmaxf(m_i[1], pmax1);
            const float al0 = __expf(m_i[0] - nm0);
            const float al1 = __expf(m_i[1] - nm1);
            float rs0 = 0.f, rs1 = 0.f;
#pragma unroll
            for (int nf = 0; nf < 8; nf++) {
                sacc[nf][0] = __expf(sacc[nf][0] - nm0);
                sacc[nf][1] = __expf(sacc[nf][1] - nm0);
                sacc[nf][2] = __expf(sacc[nf][2] - nm1);
                sacc[nf][3] = __expf(sacc[nf][3] - nm1);
                rs0 += sacc[nf][0] + sacc[nf][1];
                rs1 += sacc[nf][2] + sacc[nf][3];
            }
#pragma unroll
            for (int d = 1; d < 4; d <<= 1) {
                rs0 += __shfl_xor_sync(0xffffffffu, rs0, d);
                rs1 += __shfl_xor_sync(0xffffffffu, rs1, d);
            }
            l_i[0] = l_i[0] * al0 + rs0;  m_i[0] = nm0;
            l_i[1] = l_i[1] * al1 + rs1;  m_i[1] = nm1;
#pragma unroll
            for (int nf = 0; nf < 8; nf++) {
                oacc[nf][0] *= al0; oacc[nf][1] *= al0;
                oacc[nf][2] *= al1; oacc[nf][3] *= al1;
            }

            // ---- O += P*V over k=64 ----
#pragma unroll
            for (int ks = 0; ks < 4; ks++) {
                uint32_t af[4];
                af[0] = pack_h2(sacc[2*ks][0],   sacc[2*ks][1]);
                af[1] = pack_h2(sacc[2*ks][2],   sacc[2*ks][3]);
                af[2] = pack_h2(sacc[2*ks+1][0], sacc[2*ks+1][1]);
                af[3] = pack_h2(sacc[2*ks+1][2], sacc[2*ks+1][3]);
                uint32_t bv[16];
                const uint32_t koff = ks * 32;
#pragma unroll
                for (int np = 0; np < 4; np++)
                    ldm_x4(&bv[np * 4], vBase + boffV + np * 16 * AV_STRIDE + koff);
#pragma unroll
                for (int nf = 0; nf < 8; nf++)
                    mma16816h(oacc[nf], af, &bv[(nf >> 1) * 4 + (nf & 1) * 2]);
            }
        }
        __syncthreads();   // all warps done with stage (kt&1) before reload
    }

    // ---- epilogue ----
    const int b = bh >> 4, h = bh & 15;
    const float inv0 = 1.0f / l_i[0];
    const float inv1 = 1.0f / l_i[1];
    const size_t m0g = (size_t)(b * L_ + q0 + wrow + g) * HID_;
    const size_t m1g = m0g + 8 * HID_;
#pragma unroll
    for (int nf = 0; nf < 8; nf++) {
        const int col = h * 64 + nf * 8 + 2 * tq;
        __half2 o0 = __floats2half2_rn(oacc[nf][0] * inv0, oacc[nf][1] * inv0);
        __half2 o1 = __floats2half2_rn(oacc[nf][2] * inv1, oacc[nf][3] * inv1);
        *(__half2*)(Of + m0g + col) = o0;
        *(__half2*)(Of + m1g + col) = o1;
    }
}

// ---------------- launcher ----------------
extern "C" void kernel_launch(void* const* d_in, const int* in_sizes, int n_in,
                              void* d_out, int out_size)
{
    const float* rel = (const float*)d_in[5];
    float* out = (float*)d_out;

    __half *xf, *wfh, *wfl, *qf, *kf, *vf;
    cudaGetSymbolAddress((void**)&xf, g_xf);
    cudaGetSymbolAddress((void**)&wfh, g_wfh);
    cudaGetSymbolAddress((void**)&wfl, g_wfl);
    cudaGetSymbolAddress((void**)&qf, g_qf);
    cudaGetSymbolAddress((void**)&kf, g_kf);
    cudaGetSymbolAddress((void**)&vf, g_vf);

    cudaFuncSetAttribute(gemm_batch, cudaFuncAttributeMaxDynamicSharedMemorySize, GEMM_SMEM);
    cudaFuncSetAttribute(gemm_out, cudaFuncAttributeMaxDynamicSharedMemorySize, GEMM_SMEM);
    cudaFuncSetAttribute(attn_mma, cudaFuncAttributeMaxDynamicSharedMemorySize, ATT_SMEM);

    const int n4 = (int)(XN / 4);

    SplitSrc ss;
    ss.p[0] = (const float*)d_in[0];
    ss.p[1] = (const float*)d_in[1];
    ss.p[2] = (const float*)d_in[2];
    ss.p[3] = (const float*)d_in[3];
    split_f16<<<dim3((n4 + 255) / 256, 4), 256>>>(ss, xf, n4);

    WSrc ws;
    ws.p[0] = (const float*)d_in[6];   ws.p[1] = (const float*)d_in[8];
    ws.p[2] = (const float*)d_in[10];  ws.p[3] = (const float*)d_in[12];
    ws.p[4] = (const float*)d_in[14];  ws.p[5] = (const float*)d_in[16];
    ws.p[6] = (const float*)d_in[18];  ws.p[7] = (const float*)d_in[20];
    splitT_h<<<dim3(32, 32, 8), dim3(32, 8)>>>(ws, wfh, wfl);

    GemmB gb;
    const int ain[7]  = {0, 1, 2, 0, 1, 2, 3};
    const int wsl[7]  = {0, 3, 5, 1, 4, 6, 2};
    const int bidx[7] = {7, 13, 17, 9, 15, 19, 11};
    for (int z = 0; z < 7; z++) {
        gb.A[z]  = xf + (size_t)ain[z] * XN;
        gb.Bh[z] = wfh + (size_t)wsl[z] * WN;
        gb.bias[z] = (const float*)d_in[bidx[z]];
    }
    gb.Oh[0] = qf; gb.mode[0] = 0; gb.part[0] = 0;
    gb.Oh[1] = qf; gb.mode[1] = 0; gb.part[1] = 1;
    gb.Oh[2] = qf; gb.mode[2] = 0; gb.part[2] = 2;
    gb.Oh[3] = kf; gb.mode[3] = 0; gb.part[3] = 0;
    gb.Oh[4] = kf; gb.mode[4] = 0; gb.part[4] = 1;
    gb.Oh[5] = kf; gb.mode[5] = 0; gb.part[5] = 2;
    gb.Oh[6] = vf; gb.mode[6] = 2; gb.part[6] = 0;
    gemm_batch<<<dim3(8, 64, 7), 256, GEMM_SMEM>>>(gb);

    attn_mma<<<dim3(8, 256), 128, ATT_SMEM>>>(rel, qf, kf, vf, xf + 4 * XN);

    gemm_out<<<dim3(8, 64), 256, GEMM_SMEM>>>(xf + 4 * XN, wfh + 7 * WN,
                                              (const float*)d_in[21], out);
}